// round 3
// baseline (speedup 1.0000x reference)
#include <cuda_runtime.h>

#define NB 128    // batch
#define NT 512    // timesteps
#define NDIM 128  // noise dim
#define NH 512    // hidden
#define NG 2048   // 4*H
#define NLAT 128  // latent out
#define NL 3      // layers
#define NCTA 128
#define NTHR 128
#define KC 64     // K chunk
#define AST 66    // padded smem row stride

struct Smem {
    float a[NB][AST];          // activation chunk [128 x 64]
    float w[16][AST];          // weight chunk transposed [16 cols][64 k]
    float bias[NL][NB][16];    // precomputed h_cpl@Wc + b (this CTA's 16 gate cols)
    float cst[NL][NB][4];      // private c-state (this CTA's 4 hidden cols)
    float gex[4][NB][5];       // gate exchange [gate][row][col]
    float woutc[NH][8];        // staged Wout columns for output projection
};

__device__ float g_h[2][NL][NB][NH];   // ping-pong hidden state
__device__ unsigned g_bar_cnt;
__device__ unsigned g_bar_gen;

__device__ __forceinline__ void ffma2(unsigned long long& d, unsigned long long a,
                                      unsigned long long b) {
    asm volatile("fma.rn.f32x2 %0, %1, %2, %0;" : "+l"(d) : "l"(a), "l"(b));
}
__device__ __forceinline__ float2 unpack2(unsigned long long v) {
    float2 r;
    asm("mov.b64 {%0, %1}, %2;" : "=f"(r.x), "=f"(r.y) : "l"(v));
    return r;
}
__device__ __forceinline__ float sigm(float x) { return 1.f / (1.f + __expf(-x)); }

__device__ __forceinline__ void grid_barrier() {
    __syncthreads();
    if (threadIdx.x == 0) {
        volatile unsigned* genp = &g_bar_gen;
        unsigned gen = *genp;
        __threadfence();
        unsigned arr = atomicAdd(&g_bar_cnt, 1u);
        if (arr == NCTA - 1) {
            g_bar_cnt = 0u;
            __threadfence();
            atomicAdd(&g_bar_gen, 1u);
        } else {
            while (*genp == gen) { __nanosleep(64); }
        }
        __threadfence();
    }
    __syncthreads();
}

// acc[i*4+j] += sum_k A[rg*4+i][k] * W[k][cg*NH + hc4 + j]
// Each u64 acc holds {even-k partial, odd-k partial}; caller sums halves.
__device__ __forceinline__ void gemm_pass(const float* __restrict__ A, size_t lda,
                                          const float* __restrict__ W, int hc4,
                                          int K, unsigned long long* acc, Smem* s) {
    const int tid = threadIdx.x;
    const int rg = tid >> 2, cg = tid & 3;
    for (int k0 = 0; k0 < K; k0 += KC) {
        // stage activation chunk [128 x 64]
        {
            int i = tid;
#pragma unroll
            for (int it = 0; it < 16; it++, i += NTHR) {
                int r = i >> 4;
                int kq = (i & 15) << 2;
                float4 v = __ldcg(reinterpret_cast<const float4*>(A + (size_t)r * lda + k0 + kq));
                float2* dst = reinterpret_cast<float2*>(&s->a[r][kq]);
                dst[0] = make_float2(v.x, v.y);
                dst[1] = make_float2(v.z, v.w);
            }
        }
        // stage weight chunk transposed: w[g*4+j][k] = W[k0+k][g*NH+hc4+j]
        {
            int i = tid;
#pragma unroll
            for (int it = 0; it < 2; it++, i += NTHR) {
                int k = i >> 2, g = i & 3;
                float4 v = __ldg(reinterpret_cast<const float4*>(
                    W + (size_t)(k0 + k) * NG + g * NH + hc4));
                s->w[g * 4 + 0][k] = v.x;
                s->w[g * 4 + 1][k] = v.y;
                s->w[g * 4 + 2][k] = v.z;
                s->w[g * 4 + 3][k] = v.w;
            }
        }
        __syncthreads();

        const float* a0 = s->a[rg * 4 + 0];
        const float* a1 = s->a[rg * 4 + 1];
        const float* a2 = s->a[rg * 4 + 2];
        const float* a3 = s->a[rg * 4 + 3];
        const float* w0 = s->w[cg * 4 + 0];
        const float* w1 = s->w[cg * 4 + 1];
        const float* w2 = s->w[cg * 4 + 2];
        const float* w3 = s->w[cg * 4 + 3];

#pragma unroll 8
        for (int kk = 0; kk < KC; kk += 2) {
            unsigned long long av0 = *reinterpret_cast<const unsigned long long*>(a0 + kk);
            unsigned long long av1 = *reinterpret_cast<const unsigned long long*>(a1 + kk);
            unsigned long long av2 = *reinterpret_cast<const unsigned long long*>(a2 + kk);
            unsigned long long av3 = *reinterpret_cast<const unsigned long long*>(a3 + kk);
            unsigned long long wv0 = *reinterpret_cast<const unsigned long long*>(w0 + kk);
            unsigned long long wv1 = *reinterpret_cast<const unsigned long long*>(w1 + kk);
            unsigned long long wv2 = *reinterpret_cast<const unsigned long long*>(w2 + kk);
            unsigned long long wv3 = *reinterpret_cast<const unsigned long long*>(w3 + kk);
            ffma2(acc[0],  av0, wv0); ffma2(acc[1],  av0, wv1);
            ffma2(acc[2],  av0, wv2); ffma2(acc[3],  av0, wv3);
            ffma2(acc[4],  av1, wv0); ffma2(acc[5],  av1, wv1);
            ffma2(acc[6],  av1, wv2); ffma2(acc[7],  av1, wv3);
            ffma2(acc[8],  av2, wv0); ffma2(acc[9],  av2, wv1);
            ffma2(acc[10], av2, wv2); ffma2(acc[11], av2, wv3);
            ffma2(acc[12], av3, wv0); ffma2(acc[13], av3, wv1);
            ffma2(acc[14], av3, wv2); ffma2(acc[15], av3, wv3);
        }
        __syncthreads();
    }
}

__global__ void __launch_bounds__(NTHR, 1)
bilateral_kernel(const float* __restrict__ noise,
                 const float* __restrict__ h_cpl,
                 const float* __restrict__ Wx0,
                 const float* __restrict__ Wxr,
                 const float* __restrict__ Wh,
                 const float* __restrict__ Wc,
                 const float* __restrict__ bvec,
                 const float* __restrict__ Wout,
                 const float* __restrict__ bout,
                 float* __restrict__ out) {
    extern __shared__ char smem_raw[];
    Smem* s = reinterpret_cast<Smem*>(smem_raw);
    const int tid = threadIdx.x;
    const int cta = blockIdx.x;
    const int rg = tid >> 2, cg = tid & 3;
    const int hc4 = cta * 4;  // this CTA's 4 hidden columns

    float* out_seq = out;                              // [B][T][NLAT]
    float* out_hfin = out + (size_t)NB * NT * NLAT;    // [L][B][H]

    // output-projection tile for this CTA
    const int orow0 = (cta >> 4) * 16;
    const int ocol0 = (cta & 15) * 8;
    const int tr = tid >> 3, tc = tid & 7;
    const float bout_r = bout[ocol0 + tc];

    // ---- phase 0: zero h buffer 0, zero private c-state, stage Wout cols ----
    {
        float* hz = &g_h[0][0][0][0];
        for (int i = cta * NTHR + tid; i < NL * NB * NH; i += NCTA * NTHR) hz[i] = 0.f;
    }
    for (int i = tid; i < NL * NB * 4; i += NTHR) (&s->cst[0][0][0])[i] = 0.f;
    for (int i = tid; i < NH * 8; i += NTHR) {
        int k = i >> 3, c = i & 7;
        s->woutc[k][c] = Wout[(size_t)k * NLAT + ocol0 + c];
    }

    // ---- phase 0b: bias = h_coupled @ Wc + b (time-invariant) ----
    for (int l = 0; l < NL; l++) {
        unsigned long long acc[16];
#pragma unroll
        for (int m = 0; m < 16; m++) acc[m] = 0ull;
        gemm_pass(h_cpl + (size_t)l * NB * NH, NH, Wc + (size_t)l * NH * NG, hc4, NH, acc, s);
#pragma unroll
        for (int i = 0; i < 4; i++)
#pragma unroll
            for (int j = 0; j < 4; j++) {
                float2 v = unpack2(acc[i * 4 + j]);
                s->bias[l][rg * 4 + i][cg * 4 + j] =
                    v.x + v.y + bvec[l * NG + cg * NH + hc4 + j];
            }
    }
    __syncthreads();
    grid_barrier();  // zeros + everything visible everywhere

    // ---- main recurrence ----
    for (int t = 0; t < NT; t++) {
        const int rd = t & 1, wr = rd ^ 1;
        for (int l = 0; l < NL; l++) {
            unsigned long long acc[16];
#pragma unroll
            for (int m = 0; m < 16; m++) acc[m] = 0ull;

            if (l == 0) {
                gemm_pass(noise + (size_t)t * NDIM, (size_t)NT * NDIM, Wx0, hc4, NDIM, acc, s);
                gemm_pass(&g_h[rd][0][0][0], NH, Wh, hc4, NH, acc, s);
            } else {
                // input = h_new of layer l-1 (this step, buffer wr)
                gemm_pass(&g_h[wr][l - 1][0][0], NH,
                          Wxr + (size_t)(l - 1) * NH * NG, hc4, NH, acc, s);
                gemm_pass(&g_h[rd][l][0][0], NH,
                          Wh + (size_t)l * NH * NG, hc4, NH, acc, s);
            }

            // add bias, exchange gates through smem
#pragma unroll
            for (int i = 0; i < 4; i++)
#pragma unroll
                for (int j = 0; j < 4; j++) {
                    float2 v = unpack2(acc[i * 4 + j]);
                    s->gex[cg][rg * 4 + i][j] =
                        v.x + v.y + s->bias[l][rg * 4 + i][cg * 4 + j];
                }
            __syncthreads();

            // cell update: thread b handles row b, this CTA's 4 hidden cols
            {
                const int b = tid;
#pragma unroll
                for (int j = 0; j < 4; j++) {
                    float ig = s->gex[0][b][j];
                    float fg = s->gex[1][b][j];
                    float gg = s->gex[2][b][j];
                    float og = s->gex[3][b][j];
                    float c_new = sigm(fg) * s->cst[l][b][j] + sigm(ig) * tanhf(gg);
                    float h_new = sigm(og) * tanhf(c_new);
                    s->cst[l][b][j] = c_new;
                    g_h[wr][l][b][hc4 + j] = h_new;
                    if (t == NT - 1)
                        out_hfin[(size_t)l * NB * NH + (size_t)b * NH + hc4 + j] = h_new;
                }
            }
            grid_barrier();
        }

        // output projection: out[orow0+tr][t][ocol0+tc]
        {
            const float* hrow = &g_h[wr][2][orow0 + tr][0];
            float accp = bout_r;
#pragma unroll 8
            for (int k = 0; k < NH; k += 4) {
                float4 hv = __ldcg(reinterpret_cast<const float4*>(hrow + k));
                accp += hv.x * s->woutc[k + 0][tc];
                accp += hv.y * s->woutc[k + 1][tc];
                accp += hv.z * s->woutc[k + 2][tc];
                accp += hv.w * s->woutc[k + 3][tc];
            }
            out_seq[(size_t)(orow0 + tr) * NT * NLAT + (size_t)t * NLAT + ocol0 + tc] =
                sigm(accp);
        }
    }
}

extern "C" void kernel_launch(void* const* d_in, const int* in_sizes, int n_in,
                              void* d_out, int out_size) {
    const float* noise = (const float*)d_in[0];
    const float* h_cpl = (const float*)d_in[1];
    const float* Wx0   = (const float*)d_in[2];
    const float* Wxr   = (const float*)d_in[3];
    const float* Wh    = (const float*)d_in[4];
    const float* Wc    = (const float*)d_in[5];
    const float* bvec  = (const float*)d_in[6];
    const float* Wout  = (const float*)d_in[7];
    const float* bout  = (const float*)d_in[8];
    float* out = (float*)d_out;

    cudaFuncSetAttribute(bilateral_kernel, cudaFuncAttributeMaxDynamicSharedMemorySize,
                         (int)sizeof(Smem));
    bilateral_kernel<<<NCTA, NTHR, sizeof(Smem)>>>(noise, h_cpl, Wx0, Wxr, Wh, Wc,
                                                   bvec, Wout, bout, out);
}

// round 4
// speedup vs baseline: 1.2237x; 1.2237x over previous
#include <cuda_runtime.h>

#define NB 128
#define NT 512
#define NDIM 128
#define NH 512
#define NG 2048
#define NLAT 128
#define NL 3
#define NCTA 128
#define NTHR 256
#define GQ 128   // threads per split-K group

struct Smem {
    float a[2][2][NB][64];     // [group][dbuf][row][k-swizzled]
    float w[2][2][16][64];     // [group][dbuf][col][k-swizzled]
    float bias[NL][NB][16];
    float cst[NL][NB][4];
    float gex[4][NB][5];
    float pex[NB][17];
    float woutc[NH][8];
    float opart[NB];
};

__device__ float g_h[2][NL][NB][NH];
__device__ float g_wx0t[NG * NDIM];        // Wx0^T  [2048][128]
__device__ float g_wxrt[NL - 1][NG * NH];  // Wxr^T  [2][2048][512]
__device__ float g_wht[NL][NG * NH];       // Wh^T   [3][2048][512]
__device__ float g_wct[NL][NG * NH];       // Wc^T   [3][2048][512]
__device__ unsigned g_bar_cnt;
__device__ unsigned g_bar_gen;

__device__ __forceinline__ void ffma2(unsigned long long& d, unsigned long long a,
                                      unsigned long long b) {
    asm volatile("fma.rn.f32x2 %0, %1, %2, %0;" : "+l"(d) : "l"(a), "l"(b));
}
__device__ __forceinline__ float2 unpack2(unsigned long long v) {
    float2 r;
    asm("mov.b64 {%0, %1}, %2;" : "=f"(r.x), "=f"(r.y) : "l"(v));
    return r;
}
__device__ __forceinline__ float sigm(float x) { return 1.f / (1.f + __expf(-x)); }

__device__ __forceinline__ void cpa16(void* dst, const void* src) {
    unsigned d = (unsigned)__cvta_generic_to_shared(dst);
    asm volatile("cp.async.cg.shared.global [%0], [%1], 16;" :: "r"(d), "l"(src));
}
__device__ __forceinline__ void cpa_commit() {
    asm volatile("cp.async.commit_group;" ::: "memory");
}
template <int N>
__device__ __forceinline__ void cpa_wait() {
    asm volatile("cp.async.wait_group %0;" :: "n"(N) : "memory");
}

__device__ __forceinline__ void grid_barrier() {
    __syncthreads();
    if (threadIdx.x == 0) {
        volatile unsigned* genp = &g_bar_gen;
        unsigned gen = *genp;
        __threadfence();
        unsigned arr = atomicAdd(&g_bar_cnt, 1u);
        if (arr == NCTA - 1) {
            g_bar_cnt = 0u;
            __threadfence();
            atomicAdd(&g_bar_gen, 1u);
        } else {
            while (*genp == gen) { __nanosleep(64); }
        }
        __threadfence();
    }
    __syncthreads();
}

struct ChunkSrc {
    const float* A;
    const float* WT;
    size_t lda;
    int ldw;
    int k0;
};

// Stage one 64-K chunk into smem buffers (group grp, buffer db) via cp.async.
__device__ __forceinline__ void stage_chunk(Smem* s, int grp, int db, const ChunkSrc& c,
                                            int hc4, int q) {
#pragma unroll
    for (int it = 0; it < 16; it++) {
        int idx = it * GQ + q;
        int r = idx >> 4, gg = idx & 15;
        const float* src = c.A + (size_t)r * c.lda + c.k0 + gg * 4;
        float* dst = &s->a[grp][db][r][(gg ^ ((r >> 2) & 7)) << 2];
        cpa16(dst, src);
    }
#pragma unroll
    for (int it = 0; it < 2; it++) {
        int idx = it * GQ + q;
        int col = idx >> 4, gg = idx & 15;
        int wtrow = (col >> 2) * NH + hc4 + (col & 3);
        const float* src = c.WT + (size_t)wtrow * c.ldw + c.k0 + gg * 4;
        float* dst = &s->w[grp][db][col][(gg ^ (col >> 2)) << 2];
        cpa16(dst, src);
    }
}

// 4x4 register tile, f32x2 packed MACs, conflict-free LDS.128 via XOR swizzle.
__device__ __forceinline__ void compute_chunk(const Smem* s, int grp, int db,
                                              unsigned long long* acc,
                                              unsigned long long* acc2, int rg, int cg) {
    const float* a0 = s->a[grp][db][rg * 4 + 0];
    const float* a1 = s->a[grp][db][rg * 4 + 1];
    const float* a2 = s->a[grp][db][rg * 4 + 2];
    const float* a3 = s->a[grp][db][rg * 4 + 3];
    const float* w0 = s->w[grp][db][cg * 4 + 0];
    const float* w1 = s->w[grp][db][cg * 4 + 1];
    const float* w2 = s->w[grp][db][cg * 4 + 2];
    const float* w3 = s->w[grp][db][cg * 4 + 3];
    const int swa = rg & 7;
#pragma unroll 2
    for (int gg = 0; gg < 16; gg++) {
        int ga = (gg ^ swa) << 2;
        int gw = (gg ^ cg) << 2;
        ulonglong2 av0 = *reinterpret_cast<const ulonglong2*>(a0 + ga);
        ulonglong2 av1 = *reinterpret_cast<const ulonglong2*>(a1 + ga);
        ulonglong2 av2 = *reinterpret_cast<const ulonglong2*>(a2 + ga);
        ulonglong2 av3 = *reinterpret_cast<const ulonglong2*>(a3 + ga);
        ulonglong2 wv0 = *reinterpret_cast<const ulonglong2*>(w0 + gw);
        ulonglong2 wv1 = *reinterpret_cast<const ulonglong2*>(w1 + gw);
        ulonglong2 wv2 = *reinterpret_cast<const ulonglong2*>(w2 + gw);
        ulonglong2 wv3 = *reinterpret_cast<const ulonglong2*>(w3 + gw);
        ffma2(acc[0],  av0.x, wv0.x); ffma2(acc2[0],  av0.y, wv0.y);
        ffma2(acc[1],  av0.x, wv1.x); ffma2(acc2[1],  av0.y, wv1.y);
        ffma2(acc[2],  av0.x, wv2.x); ffma2(acc2[2],  av0.y, wv2.y);
        ffma2(acc[3],  av0.x, wv3.x); ffma2(acc2[3],  av0.y, wv3.y);
        ffma2(acc[4],  av1.x, wv0.x); ffma2(acc2[4],  av1.y, wv0.y);
        ffma2(acc[5],  av1.x, wv1.x); ffma2(acc2[5],  av1.y, wv1.y);
        ffma2(acc[6],  av1.x, wv2.x); ffma2(acc2[6],  av1.y, wv2.y);
        ffma2(acc[7],  av1.x, wv3.x); ffma2(acc2[7],  av1.y, wv3.y);
        ffma2(acc[8],  av2.x, wv0.x); ffma2(acc2[8],  av2.y, wv0.y);
        ffma2(acc[9],  av2.x, wv1.x); ffma2(acc2[9],  av2.y, wv1.y);
        ffma2(acc[10], av2.x, wv2.x); ffma2(acc2[10], av2.y, wv2.y);
        ffma2(acc[11], av2.x, wv3.x); ffma2(acc2[11], av2.y, wv3.y);
        ffma2(acc[12], av3.x, wv0.x); ffma2(acc2[12], av3.y, wv0.y);
        ffma2(acc[13], av3.x, wv1.x); ffma2(acc2[13], av3.y, wv1.y);
        ffma2(acc[14], av3.x, wv2.x); ffma2(acc2[14], av3.y, wv2.y);
        ffma2(acc[15], av3.x, wv3.x); ffma2(acc2[15], av3.y, wv3.y);
    }
}

__device__ __forceinline__ void gemm_run(Smem* s, int grp, const ChunkSrc* cs, int nc2,
                                         unsigned long long* acc, unsigned long long* acc2,
                                         int rg, int cg, int hc4, int q) {
    stage_chunk(s, grp, 0, cs[0], hc4, q);
    cpa_commit();
    int db = 0;
    for (int u = 0; u < nc2; u++) {
        if (u + 1 < nc2) {
            stage_chunk(s, grp, db ^ 1, cs[u + 1], hc4, q);
            cpa_commit();
            cpa_wait<1>();
        } else {
            cpa_commit();
            cpa_wait<0>();
        }
        __syncthreads();
        compute_chunk(s, grp, db, acc, acc2, rg, cg);
        __syncthreads();
        db ^= 1;
    }
}

__global__ void transpose_k(const float* __restrict__ in, float* __restrict__ out,
                            int R, int C) {
    __shared__ float tile[32][33];
    size_t base = (size_t)blockIdx.z * (size_t)R * C;
    int c0 = blockIdx.x * 32, r0 = blockIdx.y * 32;
    int tx = threadIdx.x, ty = threadIdx.y;
#pragma unroll
    for (int i = 0; i < 32; i += 8)
        tile[ty + i][tx] = in[base + (size_t)(r0 + ty + i) * C + c0 + tx];
    __syncthreads();
#pragma unroll
    for (int i = 0; i < 32; i += 8)
        out[base + (size_t)(c0 + ty + i) * R + r0 + tx] = tile[tx][ty + i];
}

__global__ void __launch_bounds__(NTHR, 1)
bilateral_kernel(const float* __restrict__ noise,
                 const float* __restrict__ h_cpl,
                 const float* __restrict__ bvec,
                 const float* __restrict__ Wout,
                 const float* __restrict__ bout,
                 float* __restrict__ out) {
    extern __shared__ char smem_raw[];
    Smem* s = reinterpret_cast<Smem*>(smem_raw);
    const int tid = threadIdx.x;
    const int cta = blockIdx.x;
    const int q = tid & 127;
    const int grp = tid >> 7;
    const int rg = q >> 2, cg = q & 3;
    const int hc4 = cta * 4;

    float* out_seq = out;                             // [B][T][NLAT]
    float* out_hfin = out + (size_t)NB * NT * NLAT;   // [L][B][H]

    const int orow0 = (cta >> 4) * 16;
    const int ocol0 = (cta & 15) * 8;
    const int tr = q >> 3, tc = q & 7;
    const float bout_r = bout[ocol0 + tc];

    // ---- init: zero h[0], zero c-state, stage Wout columns ----
    {
        float* hz = &g_h[0][0][0][0];
        for (int i = cta * NTHR + tid; i < NL * NB * NH; i += NCTA * NTHR) hz[i] = 0.f;
    }
    for (int i = tid; i < NL * NB * 4; i += NTHR) (&s->cst[0][0][0])[i] = 0.f;
    for (int i = tid; i < NH * 8; i += NTHR) {
        int k = i >> 3, c = i & 7;
        s->woutc[k][c] = Wout[(size_t)k * NLAT + ocol0 + c];
    }
    __syncthreads();

    // ---- bias = h_coupled @ Wc + b (time-invariant), split-K across groups ----
    for (int l = 0; l < NL; l++) {
        unsigned long long acc[16], acc2[16];
#pragma unroll
        for (int m = 0; m < 16; m++) { acc[m] = 0ull; acc2[m] = 0ull; }
        ChunkSrc cs[8];
        for (int u = 0; u < 4; u++) {
            int c = grp + 2 * u;
            cs[u].A = h_cpl + (size_t)l * NB * NH;
            cs[u].WT = g_wct[l];
            cs[u].lda = NH; cs[u].ldw = NH; cs[u].k0 = c * 64;
        }
        gemm_run(s, grp, cs, 4, acc, acc2, rg, cg, hc4, q);
        float val[16];
#pragma unroll
        for (int m = 0; m < 16; m++) {
            float2 va = unpack2(acc[m]), vb = unpack2(acc2[m]);
            val[m] = (va.x + va.y) + (vb.x + vb.y);
        }
        if (grp == 1) {
#pragma unroll
            for (int i = 0; i < 4; i++)
#pragma unroll
                for (int j = 0; j < 4; j++)
                    s->pex[rg * 4 + i][cg * 4 + j] = val[i * 4 + j];
        }
        __syncthreads();
        if (grp == 0) {
#pragma unroll
            for (int i = 0; i < 4; i++)
#pragma unroll
                for (int j = 0; j < 4; j++)
                    s->bias[l][rg * 4 + i][cg * 4 + j] =
                        val[i * 4 + j] + s->pex[rg * 4 + i][cg * 4 + j] +
                        bvec[l * NG + cg * NH + hc4 + j];
        }
        __syncthreads();
    }
    grid_barrier();

    // ---- main recurrence ----
    for (int t = 0; t < NT; t++) {
        const int rd = t & 1, wr = rd ^ 1;
        for (int l = 0; l < NL; l++) {
            unsigned long long acc[16], acc2[16];
#pragma unroll
            for (int m = 0; m < 16; m++) { acc[m] = 0ull; acc2[m] = 0ull; }

            const int nc2 = (l == 0) ? 5 : 8;
            ChunkSrc cs[8];
            for (int u = 0; u < nc2; u++) {
                int c = grp + 2 * u;
                if (l == 0) {
                    if (c < 2) {
                        cs[u].A = noise + (size_t)t * NDIM;
                        cs[u].lda = (size_t)NT * NDIM;
                        cs[u].WT = g_wx0t; cs[u].ldw = NDIM; cs[u].k0 = c * 64;
                    } else {
                        cs[u].A = &g_h[rd][0][0][0]; cs[u].lda = NH;
                        cs[u].WT = g_wht[0]; cs[u].ldw = NH; cs[u].k0 = (c - 2) * 64;
                    }
                } else {
                    if (c < 8) {
                        cs[u].A = &g_h[wr][l - 1][0][0]; cs[u].lda = NH;
                        cs[u].WT = g_wxrt[l - 1]; cs[u].ldw = NH; cs[u].k0 = c * 64;
                    } else {
                        cs[u].A = &g_h[rd][l][0][0]; cs[u].lda = NH;
                        cs[u].WT = g_wht[l]; cs[u].ldw = NH; cs[u].k0 = (c - 8) * 64;
                    }
                }
            }
            gemm_run(s, grp, cs, nc2, acc, acc2, rg, cg, hc4, q);

            float val[16];
#pragma unroll
            for (int m = 0; m < 16; m++) {
                float2 va = unpack2(acc[m]), vb = unpack2(acc2[m]);
                val[m] = (va.x + va.y) + (vb.x + vb.y);
            }
            if (grp == 1) {
#pragma unroll
                for (int i = 0; i < 4; i++)
#pragma unroll
                    for (int j = 0; j < 4; j++)
                        s->pex[rg * 4 + i][cg * 4 + j] = val[i * 4 + j];
            }
            __syncthreads();
            if (grp == 0) {
#pragma unroll
                for (int i = 0; i < 4; i++)
#pragma unroll
                    for (int j = 0; j < 4; j++)
                        s->gex[cg][rg * 4 + i][j] =
                            val[i * 4 + j] + s->pex[rg * 4 + i][cg * 4 + j] +
                            s->bias[l][rg * 4 + i][cg * 4 + j];
            }
            __syncthreads();

            if (tid < NB) {
                const int b = tid;
#pragma unroll
                for (int j = 0; j < 4; j++) {
                    float ig = s->gex[0][b][j];
                    float fg = s->gex[1][b][j];
                    float gg = s->gex[2][b][j];
                    float og = s->gex[3][b][j];
                    float c_new = sigm(fg) * s->cst[l][b][j] + sigm(ig) * tanhf(gg);
                    float h_new = sigm(og) * tanhf(c_new);
                    s->cst[l][b][j] = c_new;
                    g_h[wr][l][b][hc4 + j] = h_new;
                    if (t == NT - 1)
                        out_hfin[(size_t)l * NB * NH + (size_t)b * NH + hc4 + j] = h_new;
                }
            }
            grid_barrier();
        }

        // ---- output projection, split-K across groups ----
        {
            const float* hrow = &g_h[wr][2][orow0 + tr][0] + (grp << 8);
            float accp = grp ? 0.f : bout_r;
            const int kb = grp << 8;
#pragma unroll 8
            for (int k = 0; k < 256; k += 4) {
                float4 hv = __ldcg(reinterpret_cast<const float4*>(hrow + k));
                accp += hv.x * s->woutc[kb + k + 0][tc];
                accp += hv.y * s->woutc[kb + k + 1][tc];
                accp += hv.z * s->woutc[kb + k + 2][tc];
                accp += hv.w * s->woutc[kb + k + 3][tc];
            }
            if (grp == 1) s->opart[q] = accp;
            __syncthreads();
            if (grp == 0) {
                accp += s->opart[q];
                out_seq[(size_t)(orow0 + tr) * NT * NLAT + (size_t)t * NLAT + ocol0 + tc] =
                    sigm(accp);
            }
        }
    }
}

extern "C" void kernel_launch(void* const* d_in, const int* in_sizes, int n_in,
                              void* d_out, int out_size) {
    const float* noise = (const float*)d_in[0];
    const float* h_cpl = (const float*)d_in[1];
    const float* Wx0   = (const float*)d_in[2];
    const float* Wxr   = (const float*)d_in[3];
    const float* Wh    = (const float*)d_in[4];
    const float* Wc    = (const float*)d_in[5];
    const float* bvec  = (const float*)d_in[6];
    const float* Wout  = (const float*)d_in[7];
    const float* bout  = (const float*)d_in[8];
    float* out = (float*)d_out;

    float *wx0t, *wxrt, *wht, *wct;
    cudaGetSymbolAddress((void**)&wx0t, g_wx0t);
    cudaGetSymbolAddress((void**)&wxrt, g_wxrt);
    cudaGetSymbolAddress((void**)&wht, g_wht);
    cudaGetSymbolAddress((void**)&wct, g_wct);

    dim3 tthr(32, 8);
    transpose_k<<<dim3(NG / 32, NDIM / 32, 1), tthr>>>(Wx0, wx0t, NDIM, NG);
    transpose_k<<<dim3(NG / 32, NH / 32, NL - 1), tthr>>>(Wxr, wxrt, NH, NG);
    transpose_k<<<dim3(NG / 32, NH / 32, NL), tthr>>>(Wh, wht, NH, NG);
    transpose_k<<<dim3(NG / 32, NH / 32, NL), tthr>>>(Wc, wct, NH, NG);

    cudaFuncSetAttribute(bilateral_kernel, cudaFuncAttributeMaxDynamicSharedMemorySize,
                         (int)sizeof(Smem));
    bilateral_kernel<<<NCTA, NTHR, sizeof(Smem)>>>(noise, h_cpl, bvec, Wout, bout, out);
}

// round 5
// speedup vs baseline: 1.4384x; 1.1755x over previous
#include <cuda_runtime.h>

#define NB 128
#define NT 512
#define NDIM 128
#define NH 512
#define NG 2048
#define NLAT 128
#define NL 3
#define NCTA 128
#define NTHR 256
#define GQ 128   // threads per split-K group

struct Smem {
    float a[2][2][NB][64];     // [group][dbuf][row][k-swizzled]  (also transpose tile scratch)
    float w[2][2][16][64];     // [group][dbuf][col][k-swizzled]
    float bias[NL][NB][16];
    float cst[NL][NB][4];
    float gex[4][NB][5];
    float pex[NB][17];
    float woutc[NH][8];
    float opart[NB];
};

__device__ float g_h[2][NL][NB][NH];
__device__ float g_wx0t[NG * NDIM];        // Wx0^T  [2048][128]
__device__ float g_wxrt[NL - 1][NG * NH];  // Wxr^T  [2][2048][512]
__device__ float g_wht[NL][NG * NH];       // Wh^T   [3][2048][512]
__device__ float g_wct[NL][NG * NH];       // Wc^T   [3][2048][512]
__device__ unsigned g_flags[NCTA];         // monotonically increasing across calls

__device__ __forceinline__ void ffma2(unsigned long long& d, unsigned long long a,
                                      unsigned long long b) {
    asm volatile("fma.rn.f32x2 %0, %1, %2, %0;" : "+l"(d) : "l"(a), "l"(b));
}
__device__ __forceinline__ float2 unpack2(unsigned long long v) {
    float2 r;
    asm("mov.b64 {%0, %1}, %2;" : "=f"(r.x), "=f"(r.y) : "l"(v));
    return r;
}
__device__ __forceinline__ float sigm(float x) { return 1.f / (1.f + __expf(-x)); }

__device__ __forceinline__ void cpa16(void* dst, const void* src) {
    unsigned d = (unsigned)__cvta_generic_to_shared(dst);
    asm volatile("cp.async.cg.shared.global [%0], [%1], 16;" :: "r"(d), "l"(src));
}
__device__ __forceinline__ void cpa_commit() {
    asm volatile("cp.async.commit_group;" ::: "memory");
}
template <int N>
__device__ __forceinline__ void cpa_wait() {
    asm volatile("cp.async.wait_group %0;" :: "n"(N) : "memory");
}
__device__ __forceinline__ void group_bar(int grp) {
    asm volatile("bar.sync %0, 128;" :: "r"(grp + 1) : "memory");
}

// Flag-array grid barrier: contention-free arrival, parallel polling.
__device__ __forceinline__ void grid_barrier2(int cta, unsigned target) {
    __syncthreads();
    if (threadIdx.x == 0) {
        __threadfence();
        atomicExch(&g_flags[cta], target);
    }
    for (;;) {
        unsigned v = (threadIdx.x < NCTA) ? __ldcg(&g_flags[threadIdx.x]) : target;
        if (__syncthreads_count((int)(v < target)) == 0) break;
    }
    __threadfence();
}

struct ChunkSrc {
    const float* A;
    const float* WT;
    size_t lda;
    int ldw;
    int k0;
};

__device__ __forceinline__ void stage_chunk(Smem* s, int grp, int db, const ChunkSrc& c,
                                            int hc4, int q) {
#pragma unroll
    for (int it = 0; it < 16; it++) {
        int idx = it * GQ + q;
        int r = idx >> 4, gg = idx & 15;
        const float* src = c.A + (size_t)r * c.lda + c.k0 + gg * 4;
        float* dst = &s->a[grp][db][r][(gg ^ ((r >> 2) & 7)) << 2];
        cpa16(dst, src);
    }
#pragma unroll
    for (int it = 0; it < 2; it++) {
        int idx = it * GQ + q;
        int col = idx >> 4, gg = idx & 15;
        int wtrow = (col >> 2) * NH + hc4 + (col & 3);
        const float* src = c.WT + (size_t)wtrow * c.ldw + c.k0 + gg * 4;
        float* dst = &s->w[grp][db][col][(gg ^ (col >> 2)) << 2];
        cpa16(dst, src);
    }
}

__device__ __forceinline__ void ldpair(const Smem* s, int grp, int db, int rg, int cg,
                                       int gg, ulonglong2* Av, ulonglong2* Wv) {
    const int ga = (gg ^ (rg & 7)) << 2;
    const int gw = (gg ^ cg) << 2;
#pragma unroll
    for (int i = 0; i < 4; i++)
        Av[i] = *reinterpret_cast<const ulonglong2*>(&s->a[grp][db][rg * 4 + i][ga]);
#pragma unroll
    for (int j = 0; j < 4; j++)
        Wv[j] = *reinterpret_cast<const ulonglong2*>(&s->w[grp][db][cg * 4 + j][gw]);
}
__device__ __forceinline__ void fmablk(const ulonglong2* Av, const ulonglong2* Wv,
                                       unsigned long long* acc, unsigned long long* acc2) {
#pragma unroll
    for (int i = 0; i < 4; i++)
#pragma unroll
        for (int j = 0; j < 4; j++) {
            ffma2(acc[i * 4 + j], Av[i].x, Wv[j].x);
            ffma2(acc2[i * 4 + j], Av[i].y, Wv[j].y);
        }
}

// Software-pipelined 4x4-tile chunk compute: operand LDS for gg+1 issued
// before FMAs of gg consume their operands.
__device__ __forceinline__ void compute_chunk(const Smem* s, int grp, int db,
                                              unsigned long long* acc,
                                              unsigned long long* acc2, int rg, int cg) {
    ulonglong2 A0[4], W0[4], A1[4], W1[4];
    ldpair(s, grp, db, rg, cg, 0, A0, W0);
#pragma unroll
    for (int g = 0; g < 16; g += 2) {
        ldpair(s, grp, db, rg, cg, g + 1, A1, W1);
        fmablk(A0, W0, acc, acc2);
        if (g + 2 < 16) ldpair(s, grp, db, rg, cg, g + 2, A0, W0);
        fmablk(A1, W1, acc, acc2);
    }
}

__device__ __forceinline__ void gemm_run(Smem* s, int grp, const ChunkSrc* cs, int nc2,
                                         unsigned long long* acc, unsigned long long* acc2,
                                         int rg, int cg, int hc4, int q) {
    stage_chunk(s, grp, 0, cs[0], hc4, q);
    cpa_commit();
    int db = 0;
    for (int u = 0; u < nc2; u++) {
        if (u + 1 < nc2) {
            stage_chunk(s, grp, db ^ 1, cs[u + 1], hc4, q);
            cpa_commit();
            cpa_wait<1>();
        } else {
            cpa_wait<0>();
        }
        group_bar(grp);
        compute_chunk(s, grp, db, acc, acc2, rg, cg);
        group_bar(grp);
        db ^= 1;
    }
}

__global__ void __launch_bounds__(NTHR, 1)
bilateral_kernel(const float* __restrict__ noise,
                 const float* __restrict__ h_cpl,
                 const float* __restrict__ Wx0,
                 const float* __restrict__ Wxr,
                 const float* __restrict__ Wh,
                 const float* __restrict__ Wc,
                 const float* __restrict__ bvec,
                 const float* __restrict__ Wout,
                 const float* __restrict__ bout,
                 float* __restrict__ out) {
    extern __shared__ char smem_raw[];
    Smem* s = reinterpret_cast<Smem*>(smem_raw);
    const int tid = threadIdx.x;
    const int cta = blockIdx.x;
    const int q = tid & 127;
    const int grp = tid >> 7;
    const int rg = q >> 2, cg = q & 3;
    const int hc4 = cta * 4;

    // barrier bookkeeping (monotonic across calls; all flags equal at call entry)
    unsigned bar_t = g_flags[cta];

    float* out_seq = out;                             // [B][T][NLAT]
    float* out_hfin = out + (size_t)NB * NT * NLAT;   // [L][B][H]

    const int orow0 = (cta >> 4) * 16;
    const int ocol0 = (cta & 15) * 8;
    const int tr = q >> 3, tc = q & 7;
    const float bout_r = bout[ocol0 + tc];

    // ---- phase 0: zero h[0], zero c-state, stage Wout columns ----
    {
        float* hz = &g_h[0][0][0][0];
        for (int i = cta * NTHR + tid; i < NL * NB * NH; i += NCTA * NTHR) hz[i] = 0.f;
    }
    for (int i = tid; i < NL * NB * 4; i += NTHR) (&s->cst[0][0][0])[i] = 0.f;
    for (int i = tid; i < NH * 8; i += NTHR) {
        int k = i >> 3, c = i & 7;
        s->woutc[k][c] = Wout[(size_t)k * NLAT + ocol0 + c];
    }

    // ---- phase 0b: in-kernel weight transposes (once per call) ----
    {
        float (*tile)[33] = reinterpret_cast<float (*)[33]>(&s->a[0][0][0][0]);
        const int tx = tid & 31, ty = tid >> 5;
        for (int idx = cta; idx < 8448; idx += NCTA) {
            const float* src;
            float* dst;
            int R, t;
            if (idx < 256) {
                src = Wx0; dst = g_wx0t; R = NDIM; t = idx;
            } else {
                int j = (idx - 256) >> 10;
                t = (idx - 256) & 1023;
                R = NH;
                if (j < 2)      { src = Wxr + (size_t)j * NH * NG;       dst = g_wxrt[j]; }
                else if (j < 5) { src = Wh  + (size_t)(j - 2) * NH * NG; dst = g_wht[j - 2]; }
                else            { src = Wc  + (size_t)(j - 5) * NH * NG; dst = g_wct[j - 5]; }
            }
            const int tr_ = t >> 6, tc_ = t & 63;
            const int r0 = tr_ * 32, c0 = tc_ * 32;
            __syncthreads();
#pragma unroll
            for (int i = 0; i < 32; i += 8)
                tile[ty + i][tx] = src[(size_t)(r0 + ty + i) * NG + c0 + tx];
            __syncthreads();
#pragma unroll
            for (int i = 0; i < 32; i += 8)
                dst[(size_t)(c0 + ty + i) * R + r0 + tx] = tile[tx][ty + i];
        }
    }
    grid_barrier2(cta, ++bar_t);  // transposes + h zeros visible everywhere

    // ---- phase 0c: bias = h_coupled @ Wc + b (time-invariant), split-K ----
    for (int l = 0; l < NL; l++) {
        unsigned long long acc[16], acc2[16];
#pragma unroll
        for (int m = 0; m < 16; m++) { acc[m] = 0ull; acc2[m] = 0ull; }
        ChunkSrc cs[8];
        for (int u = 0; u < 4; u++) {
            int c = grp + 2 * u;
            cs[u].A = h_cpl + (size_t)l * NB * NH;
            cs[u].WT = g_wct[l];
            cs[u].lda = NH; cs[u].ldw = NH; cs[u].k0 = c * 64;
        }
        gemm_run(s, grp, cs, 4, acc, acc2, rg, cg, hc4, q);
        float val[16];
#pragma unroll
        for (int m = 0; m < 16; m++) {
            float2 va = unpack2(acc[m]), vb = unpack2(acc2[m]);
            val[m] = (va.x + va.y) + (vb.x + vb.y);
        }
        if (grp == 1) {
#pragma unroll
            for (int i = 0; i < 4; i++)
#pragma unroll
                for (int j = 0; j < 4; j++)
                    s->pex[rg * 4 + i][cg * 4 + j] = val[i * 4 + j];
        }
        __syncthreads();
        if (grp == 0) {
#pragma unroll
            for (int i = 0; i < 4; i++)
#pragma unroll
                for (int j = 0; j < 4; j++)
                    s->bias[l][rg * 4 + i][cg * 4 + j] =
                        val[i * 4 + j] + s->pex[rg * 4 + i][cg * 4 + j] +
                        bvec[l * NG + cg * NH + hc4 + j];
        }
        __syncthreads();
    }

    // ---- main recurrence ----
    for (int t = 0; t < NT; t++) {
        const int rd = t & 1, wr = rd ^ 1;
        for (int l = 0; l < NL; l++) {
            unsigned long long acc[16], acc2[16];
#pragma unroll
            for (int m = 0; m < 16; m++) { acc[m] = 0ull; acc2[m] = 0ull; }

            const int nc2 = (l == 0) ? 5 : 8;
            ChunkSrc cs[8];
            for (int u = 0; u < nc2; u++) {
                int c = grp + 2 * u;
                if (l == 0) {
                    if (c < 2) {
                        cs[u].A = noise + (size_t)t * NDIM;
                        cs[u].lda = (size_t)NT * NDIM;
                        cs[u].WT = g_wx0t; cs[u].ldw = NDIM; cs[u].k0 = c * 64;
                    } else {
                        cs[u].A = &g_h[rd][0][0][0]; cs[u].lda = NH;
                        cs[u].WT = g_wht[0]; cs[u].ldw = NH; cs[u].k0 = (c - 2) * 64;
                    }
                } else {
                    if (c < 8) {
                        cs[u].A = &g_h[wr][l - 1][0][0]; cs[u].lda = NH;
                        cs[u].WT = g_wxrt[l - 1]; cs[u].ldw = NH; cs[u].k0 = c * 64;
                    } else {
                        cs[u].A = &g_h[rd][l][0][0]; cs[u].lda = NH;
                        cs[u].WT = g_wht[l]; cs[u].ldw = NH; cs[u].k0 = (c - 8) * 64;
                    }
                }
            }
            gemm_run(s, grp, cs, nc2, acc, acc2, rg, cg, hc4, q);

            float val[16];
#pragma unroll
            for (int m = 0; m < 16; m++) {
                float2 va = unpack2(acc[m]), vb = unpack2(acc2[m]);
                val[m] = (va.x + va.y) + (vb.x + vb.y);
            }
            if (grp == 1) {
#pragma unroll
                for (int i = 0; i < 4; i++)
#pragma unroll
                    for (int j = 0; j < 4; j++)
                        s->pex[rg * 4 + i][cg * 4 + j] = val[i * 4 + j];
            }
            __syncthreads();
            if (grp == 0) {
#pragma unroll
                for (int i = 0; i < 4; i++)
#pragma unroll
                    for (int j = 0; j < 4; j++)
                        s->gex[cg][rg * 4 + i][j] =
                            val[i * 4 + j] + s->pex[rg * 4 + i][cg * 4 + j] +
                            s->bias[l][rg * 4 + i][cg * 4 + j];
            }
            __syncthreads();

            if (tid < NB) {
                const int b = tid;
#pragma unroll
                for (int j = 0; j < 4; j++) {
                    float ig = s->gex[0][b][j];
                    float fg = s->gex[1][b][j];
                    float gg = s->gex[2][b][j];
                    float og = s->gex[3][b][j];
                    float c_new = sigm(fg) * s->cst[l][b][j] + sigm(ig) * tanhf(gg);
                    float h_new = sigm(og) * tanhf(c_new);
                    s->cst[l][b][j] = c_new;
                    g_h[wr][l][b][hc4 + j] = h_new;
                    if (t == NT - 1)
                        out_hfin[(size_t)l * NB * NH + (size_t)b * NH + hc4 + j] = h_new;
                }
            }
            grid_barrier2(cta, ++bar_t);
        }

        // ---- output projection, split-K across groups ----
        {
            const float* hrow = &g_h[wr][2][orow0 + tr][0] + (grp << 8);
            float accp = grp ? 0.f : bout_r;
            const int kb = grp << 8;
#pragma unroll 8
            for (int k = 0; k < 256; k += 4) {
                float4 hv = __ldcg(reinterpret_cast<const float4*>(hrow + k));
                accp += hv.x * s->woutc[kb + k + 0][tc];
                accp += hv.y * s->woutc[kb + k + 1][tc];
                accp += hv.z * s->woutc[kb + k + 2][tc];
                accp += hv.w * s->woutc[kb + k + 3][tc];
            }
            if (grp == 1) s->opart[q] = accp;
            __syncthreads();
            if (grp == 0) {
                accp += s->opart[q];
                out_seq[(size_t)(orow0 + tr) * NT * NLAT + (size_t)t * NLAT + ocol0 + tc] =
                    sigm(accp);
            }
            __syncthreads();
        }
    }
}

extern "C" void kernel_launch(void* const* d_in, const int* in_sizes, int n_in,
                              void* d_out, int out_size) {
    const float* noise = (const float*)d_in[0];
    const float* h_cpl = (const float*)d_in[1];
    const float* Wx0   = (const float*)d_in[2];
    const float* Wxr   = (const float*)d_in[3];
    const float* Wh    = (const float*)d_in[4];
    const float* Wc    = (const float*)d_in[5];
    const float* bvec  = (const float*)d_in[6];
    const float* Wout  = (const float*)d_in[7];
    const float* bout  = (const float*)d_in[8];
    float* out = (float*)d_out;

    cudaFuncSetAttribute(bilateral_kernel, cudaFuncAttributeMaxDynamicSharedMemorySize,
                         (int)sizeof(Smem));
    bilateral_kernel<<<NCTA, NTHR, sizeof(Smem)>>>(noise, h_cpl, Wx0, Wxr, Wh, Wc,
                                                   bvec, Wout, bout, out);
}

// round 6
// speedup vs baseline: 1.5244x; 1.0598x over previous
#include <cuda_runtime.h>
#include <cuda_bf16.h>

#define NB 128
#define NT 512
#define NDIM 128
#define NH 512
#define NG 2048
#define NLAT 128
#define NL 3
#define NCTA 128
#define NTHR 256
#define AK 72     // padded bf16 row stride (144B)

struct Smem {
    __nv_bfloat16 a[2][2][NB][AK];   // [dbuf][hi/lo][row][k]
    __nv_bfloat16 w[2][2][16][AK];   // [dbuf][hi/lo][col][k]
    float bias[NL][NB][16];
    float cst[NL][NB][4];
    float gex[4][NB][5];
    float woutc[NH][8];
    float opart[NB];
};

__device__ float g_h2[NB][NH];                       // fp32 layer-2 h (projection)
__device__ __nv_bfloat16 g_hb[2][2][NL][NB][NH];     // [pingpong][hi/lo]
__device__ __nv_bfloat16 g_nb[2][NB * NT * NDIM];    // noise hi/lo
__device__ __nv_bfloat16 g_cb[2][NL * NB * NH];      // h_coupled hi/lo
__device__ __nv_bfloat16 g_wx0t[2][NG * NDIM];
__device__ __nv_bfloat16 g_wxrt[2][(NL - 1) * NG * NH];
__device__ __nv_bfloat16 g_wht[2][NL * NG * NH];
__device__ __nv_bfloat16 g_wct[2][NL * NG * NH];
__device__ unsigned g_flags[NCTA];

__device__ __forceinline__ float sigm(float x) { return 1.f / (1.f + __expf(-x)); }

__device__ __forceinline__ void split_bf16(float v, __nv_bfloat16& hi, __nv_bfloat16& lo) {
    unsigned u = __float_as_uint(v);
    hi = __ushort_as_bfloat16((unsigned short)(u >> 16));
    float hf = __uint_as_float(u & 0xFFFF0000u);
    lo = __float2bfloat16(v - hf);
}

__device__ __forceinline__ void cpa16(void* dst, const void* src) {
    unsigned d = (unsigned)__cvta_generic_to_shared(dst);
    asm volatile("cp.async.cg.shared.global [%0], [%1], 16;" :: "r"(d), "l"(src));
}
__device__ __forceinline__ void cpa_commit() {
    asm volatile("cp.async.commit_group;" ::: "memory");
}
template <int N>
__device__ __forceinline__ void cpa_wait() {
    asm volatile("cp.async.wait_group %0;" :: "n"(N) : "memory");
}

__device__ __forceinline__ void ldsm4(unsigned& r0, unsigned& r1, unsigned& r2,
                                      unsigned& r3, unsigned addr) {
    asm volatile("ldmatrix.sync.aligned.m8n8.x4.shared.b16 {%0,%1,%2,%3}, [%4];"
                 : "=r"(r0), "=r"(r1), "=r"(r2), "=r"(r3) : "r"(addr));
}
__device__ __forceinline__ void mma16816(float* c, unsigned a0, unsigned a1, unsigned a2,
                                         unsigned a3, unsigned b0, unsigned b1) {
    asm volatile(
        "mma.sync.aligned.m16n8k16.row.col.f32.bf16.bf16.f32 "
        "{%0,%1,%2,%3}, {%4,%5,%6,%7}, {%8,%9}, {%0,%1,%2,%3};"
        : "+f"(c[0]), "+f"(c[1]), "+f"(c[2]), "+f"(c[3])
        : "r"(a0), "r"(a1), "r"(a2), "r"(a3), "r"(b0), "r"(b1));
}

__device__ __forceinline__ void grid_barrier2(int cta, unsigned target) {
    __syncthreads();
    if (threadIdx.x == 0) {
        __threadfence();
        atomicExch(&g_flags[cta], target);
    }
    for (;;) {
        unsigned v = (threadIdx.x < NCTA) ? __ldcg(&g_flags[threadIdx.x]) : target;
        if (__syncthreads_count((int)(v < target)) == 0) break;
    }
    __threadfence();
}

struct ChunkSrc {
    const __nv_bfloat16* Ahi;
    const __nv_bfloat16* Alo;
    const __nv_bfloat16* Whi;
    const __nv_bfloat16* Wlo;
    int lda;
    int ldw;
    int k0;
};

__device__ __forceinline__ void stage_chunk(Smem* s, int db, const ChunkSrc& c,
                                            int tid, int hc4) {
#pragma unroll
    for (int it = 0; it < 4; it++) {
        int idx = it * NTHR + tid;       // 0..1023
        int r = idx >> 3, kq = idx & 7;
        size_t off = (size_t)r * c.lda + c.k0 + kq * 8;
        cpa16(&s->a[db][0][r][kq * 8], c.Ahi + off);
        cpa16(&s->a[db][1][r][kq * 8], c.Alo + off);
    }
    {
        int idx = tid;                   // 0..255
        int hl = idx >> 7, cc = (idx >> 3) & 15, kq = idx & 7;
        int wtrow = (cc >> 2) * NH + hc4 + (cc & 3);
        const __nv_bfloat16* src = hl ? c.Wlo : c.Whi;
        cpa16(&s->w[db][hl][cc][kq * 8], src + (size_t)wtrow * c.ldw + c.k0 + kq * 8);
    }
}

__device__ __forceinline__ void compute_chunk(Smem* s, int db, float* C0, float* C1,
                                              int warp, int lane) {
    const int ar = warp * 16 + (lane & 15);
    const int ak = (lane >> 4) * 8;
    unsigned ah_b = (unsigned)__cvta_generic_to_shared(&s->a[db][0][ar][ak]);
    unsigned al_b = (unsigned)__cvta_generic_to_shared(&s->a[db][1][ar][ak]);
    const int bc = (lane & 7) + ((lane >= 16) ? 8 : 0);
    const int bk = ((lane >> 3) & 1) * 8;
    unsigned bh_b = (unsigned)__cvta_generic_to_shared(&s->w[db][0][bc][bk]);
    unsigned bl_b = (unsigned)__cvta_generic_to_shared(&s->w[db][1][bc][bk]);
#pragma unroll
    for (int ks = 0; ks < 4; ks++) {
        unsigned ah0, ah1, ah2, ah3, al0, al1, al2, al3;
        unsigned bh0, bh1, bh2, bh3, bl0, bl1, bl2, bl3;
        ldsm4(ah0, ah1, ah2, ah3, ah_b + ks * 32);
        ldsm4(bh0, bh1, bh2, bh3, bh_b + ks * 32);
        ldsm4(al0, al1, al2, al3, al_b + ks * 32);
        ldsm4(bl0, bl1, bl2, bl3, bl_b + ks * 32);
        mma16816(C0, ah0, ah1, ah2, ah3, bh0, bh1);
        mma16816(C1, ah0, ah1, ah2, ah3, bh2, bh3);
        mma16816(C0, ah0, ah1, ah2, ah3, bl0, bl1);
        mma16816(C1, ah0, ah1, ah2, ah3, bl2, bl3);
        mma16816(C0, al0, al1, al2, al3, bh0, bh1);
        mma16816(C1, al0, al1, al2, al3, bh2, bh3);
    }
}

__device__ __forceinline__ void gemm_run(Smem* s, const ChunkSrc* cs, int nc,
                                         float* C0, float* C1, int warp, int lane,
                                         int tid, int hc4) {
    stage_chunk(s, 0, cs[0], tid, hc4);
    cpa_commit();
    int db = 0;
    for (int u = 0; u < nc; u++) {
        if (u + 1 < nc) {
            stage_chunk(s, db ^ 1, cs[u + 1], tid, hc4);
            cpa_commit();
            cpa_wait<1>();
        } else {
            cpa_wait<0>();
        }
        __syncthreads();
        compute_chunk(s, db, C0, C1, warp, lane);
        __syncthreads();
        db ^= 1;
    }
}

__global__ void __launch_bounds__(NTHR, 1)
bilateral_kernel(const float* __restrict__ noise,
                 const float* __restrict__ h_cpl,
                 const float* __restrict__ Wx0,
                 const float* __restrict__ Wxr,
                 const float* __restrict__ Wh,
                 const float* __restrict__ Wc,
                 const float* __restrict__ bvec,
                 const float* __restrict__ Wout,
                 const float* __restrict__ bout,
                 float* __restrict__ out) {
    extern __shared__ char smem_raw[];
    Smem* s = reinterpret_cast<Smem*>(smem_raw);
    const int tid = threadIdx.x;
    const int cta = blockIdx.x;
    const int warp = tid >> 5, lane = tid & 31;
    const int hc4 = cta * 4;

    unsigned bar_t = g_flags[cta];

    float* out_seq = out;
    float* out_hfin = out + (size_t)NB * NT * NLAT;

    const int orow0 = (cta >> 4) * 16;
    const int ocol0 = (cta & 15) * 8;
    const int q = tid & 127, grp = tid >> 7;
    const int tr = q >> 3, tc = q & 7;
    const float bout_r = bout[ocol0 + tc];

    // ---- phase 0: conversions + zero init (grid-strided) ----
    for (int i = cta * NTHR + tid; i < NB * NT * NDIM; i += NCTA * NTHR)
        split_bf16(noise[i], g_nb[0][i], g_nb[1][i]);
    for (int i = cta * NTHR + tid; i < NL * NB * NH; i += NCTA * NTHR)
        split_bf16(h_cpl[i], g_cb[0][i], g_cb[1][i]);
    {
        __nv_bfloat16* hz = &g_hb[0][0][0][0][0];
        __nv_bfloat16 z = __float2bfloat16(0.f);
        for (int i = cta * NTHR + tid; i < 2 * NL * NB * NH; i += NCTA * NTHR) hz[i] = z;
    }
    for (int i = tid; i < NL * NB * 4; i += NTHR) (&s->cst[0][0][0])[i] = 0.f;
    for (int i = tid; i < NH * 8; i += NTHR) {
        int k = i >> 3, c = i & 7;
        s->woutc[k][c] = Wout[(size_t)k * NLAT + ocol0 + c];
    }

    // ---- phase 0b: weight transpose + bf16 split ----
    {
        float (*tile)[33] = reinterpret_cast<float (*)[33]>(&s->a[0][0][0][0]);
        const int tx = tid & 31, ty = tid >> 5;
        for (int idx = cta; idx < 8448; idx += NCTA) {
            const float* src;
            __nv_bfloat16 *dh, *dl;
            int R, t;
            if (idx < 256) {
                src = Wx0; dh = g_wx0t[0]; dl = g_wx0t[1]; R = NDIM; t = idx;
            } else {
                int j = (idx - 256) >> 10;
                t = (idx - 256) & 1023;
                R = NH;
                if (j < 2) {
                    src = Wxr + (size_t)j * NH * NG;
                    dh = g_wxrt[0] + (size_t)j * NG * NH; dl = g_wxrt[1] + (size_t)j * NG * NH;
                } else if (j < 5) {
                    src = Wh + (size_t)(j - 2) * NH * NG;
                    dh = g_wht[0] + (size_t)(j - 2) * NG * NH; dl = g_wht[1] + (size_t)(j - 2) * NG * NH;
                } else {
                    src = Wc + (size_t)(j - 5) * NH * NG;
                    dh = g_wct[0] + (size_t)(j - 5) * NG * NH; dl = g_wct[1] + (size_t)(j - 5) * NG * NH;
                }
            }
            const int tr_ = t / (NG / 32), tc_ = t % (NG / 32);
            const int r0 = tr_ * 32, c0 = tc_ * 32;
            __syncthreads();
#pragma unroll
            for (int i = 0; i < 32; i += 8)
                tile[ty + i][tx] = src[(size_t)(r0 + ty + i) * NG + c0 + tx];
            __syncthreads();
#pragma unroll
            for (int i = 0; i < 32; i += 8) {
                float v = tile[tx][ty + i];
                __nv_bfloat16 hi, lo;
                split_bf16(v, hi, lo);
                size_t o = (size_t)(c0 + ty + i) * R + r0 + tx;
                dh[o] = hi;
                dl[o] = lo;
            }
        }
    }
    grid_barrier2(cta, ++bar_t);

    // ---- phase 0c: bias = h_coupled @ Wc + b ----
    for (int l = 0; l < NL; l++) {
        float C0[4] = {0, 0, 0, 0}, C1[4] = {0, 0, 0, 0};
        ChunkSrc cs[16];
        for (int u = 0; u < 8; u++) {
            cs[u].Ahi = g_cb[0] + (size_t)l * NB * NH;
            cs[u].Alo = g_cb[1] + (size_t)l * NB * NH;
            cs[u].Whi = g_wct[0] + (size_t)l * NG * NH;
            cs[u].Wlo = g_wct[1] + (size_t)l * NG * NH;
            cs[u].lda = NH; cs[u].ldw = NH; cs[u].k0 = u * 64;
        }
        gemm_run(s, cs, 8, C0, C1, warp, lane, tid, hc4);
        const int r0 = warp * 16 + (lane >> 2);
        const int cA = 2 * (lane & 3);
#pragma unroll
        for (int nt = 0; nt < 2; nt++) {
            float* C = nt ? C1 : C0;
            int c = nt * 8 + cA;
#pragma unroll
            for (int v = 0; v < 4; v++) {
                int rr = r0 + ((v >> 1) ? 8 : 0);
                int ccol = c + (v & 1);
                s->bias[l][rr][ccol] =
                    C[v] + bvec[l * NG + (ccol >> 2) * NH + hc4 + (ccol & 3)];
            }
        }
        __syncthreads();
    }

    // ---- main recurrence ----
    for (int t = 0; t < NT; t++) {
        const int rd = t & 1, wr = rd ^ 1;
        for (int l = 0; l < NL; l++) {
            float C0[4] = {0, 0, 0, 0}, C1[4] = {0, 0, 0, 0};
            const int nc = (l == 0) ? 10 : 16;
            ChunkSrc cs[16];
            for (int u = 0; u < nc; u++) {
                if (l == 0) {
                    if (u < 2) {
                        cs[u].Ahi = g_nb[0] + (size_t)t * NDIM;
                        cs[u].Alo = g_nb[1] + (size_t)t * NDIM;
                        cs[u].lda = NT * NDIM;
                        cs[u].Whi = g_wx0t[0]; cs[u].Wlo = g_wx0t[1];
                        cs[u].ldw = NDIM; cs[u].k0 = u * 64;
                    } else {
                        cs[u].Ahi = &g_hb[rd][0][0][0][0];
                        cs[u].Alo = &g_hb[rd][1][0][0][0];
                        cs[u].lda = NH;
                        cs[u].Whi = g_wht[0]; cs[u].Wlo = g_wht[1];
                        cs[u].ldw = NH; cs[u].k0 = (u - 2) * 64;
                    }
                } else {
                    if (u < 8) {
                        cs[u].Ahi = &g_hb[wr][0][l - 1][0][0];
                        cs[u].Alo = &g_hb[wr][1][l - 1][0][0];
                        cs[u].lda = NH;
                        cs[u].Whi = g_wxrt[0] + (size_t)(l - 1) * NG * NH;
                        cs[u].Wlo = g_wxrt[1] + (size_t)(l - 1) * NG * NH;
                        cs[u].ldw = NH; cs[u].k0 = u * 64;
                    } else {
                        cs[u].Ahi = &g_hb[rd][0][l][0][0];
                        cs[u].Alo = &g_hb[rd][1][l][0][0];
                        cs[u].lda = NH;
                        cs[u].Whi = g_wht[0] + (size_t)l * NG * NH;
                        cs[u].Wlo = g_wht[1] + (size_t)l * NG * NH;
                        cs[u].ldw = NH; cs[u].k0 = (u - 8) * 64;
                    }
                }
            }
            gemm_run(s, cs, nc, C0, C1, warp, lane, tid, hc4);

            // epilogue: gates -> smem (+bias)
            {
                const int r0 = warp * 16 + (lane >> 2);
                const int cA = 2 * (lane & 3);
#pragma unroll
                for (int nt = 0; nt < 2; nt++) {
                    float* C = nt ? C1 : C0;
                    int c = nt * 8 + cA;
#pragma unroll
                    for (int v = 0; v < 4; v++) {
                        int rr = r0 + ((v >> 1) ? 8 : 0);
                        int ccol = c + (v & 1);
                        s->gex[ccol >> 2][rr][ccol & 3] = C[v] + s->bias[l][rr][ccol];
                    }
                }
            }
            __syncthreads();

            if (tid < NB) {
                const int b = tid;
#pragma unroll
                for (int j = 0; j < 4; j++) {
                    float ig = s->gex[0][b][j];
                    float fg = s->gex[1][b][j];
                    float gg = s->gex[2][b][j];
                    float og = s->gex[3][b][j];
                    float c_new = sigm(fg) * s->cst[l][b][j] + sigm(ig) * tanhf(gg);
                    float h_new = sigm(og) * tanhf(c_new);
                    s->cst[l][b][j] = c_new;
                    __nv_bfloat16 hi, lo;
                    split_bf16(h_new, hi, lo);
                    g_hb[wr][0][l][b][hc4 + j] = hi;
                    g_hb[wr][1][l][b][hc4 + j] = lo;
                    if (l == 2) g_h2[b][hc4 + j] = h_new;
                    if (t == NT - 1)
                        out_hfin[(size_t)l * NB * NH + (size_t)b * NH + hc4 + j] = h_new;
                }
            }
            grid_barrier2(cta, ++bar_t);
        }

        // ---- output projection (split-K across thread halves) ----
        {
            const float* hrow = &g_h2[orow0 + tr][0] + (grp << 8);
            float accp = grp ? 0.f : bout_r;
            const int kb = grp << 8;
#pragma unroll 8
            for (int k = 0; k < 256; k += 4) {
                float4 hv = __ldcg(reinterpret_cast<const float4*>(hrow + k));
                accp += hv.x * s->woutc[kb + k + 0][tc];
                accp += hv.y * s->woutc[kb + k + 1][tc];
                accp += hv.z * s->woutc[kb + k + 2][tc];
                accp += hv.w * s->woutc[kb + k + 3][tc];
            }
            if (grp == 1) s->opart[q] = accp;
            __syncthreads();
            if (grp == 0) {
                accp += s->opart[q];
                out_seq[(size_t)(orow0 + tr) * NT * NLAT + (size_t)t * NLAT + ocol0 + tc] =
                    sigm(accp);
            }
            __syncthreads();
        }
    }
}

extern "C" void kernel_launch(void* const* d_in, const int* in_sizes, int n_in,
                              void* d_out, int out_size) {
    const float* noise = (const float*)d_in[0];
    const float* h_cpl = (const float*)d_in[1];
    const float* Wx0   = (const float*)d_in[2];
    const float* Wxr   = (const float*)d_in[3];
    const float* Wh    = (const float*)d_in[4];
    const float* Wc    = (const float*)d_in[5];
    const float* bvec  = (const float*)d_in[6];
    const float* Wout  = (const float*)d_in[7];
    const float* bout  = (const float*)d_in[8];
    float* out = (float*)d_out;

    cudaFuncSetAttribute(bilateral_kernel, cudaFuncAttributeMaxDynamicSharedMemorySize,
                         (int)sizeof(Smem));
    bilateral_kernel<<<NCTA, NTHR, sizeof(Smem)>>>(noise, h_cpl, Wx0, Wxr, Wh, Wc,
                                                   bvec, Wout, bout, out);
}

// round 8
// speedup vs baseline: 2.2291x; 1.4623x over previous
#include <cuda_runtime.h>
#include <cuda_bf16.h>
#include <cstdint>

#define NB 128
#define NT 512
#define NDIM 128
#define NH 512
#define NG 2048
#define NLAT 128
#define NL 3
#define NCTA 128
#define NTHR 256
#define NKT 8            // k-tiles
#define NCT 16           // col-tiles
#define KSL 64           // K slice per tile
#define AK 72            // padded bf16 row stride (144B)

struct __align__(1024) Smem {
    __nv_bfloat16 stg[2][4][128][AK];   // [buf][Ahi,Alo,Whi,Wlo][row][k]
    float bias[NL][NB][16];
    float cst[NL][NB][4];
    float gex[4][NB][5];
    float woutc[NH][8];
    float opart[NB];
};

__device__ float g_part[NKT][NG][NB];                  // 8MB k-split partials
__device__ float g_xproj[(size_t)NT * NG * NB];        // 512MB precomputed x@Wx0
__device__ float g_h2[NB][NH];
__device__ __nv_bfloat16 g_hb[2][2][NL][NB][NH];       // [pingpong][hi/lo]
__device__ __nv_bfloat16 g_nb[2][NB * NT * NDIM];
__device__ __nv_bfloat16 g_cb[2][NL * NB * NH];
__device__ __nv_bfloat16 g_wx0t[2][NG * NDIM];
__device__ __nv_bfloat16 g_wxrt[2][(NL - 1) * NG * NH];
__device__ __nv_bfloat16 g_wht[2][NL * NG * NH];
__device__ __nv_bfloat16 g_wct[2][NL * NG * NH];
__device__ unsigned g_flags[NCTA];

__device__ __forceinline__ float sigm(float x) { return 1.f / (1.f + __expf(-x)); }

__device__ __forceinline__ void split_bf16(float v, __nv_bfloat16& hi, __nv_bfloat16& lo) {
    unsigned u = __float_as_uint(v);
    hi = __ushort_as_bfloat16((unsigned short)(u >> 16));
    float hf = __uint_as_float(u & 0xFFFF0000u);
    lo = __float2bfloat16(v - hf);
}

__device__ __forceinline__ uint32_t smem_u32(const void* p) {
    uint32_t a;
    asm("{ .reg .u64 t; cvta.to.shared.u64 t, %1; cvt.u32.u64 %0, t; }" : "=r"(a) : "l"(p));
    return a;
}

__device__ __forceinline__ void cpa16(void* dst, const void* src) {
    unsigned d = (unsigned)__cvta_generic_to_shared(dst);
    asm volatile("cp.async.cg.shared.global [%0], [%1], 16;" :: "r"(d), "l"(src));
}
__device__ __forceinline__ void cpa_commit() {
    asm volatile("cp.async.commit_group;" ::: "memory");
}
template <int N>
__device__ __forceinline__ void cpa_wait() {
    asm volatile("cp.async.wait_group %0;" :: "n"(N) : "memory");
}

__device__ __forceinline__ void ldsm4(unsigned& r0, unsigned& r1, unsigned& r2,
                                      unsigned& r3, unsigned addr) {
    asm volatile("ldmatrix.sync.aligned.m8n8.x4.shared.b16 {%0,%1,%2,%3}, [%4];"
                 : "=r"(r0), "=r"(r1), "=r"(r2), "=r"(r3) : "r"(addr));
}
__device__ __forceinline__ void mma16816(float* c, unsigned a0, unsigned a1, unsigned a2,
                                         unsigned a3, unsigned b0, unsigned b1) {
    asm volatile(
        "mma.sync.aligned.m16n8k16.row.col.f32.bf16.bf16.f32 "
        "{%0,%1,%2,%3}, {%4,%5,%6,%7}, {%8,%9}, {%0,%1,%2,%3};"
        : "+f"(c[0]), "+f"(c[1]), "+f"(c[2]), "+f"(c[3])
        : "r"(a0), "r"(a1), "r"(a2), "r"(a3), "r"(b0), "r"(b1));
}

__device__ __forceinline__ void grid_barrier2(int cta, unsigned target) {
    __syncthreads();
    if (threadIdx.x == 0) {
        __threadfence();
        atomicExch(&g_flags[cta], target);
    }
    for (;;) {
        unsigned v = (threadIdx.x < NCTA) ? __ldcg(&g_flags[threadIdx.x]) : target;
        if (__syncthreads_count((int)(v < target)) == 0) break;
    }
    __threadfence();
}

// Stage one 128x64 bf16 tile into padded smem rows (144B pitch).
__device__ __forceinline__ void stage_tile(__nv_bfloat16* dst, const __nv_bfloat16* src,
                                           int ld) {
    const int tid = threadIdx.x;
#pragma unroll
    for (int it = 0; it < 4; it++) {
        int idx = it * NTHR + tid;       // 0..1023
        int r = idx >> 3, g = idx & 7;
        cpa16(dst + r * AK + g * 8, src + (size_t)r * ld + g * 8);
    }
}

__device__ __forceinline__ void stage_set(Smem* s, int buf,
                                          const __nv_bfloat16* Ahi, const __nv_bfloat16* Alo,
                                          int lda,
                                          const __nv_bfloat16* Whi, const __nv_bfloat16* Wlo,
                                          int ldw) {
    stage_tile(&s->stg[buf][0][0][0], Ahi, lda);
    stage_tile(&s->stg[buf][1][0][0], Alo, lda);
    stage_tile(&s->stg[buf][2][0][0], Whi, ldw);
    stage_tile(&s->stg[buf][3][0][0], Wlo, ldw);
}

// HMMA over one staged buffer: C[16][4] += A[128x64] * W[128x64]^T (3-term bf16 split),
// this warp's 16 rows x 128 cols.
__device__ __forceinline__ void compute_buf(Smem* s, int buf, float (*C)[4],
                                            int warp, int lane) {
    const int ar = warp * 16 + (lane & 15);
    const int ak = (lane >> 4) * 8;
    const unsigned ah_b = smem_u32(&s->stg[buf][0][ar][ak]);
    const unsigned al_b = smem_u32(&s->stg[buf][1][ar][ak]);
    const int bc = (lane & 7) + ((lane >= 16) ? 8 : 0);
    const int bk = ((lane >> 3) & 1) * 8;
    const unsigned bh_b = smem_u32(&s->stg[buf][2][bc][bk]);
    const unsigned bl_b = smem_u32(&s->stg[buf][3][bc][bk]);
#pragma unroll
    for (int ks = 0; ks < 4; ks++) {
        unsigned ah0, ah1, ah2, ah3, al0, al1, al2, al3;
        ldsm4(ah0, ah1, ah2, ah3, ah_b + ks * 32);
        ldsm4(al0, al1, al2, al3, al_b + ks * 32);
#pragma unroll
        for (int nt = 0; nt < 8; nt++) {
            unsigned bh0, bh1, bh2, bh3, bl0, bl1, bl2, bl3;
            const unsigned off = nt * 16 * (AK * 2) + ks * 32;
            ldsm4(bh0, bh1, bh2, bh3, bh_b + off);
            ldsm4(bl0, bl1, bl2, bl3, bl_b + off);
            mma16816(C[2 * nt],     ah0, ah1, ah2, ah3, bh0, bh1);
            mma16816(C[2 * nt + 1], ah0, ah1, ah2, ah3, bh2, bh3);
            mma16816(C[2 * nt],     ah0, ah1, ah2, ah3, bl0, bl1);
            mma16816(C[2 * nt + 1], ah0, ah1, ah2, ah3, bl2, bl3);
            mma16816(C[2 * nt],     al0, al1, al2, al3, bh0, bh1);
            mma16816(C[2 * nt + 1], al0, al1, al2, al3, bh2, bh3);
        }
    }
}

// Write C tile to base[col][NB] (column-major over rows).
__device__ __forceinline__ void epilogue_regs(float* base, float (*C)[4],
                                              int warp, int lane) {
    const int r0 = warp * 16 + (lane >> 2);
    const int c0 = 2 * (lane & 3);
#pragma unroll
    for (int n8 = 0; n8 < 16; n8++) {
        int cb = n8 * 8 + c0;
        base[(size_t)cb * NB + r0] = C[n8][0];
        base[(size_t)(cb + 1) * NB + r0] = C[n8][1];
        base[(size_t)cb * NB + r0 + 8] = C[n8][2];
        base[(size_t)(cb + 1) * NB + r0 + 8] = C[n8][3];
    }
}

__global__ void __launch_bounds__(NTHR, 1)
bilateral_kernel(const float* __restrict__ noise,
                 const float* __restrict__ h_cpl,
                 const float* __restrict__ Wx0,
                 const float* __restrict__ Wxr,
                 const float* __restrict__ Wh,
                 const float* __restrict__ Wc,
                 const float* __restrict__ bvec,
                 const float* __restrict__ Wout,
                 const float* __restrict__ bout,
                 float* __restrict__ out) {
    extern __shared__ char smem_raw[];
    Smem* s = reinterpret_cast<Smem*>(smem_raw);
    const int tid = threadIdx.x;
    const int cta = blockIdx.x;
    const int warp = tid >> 5, lane = tid & 31;
    const int kt = cta >> 4;           // k-tile 0..7
    const int ct = cta & 15;           // col-tile 0..15
    const int gc0 = ct * 128;          // gate-col base (GEMM role)
    const int kb = kt * KSL;           // k base (GEMM role)
    const int hc4 = cta * 4;           // hidden-col base (reduce role)
    const int half = tid >> 7, rr = tid & 127;

    unsigned bar_t = g_flags[cta];

    float* out_seq = out;
    float* out_hfin = out + (size_t)NB * NT * NLAT;

    const int orow0 = (cta >> 4) * 16;
    const int ocol0 = (cta & 15) * 8;
    const int q = tid & 127, grp = tid >> 7;
    const int tr = q >> 3, tc = q & 7;
    const float bout_r = bout[ocol0 + tc];

    // ---- phase 0: conversions + zero init ----
    for (int i = cta * NTHR + tid; i < NB * NT * NDIM; i += NCTA * NTHR)
        split_bf16(noise[i], g_nb[0][i], g_nb[1][i]);
    for (int i = cta * NTHR + tid; i < NL * NB * NH; i += NCTA * NTHR)
        split_bf16(h_cpl[i], g_cb[0][i], g_cb[1][i]);
    {
        __nv_bfloat16* hz = &g_hb[0][0][0][0][0];
        __nv_bfloat16 z = __float2bfloat16(0.f);
        for (int i = cta * NTHR + tid; i < 2 * NL * NB * NH; i += NCTA * NTHR) hz[i] = z;
    }
    for (int i = tid; i < NL * NB * 4; i += NTHR) (&s->cst[0][0][0])[i] = 0.f;
    for (int i = tid; i < NH * 8; i += NTHR) {
        int k = i >> 3, c = i & 7;
        s->woutc[k][c] = Wout[(size_t)k * NLAT + ocol0 + c];
    }

    // ---- phase 0b: weight transpose + bf16 split ----
    {
        float (*tile)[33] = reinterpret_cast<float (*)[33]>(&s->stg[0][0][0][0]);
        const int tx = tid & 31, ty = tid >> 5;
        for (int idx = cta; idx < 8448; idx += NCTA) {
            const float* src;
            __nv_bfloat16 *dh, *dl;
            int R, t;
            if (idx < 256) {
                src = Wx0; dh = g_wx0t[0]; dl = g_wx0t[1]; R = NDIM; t = idx;
            } else {
                int j = (idx - 256) >> 10;
                t = (idx - 256) & 1023;
                R = NH;
                if (j < 2) {
                    src = Wxr + (size_t)j * NH * NG;
                    dh = g_wxrt[0] + (size_t)j * NG * NH;
                    dl = g_wxrt[1] + (size_t)j * NG * NH;
                } else if (j < 5) {
                    src = Wh + (size_t)(j - 2) * NH * NG;
                    dh = g_wht[0] + (size_t)(j - 2) * NG * NH;
                    dl = g_wht[1] + (size_t)(j - 2) * NG * NH;
                } else {
                    src = Wc + (size_t)(j - 5) * NH * NG;
                    dh = g_wct[0] + (size_t)(j - 5) * NG * NH;
                    dl = g_wct[1] + (size_t)(j - 5) * NG * NH;
                }
            }
            const int tr_ = t / (NG / 32), tc_ = t % (NG / 32);
            const int r0 = tr_ * 32, c0 = tc_ * 32;
            __syncthreads();
#pragma unroll
            for (int i = 0; i < 32; i += 8)
                tile[ty + i][tx] = src[(size_t)(r0 + ty + i) * NG + c0 + tx];
            __syncthreads();
#pragma unroll
            for (int i = 0; i < 32; i += 8) {
                float v = tile[tx][ty + i];
                __nv_bfloat16 hi, lo;
                split_bf16(v, hi, lo);
                size_t o = (size_t)(c0 + ty + i) * R + r0 + tx;
                dh[o] = hi;
                dl[o] = lo;
            }
        }
    }
    __syncthreads();
    grid_barrier2(cta, ++bar_t);

    // ---- phase 1: precompute x@Wx0 for all t (512 t x 16 ct work items) ----
    for (int idx = cta; idx < NT * NCT; idx += NCTA) {
        const int t = idx >> 4;
        const int gx = (idx & 15) * 128;
        stage_set(s, 0, g_nb[0] + (size_t)t * NDIM, g_nb[1] + (size_t)t * NDIM,
                  NT * NDIM, g_wx0t[0] + (size_t)gx * NDIM, g_wx0t[1] + (size_t)gx * NDIM,
                  NDIM);
        cpa_commit();
        stage_set(s, 1, g_nb[0] + (size_t)t * NDIM + 64, g_nb[1] + (size_t)t * NDIM + 64,
                  NT * NDIM, g_wx0t[0] + (size_t)gx * NDIM + 64,
                  g_wx0t[1] + (size_t)gx * NDIM + 64, NDIM);
        cpa_commit();
        float C[16][4];
#pragma unroll
        for (int m = 0; m < 16; m++)
#pragma unroll
            for (int v = 0; v < 4; v++) C[m][v] = 0.f;
        cpa_wait<1>();
        __syncthreads();
        compute_buf(s, 0, C, warp, lane);
        cpa_wait<0>();
        __syncthreads();
        compute_buf(s, 1, C, warp, lane);
        epilogue_regs(&g_xproj[((size_t)t * NG + gx) * NB], C, warp, lane);
        __syncthreads();
    }

    // ---- phase 2: bias = h_coupled @ Wc + b (k-split) ----
    for (int l = 0; l < NL; l++) {
        stage_set(s, 0,
                  g_cb[0] + (size_t)l * NB * NH + kb, g_cb[1] + (size_t)l * NB * NH + kb, NH,
                  g_wct[0] + ((size_t)l * NG + gc0) * NH + kb,
                  g_wct[1] + ((size_t)l * NG + gc0) * NH + kb, NH);
        cpa_commit();
        float C[16][4];
#pragma unroll
        for (int m = 0; m < 16; m++)
#pragma unroll
            for (int v = 0; v < 4; v++) C[m][v] = 0.f;
        cpa_wait<0>();
        __syncthreads();
        compute_buf(s, 0, C, warp, lane);
        epilogue_regs(&g_part[kt][gc0][0], C, warp, lane);
        grid_barrier2(cta, ++bar_t);
        // reduce -> bias
#pragma unroll
        for (int gi = 0; gi < 8; gi++) {
            int gl = gi * 2 + half;
            int gcol = (gl >> 2) * 512 + hc4 + (gl & 3);
            float sum = 0.f;
#pragma unroll
            for (int k2 = 0; k2 < NKT; k2++) sum += __ldcg(&g_part[k2][gcol][rr]);
            s->bias[l][rr][gl] = sum + bvec[l * NG + gcol];
        }
        grid_barrier2(cta, ++bar_t);
    }

    // ---- phase 3: main recurrence ----
    for (int t = 0; t < NT; t++) {
        const int rd = t & 1, wr = rd ^ 1;
        for (int l = 0; l < NL; l++) {
            if (l == 0) {
                stage_set(s, 0,
                          &g_hb[rd][0][0][0][kb], &g_hb[rd][1][0][0][kb], NH,
                          g_wht[0] + (size_t)gc0 * NH + kb,
                          g_wht[1] + (size_t)gc0 * NH + kb, NH);
                cpa_commit();
            } else {
                stage_set(s, 0,
                          &g_hb[wr][0][l - 1][0][kb], &g_hb[wr][1][l - 1][0][kb], NH,
                          g_wxrt[0] + ((size_t)(l - 1) * NG + gc0) * NH + kb,
                          g_wxrt[1] + ((size_t)(l - 1) * NG + gc0) * NH + kb, NH);
                cpa_commit();
                stage_set(s, 1,
                          &g_hb[rd][0][l][0][kb], &g_hb[rd][1][l][0][kb], NH,
                          g_wht[0] + ((size_t)l * NG + gc0) * NH + kb,
                          g_wht[1] + ((size_t)l * NG + gc0) * NH + kb, NH);
                cpa_commit();
            }
            float C[16][4];
#pragma unroll
            for (int m = 0; m < 16; m++)
#pragma unroll
                for (int v = 0; v < 4; v++) C[m][v] = 0.f;
            if (l == 0) {
                cpa_wait<0>();
                __syncthreads();
                compute_buf(s, 0, C, warp, lane);
            } else {
                cpa_wait<1>();
                __syncthreads();
                compute_buf(s, 0, C, warp, lane);
                cpa_wait<0>();
                __syncthreads();
                compute_buf(s, 1, C, warp, lane);
            }
            epilogue_regs(&g_part[kt][gc0][0], C, warp, lane);
            grid_barrier2(cta, ++bar_t);

            // reduce over k-tiles (+ xproj for layer 0) -> gates
#pragma unroll
            for (int gi = 0; gi < 8; gi++) {
                int gl = gi * 2 + half;
                int gcol = (gl >> 2) * 512 + hc4 + (gl & 3);
                float sum = 0.f;
#pragma unroll
                for (int k2 = 0; k2 < NKT; k2++) sum += __ldcg(&g_part[k2][gcol][rr]);
                if (l == 0) sum += __ldcg(&g_xproj[((size_t)t * NG + gcol) * NB + rr]);
                s->gex[gl >> 2][rr][gl & 3] = sum;
            }
            __syncthreads();

            if (tid < NB) {
                const int b = tid;
#pragma unroll
                for (int j = 0; j < 4; j++) {
                    float ig = s->gex[0][b][j] + s->bias[l][b][j];
                    float fg = s->gex[1][b][j] + s->bias[l][b][4 + j];
                    float gg = s->gex[2][b][j] + s->bias[l][b][8 + j];
                    float og = s->gex[3][b][j] + s->bias[l][b][12 + j];
                    float c_new = sigm(fg) * s->cst[l][b][j] + sigm(ig) * tanhf(gg);
                    float h_new = sigm(og) * tanhf(c_new);
                    s->cst[l][b][j] = c_new;
                    __nv_bfloat16 hi, lo;
                    split_bf16(h_new, hi, lo);
                    g_hb[wr][0][l][b][hc4 + j] = hi;
                    g_hb[wr][1][l][b][hc4 + j] = lo;
                    if (l == 2) g_h2[b][hc4 + j] = h_new;
                    if (t == NT - 1)
                        out_hfin[(size_t)l * NB * NH + (size_t)b * NH + hc4 + j] = h_new;
                }
            }
            grid_barrier2(cta, ++bar_t);
        }

        // ---- output projection ----
        {
            const float* hrow = &g_h2[orow0 + tr][0] + (grp << 8);
            float accp = grp ? 0.f : bout_r;
            const int kb2 = grp << 8;
#pragma unroll 8
            for (int k = 0; k < 256; k += 4) {
                float4 hv = __ldcg(reinterpret_cast<const float4*>(hrow + k));
                accp += hv.x * s->woutc[kb2 + k + 0][tc];
                accp += hv.y * s->woutc[kb2 + k + 1][tc];
                accp += hv.z * s->woutc[kb2 + k + 2][tc];
                accp += hv.w * s->woutc[kb2 + k + 3][tc];
            }
            if (grp == 1) s->opart[q] = accp;
            __syncthreads();
            if (grp == 0) {
                accp += s->opart[q];
                out_seq[(size_t)(orow0 + tr) * NT * NLAT + (size_t)t * NLAT + ocol0 + tc] =
                    sigm(accp);
            }
            __syncthreads();
        }
    }
}

extern "C" void kernel_launch(void* const* d_in, const int* in_sizes, int n_in,
                              void* d_out, int out_size) {
    const float* noise = (const float*)d_in[0];
    const float* h_cpl = (const float*)d_in[1];
    const float* Wx0   = (const float*)d_in[2];
    const float* Wxr   = (const float*)d_in[3];
    const float* Wh    = (const float*)d_in[4];
    const float* Wc    = (const float*)d_in[5];
    const float* bvec  = (const float*)d_in[6];
    const float* Wout  = (const float*)d_in[7];
    const float* bout  = (const float*)d_in[8];
    float* out = (float*)d_out;

    cudaFuncSetAttribute(bilateral_kernel, cudaFuncAttributeMaxDynamicSharedMemorySize,
                         (int)sizeof(Smem));
    bilateral_kernel<<<NCTA, NTHR, sizeof(Smem)>>>(noise, h_cpl, Wx0, Wxr, Wh, Wc,
                                                   bvec, Wout, bout, out);
}

// round 9
// speedup vs baseline: 2.3424x; 1.0508x over previous
#include <cuda_runtime.h>
#include <cuda_bf16.h>
#include <cstdint>

#define NB 128
#define NT 512
#define NDIM 128
#define NH 512
#define NG 2048
#define NLAT 128
#define NL 3
#define NCTA 128
#define NTHR 256
#define NKT 8            // k-tiles
#define NCT 16           // col-tiles
#define KSL 64           // K slice per tile
#define AK 72            // padded bf16 row stride (144B)

struct __align__(1024) Smem {
    __nv_bfloat16 stg[2][4][128][AK];   // [buf][Ahi,Alo,Whi,Wlo][row][k]
    float bias[NL][NB][16];
    float cst[NL][NB][4];
    float gex[4][NB][5];
    float woutc[NH][8];
    float opart[NB];
};

__device__ float g_part[2][NKT][NG][NB];               // ping-pong k-split partials
__device__ float g_xproj[(size_t)NT * NG * NB];        // precomputed x@Wx0
__device__ float g_h2[NB][NH];
__device__ __nv_bfloat16 g_hb[2][2][NL][NB][NH];       // [pingpong][hi/lo]
__device__ __nv_bfloat16 g_nb[2][NB * NT * NDIM];
__device__ __nv_bfloat16 g_cb[2][NL * NB * NH];
__device__ __nv_bfloat16 g_wx0t[2][NG * NDIM];
__device__ __nv_bfloat16 g_wxrt[2][(NL - 1) * NG * NH];
__device__ __nv_bfloat16 g_wht[2][NL * NG * NH];
__device__ __nv_bfloat16 g_wct[2][NL * NG * NH];
__device__ unsigned g_flags[NCTA];

__device__ __forceinline__ float sigm(float x) { return 1.f / (1.f + __expf(-x)); }

__device__ __forceinline__ void split_bf16(float v, __nv_bfloat16& hi, __nv_bfloat16& lo) {
    unsigned u = __float_as_uint(v);
    hi = __ushort_as_bfloat16((unsigned short)(u >> 16));
    float hf = __uint_as_float(u & 0xFFFF0000u);
    lo = __float2bfloat16(v - hf);
}

__device__ __forceinline__ uint32_t smem_u32(const void* p) {
    uint32_t a;
    asm("{ .reg .u64 t; cvta.to.shared.u64 t, %1; cvt.u32.u64 %0, t; }" : "=r"(a) : "l"(p));
    return a;
}

__device__ __forceinline__ void cpa16(void* dst, const void* src) {
    unsigned d = (unsigned)__cvta_generic_to_shared(dst);
    asm volatile("cp.async.cg.shared.global [%0], [%1], 16;" :: "r"(d), "l"(src));
}
__device__ __forceinline__ void cpa_commit() {
    asm volatile("cp.async.commit_group;" ::: "memory");
}
template <int N>
__device__ __forceinline__ void cpa_wait() {
    asm volatile("cp.async.wait_group %0;" :: "n"(N) : "memory");
}

__device__ __forceinline__ void ldsm4(unsigned& r0, unsigned& r1, unsigned& r2,
                                      unsigned& r3, unsigned addr) {
    asm volatile("ldmatrix.sync.aligned.m8n8.x4.shared.b16 {%0,%1,%2,%3}, [%4];"
                 : "=r"(r0), "=r"(r1), "=r"(r2), "=r"(r3) : "r"(addr));
}
__device__ __forceinline__ void mma16816(float* c, unsigned a0, unsigned a1, unsigned a2,
                                         unsigned a3, unsigned b0, unsigned b1) {
    asm volatile(
        "mma.sync.aligned.m16n8k16.row.col.f32.bf16.bf16.f32 "
        "{%0,%1,%2,%3}, {%4,%5,%6,%7}, {%8,%9}, {%0,%1,%2,%3};"
        : "+f"(c[0]), "+f"(c[1]), "+f"(c[2]), "+f"(c[3])
        : "r"(a0), "r"(a1), "r"(a2), "r"(a3), "r"(b0), "r"(b1));
}

__device__ __forceinline__ void bar_arrive(int cta, unsigned target) {
    __syncthreads();
    if (threadIdx.x == 0) {
        __threadfence();
        atomicExch(&g_flags[cta], target);
    }
}
__device__ __forceinline__ void bar_wait(unsigned target) {
    for (;;) {
        unsigned v = (threadIdx.x < NCTA) ? __ldcg(&g_flags[threadIdx.x]) : target;
        if (__syncthreads_count((int)(v < target)) == 0) break;
    }
    __threadfence();
}
__device__ __forceinline__ void grid_barrier2(int cta, unsigned target) {
    bar_arrive(cta, target);
    bar_wait(target);
}

// Stage one 128x64 bf16 tile into padded smem rows (144B pitch).
__device__ __forceinline__ void stage_tile(__nv_bfloat16* dst, const __nv_bfloat16* src,
                                           int ld) {
    const int tid = threadIdx.x;
#pragma unroll
    for (int it = 0; it < 4; it++) {
        int idx = it * NTHR + tid;       // 0..1023
        int r = idx >> 3, g = idx & 7;
        cpa16(dst + r * AK + g * 8, src + (size_t)r * ld + g * 8);
    }
}

__device__ __forceinline__ void stage_set(Smem* s, int buf,
                                          const __nv_bfloat16* Ahi, const __nv_bfloat16* Alo,
                                          int lda,
                                          const __nv_bfloat16* Whi, const __nv_bfloat16* Wlo,
                                          int ldw) {
    stage_tile(&s->stg[buf][0][0][0], Ahi, lda);
    stage_tile(&s->stg[buf][1][0][0], Alo, lda);
    stage_tile(&s->stg[buf][2][0][0], Whi, ldw);
    stage_tile(&s->stg[buf][3][0][0], Wlo, ldw);
}

// HMMA over one staged buffer (3-term bf16 split), warp's 16 rows x 128 cols.
__device__ __forceinline__ void compute_buf(Smem* s, int buf, float (*C)[4],
                                            int warp, int lane) {
    const int ar = warp * 16 + (lane & 15);
    const int ak = (lane >> 4) * 8;
    const unsigned ah_b = smem_u32(&s->stg[buf][0][ar][ak]);
    const unsigned al_b = smem_u32(&s->stg[buf][1][ar][ak]);
    const int bc = (lane & 7) + ((lane >= 16) ? 8 : 0);
    const int bk = ((lane >> 3) & 1) * 8;
    const unsigned bh_b = smem_u32(&s->stg[buf][2][bc][bk]);
    const unsigned bl_b = smem_u32(&s->stg[buf][3][bc][bk]);
#pragma unroll
    for (int ks = 0; ks < 4; ks++) {
        unsigned ah0, ah1, ah2, ah3, al0, al1, al2, al3;
        ldsm4(ah0, ah1, ah2, ah3, ah_b + ks * 32);
        ldsm4(al0, al1, al2, al3, al_b + ks * 32);
#pragma unroll
        for (int nt = 0; nt < 8; nt++) {
            unsigned bh0, bh1, bh2, bh3, bl0, bl1, bl2, bl3;
            const unsigned off = nt * 16 * (AK * 2) + ks * 32;
            ldsm4(bh0, bh1, bh2, bh3, bh_b + off);
            ldsm4(bl0, bl1, bl2, bl3, bl_b + off);
            mma16816(C[2 * nt],     ah0, ah1, ah2, ah3, bh0, bh1);
            mma16816(C[2 * nt + 1], ah0, ah1, ah2, ah3, bh2, bh3);
            mma16816(C[2 * nt],     ah0, ah1, ah2, ah3, bl0, bl1);
            mma16816(C[2 * nt + 1], ah0, ah1, ah2, ah3, bl2, bl3);
            mma16816(C[2 * nt],     al0, al1, al2, al3, bh0, bh1);
            mma16816(C[2 * nt + 1], al0, al1, al2, al3, bh2, bh3);
        }
    }
}

__device__ __forceinline__ void epilogue_regs(float* base, float (*C)[4],
                                              int warp, int lane) {
    const int r0 = warp * 16 + (lane >> 2);
    const int c0 = 2 * (lane & 3);
#pragma unroll
    for (int n8 = 0; n8 < 16; n8++) {
        int cb = n8 * 8 + c0;
        base[(size_t)cb * NB + r0] = C[n8][0];
        base[(size_t)(cb + 1) * NB + r0] = C[n8][1];
        base[(size_t)cb * NB + r0 + 8] = C[n8][2];
        base[(size_t)(cb + 1) * NB + r0 + 8] = C[n8][3];
    }
}

__global__ void __launch_bounds__(NTHR, 1)
bilateral_kernel(const float* __restrict__ noise,
                 const float* __restrict__ h_cpl,
                 const float* __restrict__ Wx0,
                 const float* __restrict__ Wxr,
                 const float* __restrict__ Wh,
                 const float* __restrict__ Wc,
                 const float* __restrict__ bvec,
                 const float* __restrict__ Wout,
                 const float* __restrict__ bout,
                 float* __restrict__ out) {
    extern __shared__ char smem_raw[];
    Smem* s = reinterpret_cast<Smem*>(smem_raw);
    const int tid = threadIdx.x;
    const int cta = blockIdx.x;
    const int warp = tid >> 5, lane = tid & 31;
    const int kt = cta >> 4;
    const int ct = cta & 15;
    const int gc0 = ct * 128;
    const int kb = kt * KSL;
    const int hc4 = cta * 4;
    const int half = tid >> 7, rr = tid & 127;

    unsigned bar_t = g_flags[cta];

    float* out_seq = out;
    float* out_hfin = out + (size_t)NB * NT * NLAT;

    const int orow0 = (cta >> 4) * 16;
    const int ocol0 = (cta & 15) * 8;
    const int q = tid & 127, grp = tid >> 7;
    const int tr = q >> 3, tc = q & 7;
    const float bout_r = bout[ocol0 + tc];

    // ---- phase 0: conversions + zero init ----
    for (int i = cta * NTHR + tid; i < NB * NT * NDIM; i += NCTA * NTHR)
        split_bf16(noise[i], g_nb[0][i], g_nb[1][i]);
    for (int i = cta * NTHR + tid; i < NL * NB * NH; i += NCTA * NTHR)
        split_bf16(h_cpl[i], g_cb[0][i], g_cb[1][i]);
    {
        __nv_bfloat16* hz = &g_hb[0][0][0][0][0];
        __nv_bfloat16 z = __float2bfloat16(0.f);
        for (int i = cta * NTHR + tid; i < 2 * NL * NB * NH; i += NCTA * NTHR) hz[i] = z;
    }
    for (int i = tid; i < NL * NB * 4; i += NTHR) (&s->cst[0][0][0])[i] = 0.f;
    for (int i = tid; i < NH * 8; i += NTHR) {
        int k = i >> 3, c = i & 7;
        s->woutc[k][c] = Wout[(size_t)k * NLAT + ocol0 + c];
    }

    // ---- phase 0b: weight transpose + bf16 split ----
    {
        float (*tile)[33] = reinterpret_cast<float (*)[33]>(&s->stg[0][0][0][0]);
        const int tx = tid & 31, ty = tid >> 5;
        for (int idx = cta; idx < 8448; idx += NCTA) {
            const float* src;
            __nv_bfloat16 *dh, *dl;
            int R, t;
            if (idx < 256) {
                src = Wx0; dh = g_wx0t[0]; dl = g_wx0t[1]; R = NDIM; t = idx;
            } else {
                int j = (idx - 256) >> 10;
                t = (idx - 256) & 1023;
                R = NH;
                if (j < 2) {
                    src = Wxr + (size_t)j * NH * NG;
                    dh = g_wxrt[0] + (size_t)j * NG * NH;
                    dl = g_wxrt[1] + (size_t)j * NG * NH;
                } else if (j < 5) {
                    src = Wh + (size_t)(j - 2) * NH * NG;
                    dh = g_wht[0] + (size_t)(j - 2) * NG * NH;
                    dl = g_wht[1] + (size_t)(j - 2) * NG * NH;
                } else {
                    src = Wc + (size_t)(j - 5) * NH * NG;
                    dh = g_wct[0] + (size_t)(j - 5) * NG * NH;
                    dl = g_wct[1] + (size_t)(j - 5) * NG * NH;
                }
            }
            const int tr_ = t / (NG / 32), tc_ = t % (NG / 32);
            const int r0 = tr_ * 32, c0 = tc_ * 32;
            __syncthreads();
#pragma unroll
            for (int i = 0; i < 32; i += 8)
                tile[ty + i][tx] = src[(size_t)(r0 + ty + i) * NG + c0 + tx];
            __syncthreads();
#pragma unroll
            for (int i = 0; i < 32; i += 8) {
                float v = tile[tx][ty + i];
                __nv_bfloat16 hi, lo;
                split_bf16(v, hi, lo);
                size_t o = (size_t)(c0 + ty + i) * R + r0 + tx;
                dh[o] = hi;
                dl[o] = lo;
            }
        }
    }
    __syncthreads();
    grid_barrier2(cta, ++bar_t);

    // ---- phase 1: precompute x@Wx0 for all t ----
    for (int idx = cta; idx < NT * NCT; idx += NCTA) {
        const int t = idx >> 4;
        const int gx = (idx & 15) * 128;
        stage_set(s, 0, g_nb[0] + (size_t)t * NDIM, g_nb[1] + (size_t)t * NDIM,
                  NT * NDIM, g_wx0t[0] + (size_t)gx * NDIM, g_wx0t[1] + (size_t)gx * NDIM,
                  NDIM);
        cpa_commit();
        stage_set(s, 1, g_nb[0] + (size_t)t * NDIM + 64, g_nb[1] + (size_t)t * NDIM + 64,
                  NT * NDIM, g_wx0t[0] + (size_t)gx * NDIM + 64,
                  g_wx0t[1] + (size_t)gx * NDIM + 64, NDIM);
        cpa_commit();
        float C[16][4];
#pragma unroll
        for (int m = 0; m < 16; m++)
#pragma unroll
            for (int v = 0; v < 4; v++) C[m][v] = 0.f;
        cpa_wait<1>();
        __syncthreads();
        compute_buf(s, 0, C, warp, lane);
        cpa_wait<0>();
        __syncthreads();
        compute_buf(s, 1, C, warp, lane);
        epilogue_regs(&g_xproj[((size_t)t * NG + gx) * NB], C, warp, lane);
        __syncthreads();
    }

    // ---- phase 2: bias = h_coupled @ Wc + b ----
    for (int l = 0; l < NL; l++) {
        stage_set(s, 0,
                  g_cb[0] + (size_t)l * NB * NH + kb, g_cb[1] + (size_t)l * NB * NH + kb, NH,
                  g_wct[0] + ((size_t)l * NG + gc0) * NH + kb,
                  g_wct[1] + ((size_t)l * NG + gc0) * NH + kb, NH);
        cpa_commit();
        float C[16][4];
#pragma unroll
        for (int m = 0; m < 16; m++)
#pragma unroll
            for (int v = 0; v < 4; v++) C[m][v] = 0.f;
        cpa_wait<0>();
        __syncthreads();
        compute_buf(s, 0, C, warp, lane);
        epilogue_regs(&g_part[0][kt][gc0][0], C, warp, lane);
        grid_barrier2(cta, ++bar_t);
#pragma unroll
        for (int gi = 0; gi < 8; gi++) {
            int gl = gi * 2 + half;
            int gcol = (gl >> 2) * 512 + hc4 + (gl & 3);
            float sum = 0.f;
#pragma unroll
            for (int k2 = 0; k2 < NKT; k2++) sum += __ldcg(&g_part[0][k2][gcol][rr]);
            s->bias[l][rr][gl] = sum + bvec[l * NG + gcol];
        }
        grid_barrier2(cta, ++bar_t);
    }

    // ---- pre-loop: prefetch L0 (t=0) stale buffer ----
    stage_set(s, 1, &g_hb[0][0][0][0][kb], &g_hb[0][1][0][0][kb], NH,
              g_wht[0] + (size_t)gc0 * NH + kb, g_wht[1] + (size_t)gc0 * NH + kb, NH);
    cpa_commit();

    int pp = 0;  // partial-buffer ping-pong (same sequence on all CTAs)

    // ---- phase 3: main recurrence ----
    for (int t = 0; t < NT; t++) {
        const int rd = t & 1, wr = rd ^ 1;

        // ======== Layer 0 (all operands prefetched) ========
        {
            float C[16][4];
#pragma unroll
            for (int m = 0; m < 16; m++)
#pragma unroll
                for (int v = 0; v < 4; v++) C[m][v] = 0.f;
            cpa_wait<0>();
            __syncthreads();
            compute_buf(s, 1, C, warp, lane);
            epilogue_regs(&g_part[pp][kt][gc0][0], C, warp, lane);
            __syncthreads();
            // prefetch L1 stale: A=h[rd][1], W=Wht[1]
            stage_set(s, 1, &g_hb[rd][0][1][0][kb], &g_hb[rd][1][1][0][kb], NH,
                      g_wht[0] + ((size_t)1 * NG + gc0) * NH + kb,
                      g_wht[1] + ((size_t)1 * NG + gc0) * NH + kb, NH);
            cpa_commit();
            bar_arrive(cta, ++bar_t);
            bar_wait(bar_t);
            // projection for previous step (g_h2 complete as of this barrier)
            if (t > 0) {
                const float* hrow = &g_h2[orow0 + tr][0] + (grp << 8);
                float accp = grp ? 0.f : bout_r;
                const int kb2 = grp << 8;
#pragma unroll 8
                for (int k = 0; k < 256; k += 4) {
                    float4 hv = __ldcg(reinterpret_cast<const float4*>(hrow + k));
                    accp += hv.x * s->woutc[kb2 + k + 0][tc];
                    accp += hv.y * s->woutc[kb2 + k + 1][tc];
                    accp += hv.z * s->woutc[kb2 + k + 2][tc];
                    accp += hv.w * s->woutc[kb2 + k + 3][tc];
                }
                if (grp == 1) s->opart[q] = accp;
                __syncthreads();
                if (grp == 0) {
                    accp += s->opart[q];
                    out_seq[(size_t)(orow0 + tr) * NT * NLAT + (size_t)(t - 1) * NLAT +
                            ocol0 + tc] = sigm(accp);
                }
            }
            // reduce (+xproj) + cell for layer 0
#pragma unroll
            for (int gi = 0; gi < 8; gi++) {
                int gl = gi * 2 + half;
                int gcol = (gl >> 2) * 512 + hc4 + (gl & 3);
                float sum = __ldcg(&g_xproj[((size_t)t * NG + gcol) * NB + rr]);
#pragma unroll
                for (int k2 = 0; k2 < NKT; k2++) sum += __ldcg(&g_part[pp][k2][gcol][rr]);
                s->gex[gl >> 2][rr][gl & 3] = sum;
            }
            pp ^= 1;
            __syncthreads();
            if (tid < NB) {
                const int b = tid;
#pragma unroll
                for (int j = 0; j < 4; j++) {
                    float ig = s->gex[0][b][j] + s->bias[0][b][j];
                    float fg = s->gex[1][b][j] + s->bias[0][b][4 + j];
                    float gg = s->gex[2][b][j] + s->bias[0][b][8 + j];
                    float og = s->gex[3][b][j] + s->bias[0][b][12 + j];
                    float c_new = sigm(fg) * s->cst[0][b][j] + sigm(ig) * tanhf(gg);
                    float h_new = sigm(og) * tanhf(c_new);
                    s->cst[0][b][j] = c_new;
                    __nv_bfloat16 hi, lo;
                    split_bf16(h_new, hi, lo);
                    g_hb[wr][0][0][b][hc4 + j] = hi;
                    g_hb[wr][1][0][b][hc4 + j] = lo;
                    if (t == NT - 1)
                        out_hfin[(size_t)b * NH + hc4 + j] = h_new;
                }
            }
            grid_barrier2(cta, ++bar_t);   // barrier B L0
        }

        // ======== Layers 1, 2 ========
#pragma unroll
        for (int l = 1; l < NL; l++) {
            // fresh: A=h[wr][l-1], W=Wxrt[l-1]
            stage_set(s, 0, &g_hb[wr][0][l - 1][0][kb], &g_hb[wr][1][l - 1][0][kb], NH,
                      g_wxrt[0] + ((size_t)(l - 1) * NG + gc0) * NH + kb,
                      g_wxrt[1] + ((size_t)(l - 1) * NG + gc0) * NH + kb, NH);
            cpa_commit();
            float C[16][4];
#pragma unroll
            for (int m = 0; m < 16; m++)
#pragma unroll
                for (int v = 0; v < 4; v++) C[m][v] = 0.f;
            cpa_wait<0>();
            __syncthreads();
            compute_buf(s, 0, C, warp, lane);
            compute_buf(s, 1, C, warp, lane);
            epilogue_regs(&g_part[pp][kt][gc0][0], C, warp, lane);
            __syncthreads();
            // prefetch next stale buffer:
            if (l == 1) {
                // L2 stale: A=h[rd][2], W=Wht[2]
                stage_set(s, 1, &g_hb[rd][0][2][0][kb], &g_hb[rd][1][2][0][kb], NH,
                          g_wht[0] + ((size_t)2 * NG + gc0) * NH + kb,
                          g_wht[1] + ((size_t)2 * NG + gc0) * NH + kb, NH);
            } else {
                // L0 next step stale: A=h[wr][0] (written this step), W=Wht[0]
                stage_set(s, 1, &g_hb[wr][0][0][0][kb], &g_hb[wr][1][0][0][kb], NH,
                          g_wht[0] + (size_t)gc0 * NH + kb,
                          g_wht[1] + (size_t)gc0 * NH + kb, NH);
            }
            cpa_commit();
            grid_barrier2(cta, ++bar_t);   // barrier A
            // reduce + cell
#pragma unroll
            for (int gi = 0; gi < 8; gi++) {
                int gl = gi * 2 + half;
                int gcol = (gl >> 2) * 512 + hc4 + (gl & 3);
                float sum = 0.f;
#pragma unroll
                for (int k2 = 0; k2 < NKT; k2++) sum += __ldcg(&g_part[pp][k2][gcol][rr]);
                s->gex[gl >> 2][rr][gl & 3] = sum;
            }
            pp ^= 1;
            __syncthreads();
            if (tid < NB) {
                const int b = tid;
#pragma unroll
                for (int j = 0; j < 4; j++) {
                    float ig = s->gex[0][b][j] + s->bias[l][b][j];
                    float fg = s->gex[1][b][j] + s->bias[l][b][4 + j];
                    float gg = s->gex[2][b][j] + s->bias[l][b][8 + j];
                    float og = s->gex[3][b][j] + s->bias[l][b][12 + j];
                    float c_new = sigm(fg) * s->cst[l][b][j] + sigm(ig) * tanhf(gg);
                    float h_new = sigm(og) * tanhf(c_new);
                    s->cst[l][b][j] = c_new;
                    __nv_bfloat16 hi, lo;
                    split_bf16(h_new, hi, lo);
                    g_hb[wr][0][l][b][hc4 + j] = hi;
                    g_hb[wr][1][l][b][hc4 + j] = lo;
                    if (l == 2) g_h2[b][hc4 + j] = h_new;
                    if (t == NT - 1)
                        out_hfin[(size_t)l * NB * NH + (size_t)b * NH + hc4 + j] = h_new;
                }
            }
            if (l == 1) grid_barrier2(cta, ++bar_t);   // barrier B (L1 only)
            // L2's barrier B is merged into next step's L0 barrier A.
        }
    }

    // ---- final projection (t = NT-1) ----
    grid_barrier2(cta, ++bar_t);
    {
        const float* hrow = &g_h2[orow0 + tr][0] + (grp << 8);
        float accp = grp ? 0.f : bout_r;
        const int kb2 = grp << 8;
#pragma unroll 8
        for (int k = 0; k < 256; k += 4) {
            float4 hv = __ldcg(reinterpret_cast<const float4*>(hrow + k));
            accp += hv.x * s->woutc[kb2 + k + 0][tc];
            accp += hv.y * s->woutc[kb2 + k + 1][tc];
            accp += hv.z * s->woutc[kb2 + k + 2][tc];
            accp += hv.w * s->woutc[kb2 + k + 3][tc];
        }
        if (grp == 1) s->opart[q] = accp;
        __syncthreads();
        if (grp == 0) {
            accp += s->opart[q];
            out_seq[(size_t)(orow0 + tr) * NT * NLAT + (size_t)(NT - 1) * NLAT +
                    ocol0 + tc] = sigm(accp);
        }
    }
}

extern "C" void kernel_launch(void* const* d_in, const int* in_sizes, int n_in,
                              void* d_out, int out_size) {
    const float* noise = (const float*)d_in[0];
    const float* h_cpl = (const float*)d_in[1];
    const float* Wx0   = (const float*)d_in[2];
    const float* Wxr   = (const float*)d_in[3];
    const float* Wh    = (const float*)d_in[4];
    const float* Wc    = (const float*)d_in[5];
    const float* bvec  = (const float*)d_in[6];
    const float* Wout  = (const float*)d_in[7];
    const float* bout  = (const float*)d_in[8];
    float* out = (float*)d_out;

    cudaFuncSetAttribute(bilateral_kernel, cudaFuncAttributeMaxDynamicSharedMemorySize,
                         (int)sizeof(Smem));
    bilateral_kernel<<<NCTA, NTHR, sizeof(Smem)>>>(noise, h_cpl, Wx0, Wxr, Wh, Wc,
                                                   bvec, Wout, bout, out);
}

// round 10
// speedup vs baseline: 2.3947x; 1.0224x over previous
#include <cuda_runtime.h>
#include <cuda_bf16.h>
#include <cstdint>

#define NB 128
#define NT 512
#define NDIM 128
#define NH 512
#define NG 2048
#define NLAT 128
#define NL 3
#define NCTA 128
#define NTHR 256
#define NKT 8            // k-tiles
#define NCT 16           // col-tiles
#define KSL 64           // K slice per tile
#define AK 72            // padded bf16 row stride (144B)

struct __align__(1024) Smem {
    __nv_bfloat16 afresh[2][128][AK];   // fresh A (hi/lo)
    __nv_bfloat16 astale[4][128][AK];   // stale GEMM: Ahi,Alo,Whi,Wlo
    __nv_bfloat16 wfresh[2][128][AK];   // fresh GEMM weights (Wxr hi/lo)
    float bias[NL][NB][16];
    float cst[NL][NB][4];
    float gex[4][NB][5];
    float woutc[NH][8];
    float opart[NB];
};

__device__ float g_part[2][NKT][NG][NB];               // ping-pong k-split partials
__device__ float g_xproj[(size_t)NT * NG * NB];        // precomputed x@Wx0
__device__ float g_h2[NB][NH];
__device__ __nv_bfloat16 g_hb[2][2][NL][NB][NH];       // [pingpong][hi/lo]
__device__ __nv_bfloat16 g_nb[2][NB * NT * NDIM];
__device__ __nv_bfloat16 g_cb[2][NL * NB * NH];
__device__ __nv_bfloat16 g_wx0t[2][NG * NDIM];
__device__ __nv_bfloat16 g_wxrt[2][(NL - 1) * NG * NH];
__device__ __nv_bfloat16 g_wht[2][NL * NG * NH];
__device__ __nv_bfloat16 g_wct[2][NL * NG * NH];
__device__ unsigned g_flags[NCTA][32];                 // 128B-padded barrier flags

__device__ __forceinline__ float sigm(float x) { return 1.f / (1.f + __expf(-x)); }

__device__ __forceinline__ void split_bf16(float v, __nv_bfloat16& hi, __nv_bfloat16& lo) {
    unsigned u = __float_as_uint(v);
    hi = __ushort_as_bfloat16((unsigned short)(u >> 16));
    float hf = __uint_as_float(u & 0xFFFF0000u);
    lo = __float2bfloat16(v - hf);
}

__device__ __forceinline__ uint32_t smem_u32(const void* p) {
    uint32_t a;
    asm("{ .reg .u64 t; cvta.to.shared.u64 t, %1; cvt.u32.u64 %0, t; }" : "=r"(a) : "l"(p));
    return a;
}

__device__ __forceinline__ void cpa16(void* dst, const void* src) {
    unsigned d = (unsigned)__cvta_generic_to_shared(dst);
    asm volatile("cp.async.cg.shared.global [%0], [%1], 16;" :: "r"(d), "l"(src));
}
__device__ __forceinline__ void cpa_commit() {
    asm volatile("cp.async.commit_group;" ::: "memory");
}
template <int N>
__device__ __forceinline__ void cpa_wait() {
    asm volatile("cp.async.wait_group %0;" :: "n"(N) : "memory");
}

__device__ __forceinline__ void ldsm4(unsigned& r0, unsigned& r1, unsigned& r2,
                                      unsigned& r3, unsigned addr) {
    asm volatile("ldmatrix.sync.aligned.m8n8.x4.shared.b16 {%0,%1,%2,%3}, [%4];"
                 : "=r"(r0), "=r"(r1), "=r"(r2), "=r"(r3) : "r"(addr));
}
__device__ __forceinline__ void mma16816(float* c, unsigned a0, unsigned a1, unsigned a2,
                                         unsigned a3, unsigned b0, unsigned b1) {
    asm volatile(
        "mma.sync.aligned.m16n8k16.row.col.f32.bf16.bf16.f32 "
        "{%0,%1,%2,%3}, {%4,%5,%6,%7}, {%8,%9}, {%0,%1,%2,%3};"
        : "+f"(c[0]), "+f"(c[1]), "+f"(c[2]), "+f"(c[3])
        : "r"(a0), "r"(a1), "r"(a2), "r"(a3), "r"(b0), "r"(b1));
}

__device__ __forceinline__ void bar_arrive(int cta, unsigned target) {
    __syncthreads();
    if (threadIdx.x == 0) {
        __threadfence();
        atomicExch(&g_flags[cta][0], target);
    }
}
__device__ __forceinline__ void bar_wait(unsigned target) {
    for (;;) {
        unsigned v = (threadIdx.x < NCTA) ? __ldcg(&g_flags[threadIdx.x][0]) : target;
        if (__syncthreads_count((int)(v < target)) == 0) break;
    }
    __threadfence();
}
__device__ __forceinline__ void grid_barrier2(int cta, unsigned target) {
    bar_arrive(cta, target);
    bar_wait(target);
}

// Stage one 128x64 bf16 tile into padded smem rows (144B pitch).
__device__ __forceinline__ void stage_tile(__nv_bfloat16* dst, const __nv_bfloat16* src,
                                           int ld) {
    const int tid = threadIdx.x;
#pragma unroll
    for (int it = 0; it < 4; it++) {
        int idx = it * NTHR + tid;       // 0..1023
        int r = idx >> 3, g = idx & 7;
        cpa16(dst + r * AK + g * 8, src + (size_t)r * ld + g * 8);
    }
}

// HMMA: C += A * W^T (3-term bf16 split). A tiles at At[0..1], W tiles at Wt[0..1].
__device__ __forceinline__ void compute_ab(const __nv_bfloat16 (*At)[128][AK],
                                           const __nv_bfloat16 (*Wt)[128][AK],
                                           float (*C)[4], int warp, int lane) {
    const int ar = warp * 16 + (lane & 15);
    const int ak = (lane >> 4) * 8;
    const unsigned ah_b = smem_u32(&At[0][ar][ak]);
    const unsigned al_b = smem_u32(&At[1][ar][ak]);
    const int bc = (lane & 7) + ((lane >= 16) ? 8 : 0);
    const int bk = ((lane >> 3) & 1) * 8;
    const unsigned bh_b = smem_u32(&Wt[0][bc][bk]);
    const unsigned bl_b = smem_u32(&Wt[1][bc][bk]);
#pragma unroll
    for (int ks = 0; ks < 4; ks++) {
        unsigned ah0, ah1, ah2, ah3, al0, al1, al2, al3;
        ldsm4(ah0, ah1, ah2, ah3, ah_b + ks * 32);
        ldsm4(al0, al1, al2, al3, al_b + ks * 32);
#pragma unroll
        for (int nt = 0; nt < 8; nt++) {
            unsigned bh0, bh1, bh2, bh3, bl0, bl1, bl2, bl3;
            const unsigned off = nt * 16 * (AK * 2) + ks * 32;
            ldsm4(bh0, bh1, bh2, bh3, bh_b + off);
            ldsm4(bl0, bl1, bl2, bl3, bl_b + off);
            mma16816(C[2 * nt],     ah0, ah1, ah2, ah3, bh0, bh1);
            mma16816(C[2 * nt + 1], ah0, ah1, ah2, ah3, bh2, bh3);
            mma16816(C[2 * nt],     ah0, ah1, ah2, ah3, bl0, bl1);
            mma16816(C[2 * nt + 1], ah0, ah1, ah2, ah3, bl2, bl3);
            mma16816(C[2 * nt],     al0, al1, al2, al3, bh0, bh1);
            mma16816(C[2 * nt + 1], al0, al1, al2, al3, bh2, bh3);
        }
    }
}

__device__ __forceinline__ void epilogue_regs(float* base, float (*C)[4],
                                              int warp, int lane) {
    const int r0 = warp * 16 + (lane >> 2);
    const int c0 = 2 * (lane & 3);
#pragma unroll
    for (int n8 = 0; n8 < 16; n8++) {
        int cb = n8 * 8 + c0;
        base[(size_t)cb * NB + r0] = C[n8][0];
        base[(size_t)(cb + 1) * NB + r0] = C[n8][1];
        base[(size_t)cb * NB + r0 + 8] = C[n8][2];
        base[(size_t)(cb + 1) * NB + r0 + 8] = C[n8][3];
    }
}

__global__ void __launch_bounds__(NTHR, 1)
bilateral_kernel(const float* __restrict__ noise,
                 const float* __restrict__ h_cpl,
                 const float* __restrict__ Wx0,
                 const float* __restrict__ Wxr,
                 const float* __restrict__ Wh,
                 const float* __restrict__ Wc,
                 const float* __restrict__ bvec,
                 const float* __restrict__ Wout,
                 const float* __restrict__ bout,
                 float* __restrict__ out) {
    extern __shared__ char smem_raw[];
    Smem* s = reinterpret_cast<Smem*>(smem_raw);
    const int tid = threadIdx.x;
    const int cta = blockIdx.x;
    const int warp = tid >> 5, lane = tid & 31;
    const int kt = cta >> 4;
    const int ct = cta & 15;
    const int gc0 = ct * 128;
    const int kb = kt * KSL;
    const int hc4 = cta * 4;
    const int half = tid >> 7, rr = tid & 127;

    unsigned bar_t = g_flags[cta][0];

    float* out_seq = out;
    float* out_hfin = out + (size_t)NB * NT * NLAT;

    const int orow0 = (cta >> 4) * 16;
    const int ocol0 = (cta & 15) * 8;
    const int q = tid & 127, grp = tid >> 7;
    const int tr = q >> 3, tc = q & 7;
    const float bout_r = bout[ocol0 + tc];

    // reduce column indices (constant per thread)
    int gcolv[8];
#pragma unroll
    for (int gi = 0; gi < 8; gi++) {
        int gl = gi * 2 + half;
        gcolv[gi] = (gl >> 2) * 512 + hc4 + (gl & 3);
    }

    // ---- phase 0: conversions + zero init ----
    for (int i = cta * NTHR + tid; i < NB * NT * NDIM; i += NCTA * NTHR)
        split_bf16(noise[i], g_nb[0][i], g_nb[1][i]);
    for (int i = cta * NTHR + tid; i < NL * NB * NH; i += NCTA * NTHR)
        split_bf16(h_cpl[i], g_cb[0][i], g_cb[1][i]);
    {
        __nv_bfloat16* hz = &g_hb[0][0][0][0][0];
        __nv_bfloat16 z = __float2bfloat16(0.f);
        for (int i = cta * NTHR + tid; i < 2 * NL * NB * NH; i += NCTA * NTHR) hz[i] = z;
    }
    for (int i = tid; i < NL * NB * 4; i += NTHR) (&s->cst[0][0][0])[i] = 0.f;
    for (int i = tid; i < NH * 8; i += NTHR) {
        int k = i >> 3, c = i & 7;
        s->woutc[k][c] = Wout[(size_t)k * NLAT + ocol0 + c];
    }

    // ---- phase 0b: weight transpose + bf16 split ----
    {
        float (*tile)[33] = reinterpret_cast<float (*)[33]>(&s->afresh[0][0][0]);
        const int tx = tid & 31, ty = tid >> 5;
        for (int idx = cta; idx < 8448; idx += NCTA) {
            const float* src;
            __nv_bfloat16 *dh, *dl;
            int R, t;
            if (idx < 256) {
                src = Wx0; dh = g_wx0t[0]; dl = g_wx0t[1]; R = NDIM; t = idx;
            } else {
                int j = (idx - 256) >> 10;
                t = (idx - 256) & 1023;
                R = NH;
                if (j < 2) {
                    src = Wxr + (size_t)j * NH * NG;
                    dh = g_wxrt[0] + (size_t)j * NG * NH;
                    dl = g_wxrt[1] + (size_t)j * NG * NH;
                } else if (j < 5) {
                    src = Wh + (size_t)(j - 2) * NH * NG;
                    dh = g_wht[0] + (size_t)(j - 2) * NG * NH;
                    dl = g_wht[1] + (size_t)(j - 2) * NG * NH;
                } else {
                    src = Wc + (size_t)(j - 5) * NH * NG;
                    dh = g_wct[0] + (size_t)(j - 5) * NG * NH;
                    dl = g_wct[1] + (size_t)(j - 5) * NG * NH;
                }
            }
            const int tr_ = t / (NG / 32), tc_ = t % (NG / 32);
            const int r0 = tr_ * 32, c0 = tc_ * 32;
            __syncthreads();
#pragma unroll
            for (int i = 0; i < 32; i += 8)
                tile[ty + i][tx] = src[(size_t)(r0 + ty + i) * NG + c0 + tx];
            __syncthreads();
#pragma unroll
            for (int i = 0; i < 32; i += 8) {
                float v = tile[tx][ty + i];
                __nv_bfloat16 hi, lo;
                split_bf16(v, hi, lo);
                size_t o = (size_t)(c0 + ty + i) * R + r0 + tx;
                dh[o] = hi;
                dl[o] = lo;
            }
        }
    }
    __syncthreads();
    grid_barrier2(cta, ++bar_t);

    // ---- phase 1: precompute x@Wx0 for all t ----
    for (int idx = cta; idx < NT * NCT; idx += NCTA) {
        const int t = idx >> 4;
        const int gx = (idx & 15) * 128;
        // chunk 0 -> astale (A + W), chunk 1 -> afresh (A) + wfresh (W)
        stage_tile(&s->astale[0][0][0], g_nb[0] + (size_t)t * NDIM, NT * NDIM);
        stage_tile(&s->astale[1][0][0], g_nb[1] + (size_t)t * NDIM, NT * NDIM);
        stage_tile(&s->astale[2][0][0], g_wx0t[0] + (size_t)gx * NDIM, NDIM);
        stage_tile(&s->astale[3][0][0], g_wx0t[1] + (size_t)gx * NDIM, NDIM);
        stage_tile(&s->afresh[0][0][0], g_nb[0] + (size_t)t * NDIM + 64, NT * NDIM);
        stage_tile(&s->afresh[1][0][0], g_nb[1] + (size_t)t * NDIM + 64, NT * NDIM);
        stage_tile(&s->wfresh[0][0][0], g_wx0t[0] + (size_t)gx * NDIM + 64, NDIM);
        stage_tile(&s->wfresh[1][0][0], g_wx0t[1] + (size_t)gx * NDIM + 64, NDIM);
        cpa_commit();
        float C[16][4];
#pragma unroll
        for (int m = 0; m < 16; m++)
#pragma unroll
            for (int v = 0; v < 4; v++) C[m][v] = 0.f;
        cpa_wait<0>();
        __syncthreads();
        compute_ab(&s->astale[0], &s->astale[2], C, warp, lane);
        compute_ab(&s->afresh[0], &s->wfresh[0], C, warp, lane);
        epilogue_regs(&g_xproj[((size_t)t * NG + gx) * NB], C, warp, lane);
        __syncthreads();
    }

    // ---- phase 2: bias = h_coupled @ Wc + b ----
    for (int l = 0; l < NL; l++) {
        stage_tile(&s->astale[0][0][0], g_cb[0] + (size_t)l * NB * NH + kb, NH);
        stage_tile(&s->astale[1][0][0], g_cb[1] + (size_t)l * NB * NH + kb, NH);
        stage_tile(&s->astale[2][0][0], g_wct[0] + ((size_t)l * NG + gc0) * NH + kb, NH);
        stage_tile(&s->astale[3][0][0], g_wct[1] + ((size_t)l * NG + gc0) * NH + kb, NH);
        cpa_commit();
        float C[16][4];
#pragma unroll
        for (int m = 0; m < 16; m++)
#pragma unroll
            for (int v = 0; v < 4; v++) C[m][v] = 0.f;
        cpa_wait<0>();
        __syncthreads();
        compute_ab(&s->astale[0], &s->astale[2], C, warp, lane);
        epilogue_regs(&g_part[0][kt][gc0][0], C, warp, lane);
        grid_barrier2(cta, ++bar_t);
#pragma unroll
        for (int gi = 0; gi < 8; gi++) {
            int gl = gi * 2 + half;
            float sum = 0.f;
#pragma unroll
            for (int k2 = 0; k2 < NKT; k2++) sum += __ldcg(&g_part[0][k2][gcolv[gi]][rr]);
            s->bias[l][rr][gl] = sum + bvec[l * NG + gcolv[gi]];
        }
        grid_barrier2(cta, ++bar_t);
    }

    // ---- pre-loop combined prefetch: L0 stale (h[0][0] + Wht[0]) + L1 wfresh (Wxr[0]) ----
    stage_tile(&s->astale[0][0][0], &g_hb[0][0][0][0][kb], NH);
    stage_tile(&s->astale[1][0][0], &g_hb[0][1][0][0][kb], NH);
    stage_tile(&s->astale[2][0][0], g_wht[0] + (size_t)gc0 * NH + kb, NH);
    stage_tile(&s->astale[3][0][0], g_wht[1] + (size_t)gc0 * NH + kb, NH);
    stage_tile(&s->wfresh[0][0][0], g_wxrt[0] + (size_t)gc0 * NH + kb, NH);
    stage_tile(&s->wfresh[1][0][0], g_wxrt[1] + (size_t)gc0 * NH + kb, NH);
    cpa_commit();

    int pp = 0;

    // ---- phase 3: main recurrence ----
    for (int t = 0; t < NT; t++) {
        const int rd = t & 1, wr = rd ^ 1;

        // ======== Layer 0 ========
        {
            float C[16][4];
#pragma unroll
            for (int m = 0; m < 16; m++)
#pragma unroll
                for (int v = 0; v < 4; v++) C[m][v] = 0.f;
            cpa_wait<0>();
            __syncthreads();
            compute_ab(&s->astale[0], &s->astale[2], C, warp, lane);
            epilogue_regs(&g_part[pp][kt][gc0][0], C, warp, lane);
            __syncthreads();
            // prefetch L1 stale: A=h[rd][1], W=Wht[1]
            stage_tile(&s->astale[0][0][0], &g_hb[rd][0][1][0][kb], NH);
            stage_tile(&s->astale[1][0][0], &g_hb[rd][1][1][0][kb], NH);
            stage_tile(&s->astale[2][0][0], g_wht[0] + ((size_t)1 * NG + gc0) * NH + kb, NH);
            stage_tile(&s->astale[3][0][0], g_wht[1] + ((size_t)1 * NG + gc0) * NH + kb, NH);
            cpa_commit();
            grid_barrier2(cta, ++bar_t);   // barrier A (L0)
            // projection for previous step (MLP-friendly: 4 accumulators, full unroll)
            if (t > 0) {
                const float* hrow = &g_h2[orow0 + tr][0] + (grp << 8);
                const int kb2 = grp << 8;
                float a0 = 0.f, a1 = 0.f, a2 = 0.f, a3 = 0.f;
#pragma unroll
                for (int k = 0; k < 256; k += 16) {
                    float4 v0 = __ldcg(reinterpret_cast<const float4*>(hrow + k));
                    float4 v1 = __ldcg(reinterpret_cast<const float4*>(hrow + k + 4));
                    float4 v2 = __ldcg(reinterpret_cast<const float4*>(hrow + k + 8));
                    float4 v3 = __ldcg(reinterpret_cast<const float4*>(hrow + k + 12));
                    a0 += v0.x * s->woutc[kb2 + k + 0][tc] + v0.y * s->woutc[kb2 + k + 1][tc]
                        + v0.z * s->woutc[kb2 + k + 2][tc] + v0.w * s->woutc[kb2 + k + 3][tc];
                    a1 += v1.x * s->woutc[kb2 + k + 4][tc] + v1.y * s->woutc[kb2 + k + 5][tc]
                        + v1.z * s->woutc[kb2 + k + 6][tc] + v1.w * s->woutc[kb2 + k + 7][tc];
                    a2 += v2.x * s->woutc[kb2 + k + 8][tc] + v2.y * s->woutc[kb2 + k + 9][tc]
                        + v2.z * s->woutc[kb2 + k + 10][tc] + v2.w * s->woutc[kb2 + k + 11][tc];
                    a3 += v3.x * s->woutc[kb2 + k + 12][tc] + v3.y * s->woutc[kb2 + k + 13][tc]
                        + v3.z * s->woutc[kb2 + k + 14][tc] + v3.w * s->woutc[kb2 + k + 15][tc];
                }
                float accp = (grp ? 0.f : bout_r) + ((a0 + a1) + (a2 + a3));
                if (grp == 1) s->opart[q] = accp;
                __syncthreads();
                if (grp == 0) {
                    accp += s->opart[q];
                    out_seq[(size_t)(orow0 + tr) * NT * NLAT + (size_t)(t - 1) * NLAT +
                            ocol0 + tc] = sigm(accp);
                }
            }
            // reduce (fully unrolled: 64 loads in flight) + xproj
            float sum[8];
#pragma unroll
            for (int gi = 0; gi < 8; gi++)
                sum[gi] = __ldcg(&g_xproj[((size_t)t * NG + gcolv[gi]) * NB + rr]);
#pragma unroll
            for (int k2 = 0; k2 < NKT; k2++)
#pragma unroll
                for (int gi = 0; gi < 8; gi++)
                    sum[gi] += __ldcg(&g_part[pp][k2][gcolv[gi]][rr]);
#pragma unroll
            for (int gi = 0; gi < 8; gi++) {
                int gl = gi * 2 + half;
                s->gex[gl >> 2][rr][gl & 3] = sum[gi];
            }
            pp ^= 1;
            __syncthreads();
            if (tid < NB) {
                const int b = tid;
#pragma unroll
                for (int j = 0; j < 4; j++) {
                    float ig = s->gex[0][b][j] + s->bias[0][b][j];
                    float fg = s->gex[1][b][j] + s->bias[0][b][4 + j];
                    float gg = s->gex[2][b][j] + s->bias[0][b][8 + j];
                    float og = s->gex[3][b][j] + s->bias[0][b][12 + j];
                    float c_new = sigm(fg) * s->cst[0][b][j] + sigm(ig) * tanhf(gg);
                    float h_new = sigm(og) * tanhf(c_new);
                    s->cst[0][b][j] = c_new;
                    __nv_bfloat16 hi, lo;
                    split_bf16(h_new, hi, lo);
                    g_hb[wr][0][0][b][hc4 + j] = hi;
                    g_hb[wr][1][0][b][hc4 + j] = lo;
                    if (t == NT - 1)
                        out_hfin[(size_t)b * NH + hc4 + j] = h_new;
                }
            }
            grid_barrier2(cta, ++bar_t);   // barrier B (L0)
        }

        // ======== Layers 1, 2 ========
#pragma unroll
        for (int l = 1; l < NL; l++) {
            // issue fresh A (h[wr][l-1]) immediately; stale compute hides it
            stage_tile(&s->afresh[0][0][0], &g_hb[wr][0][l - 1][0][kb], NH);
            stage_tile(&s->afresh[1][0][0], &g_hb[wr][1][l - 1][0][kb], NH);
            cpa_commit();
            float C[16][4];
#pragma unroll
            for (int m = 0; m < 16; m++)
#pragma unroll
                for (int v = 0; v < 4; v++) C[m][v] = 0.f;
            cpa_wait<1>();                  // stale (+wfresh) group done
            __syncthreads();
            compute_ab(&s->astale[0], &s->astale[2], C, warp, lane);   // Wh GEMM
            cpa_wait<0>();                  // fresh A done
            __syncthreads();
            compute_ab(&s->afresh[0], &s->wfresh[0], C, warp, lane);   // Wxr GEMM
            epilogue_regs(&g_part[pp][kt][gc0][0], C, warp, lane);
            __syncthreads();
            // combined prefetch for next stale + next fresh-W
            if (l == 1) {
                stage_tile(&s->astale[0][0][0], &g_hb[rd][0][2][0][kb], NH);
                stage_tile(&s->astale[1][0][0], &g_hb[rd][1][2][0][kb], NH);
                stage_tile(&s->astale[2][0][0], g_wht[0] + ((size_t)2 * NG + gc0) * NH + kb, NH);
                stage_tile(&s->astale[3][0][0], g_wht[1] + ((size_t)2 * NG + gc0) * NH + kb, NH);
                stage_tile(&s->wfresh[0][0][0],
                           g_wxrt[0] + ((size_t)1 * NG + gc0) * NH + kb, NH);
                stage_tile(&s->wfresh[1][0][0],
                           g_wxrt[1] + ((size_t)1 * NG + gc0) * NH + kb, NH);
            } else {
                stage_tile(&s->astale[0][0][0], &g_hb[wr][0][0][0][kb], NH);
                stage_tile(&s->astale[1][0][0], &g_hb[wr][1][0][0][kb], NH);
                stage_tile(&s->astale[2][0][0], g_wht[0] + (size_t)gc0 * NH + kb, NH);
                stage_tile(&s->astale[3][0][0], g_wht[1] + (size_t)gc0 * NH + kb, NH);
                stage_tile(&s->wfresh[0][0][0], g_wxrt[0] + (size_t)gc0 * NH + kb, NH);
                stage_tile(&s->wfresh[1][0][0], g_wxrt[1] + (size_t)gc0 * NH + kb, NH);
            }
            cpa_commit();
            grid_barrier2(cta, ++bar_t);   // barrier A
            // reduce (fully unrolled)
            float sum[8];
#pragma unroll
            for (int gi = 0; gi < 8; gi++) sum[gi] = 0.f;
#pragma unroll
            for (int k2 = 0; k2 < NKT; k2++)
#pragma unroll
                for (int gi = 0; gi < 8; gi++)
                    sum[gi] += __ldcg(&g_part[pp][k2][gcolv[gi]][rr]);
#pragma unroll
            for (int gi = 0; gi < 8; gi++) {
                int gl = gi * 2 + half;
                s->gex[gl >> 2][rr][gl & 3] = sum[gi];
            }
            pp ^= 1;
            __syncthreads();
            if (tid < NB) {
                const int b = tid;
#pragma unroll
                for (int j = 0; j < 4; j++) {
                    float ig = s->gex[0][b][j] + s->bias[l][b][j];
                    float fg = s->gex[1][b][j] + s->bias[l][b][4 + j];
                    float gg = s->gex[2][b][j] + s->bias[l][b][8 + j];
                    float og = s->gex[3][b][j] + s->bias[l][b][12 + j];
                    float c_new = sigm(fg) * s->cst[l][b][j] + sigm(ig) * tanhf(gg);
                    float h_new = sigm(og) * tanhf(c_new);
                    s->cst[l][b][j] = c_new;
                    __nv_bfloat16 hi, lo;
                    split_bf16(h_new, hi, lo);
                    g_hb[wr][0][l][b][hc4 + j] = hi;
                    g_hb[wr][1][l][b][hc4 + j] = lo;
                    if (l == 2) g_h2[b][hc4 + j] = h_new;
                    if (t == NT - 1)
                        out_hfin[(size_t)l * NB * NH + (size_t)b * NH + hc4 + j] = h_new;
                }
            }
            if (l == 1) grid_barrier2(cta, ++bar_t);   // barrier B (L1 only)
        }
    }

    // ---- final projection (t = NT-1) ----
    grid_barrier2(cta, ++bar_t);
    {
        const float* hrow = &g_h2[orow0 + tr][0] + (grp << 8);
        const int kb2 = grp << 8;
        float a0 = 0.f, a1 = 0.f;
#pragma unroll
        for (int k = 0; k < 256; k += 8) {
            float4 v0 = __ldcg(reinterpret_cast<const float4*>(hrow + k));
            float4 v1 = __ldcg(reinterpret_cast<const float4*>(hrow + k + 4));
            a0 += v0.x * s->woutc[kb2 + k + 0][tc] + v0.y * s->woutc[kb2 + k + 1][tc]
                + v0.z * s->woutc[kb2 + k + 2][tc] + v0.w * s->woutc[kb2 + k + 3][tc];
            a1 += v1.x * s->woutc[kb2 + k + 4][tc] + v1.y * s->woutc[kb2 + k + 5][tc]
                + v1.z * s->woutc[kb2 + k + 6][tc] + v1.w * s->woutc[kb2 + k + 7][tc];
        }
        float accp = (grp ? 0.f : bout_r) + a0 + a1;
        if (grp == 1) s->opart[q] = accp;
        __syncthreads();
        if (grp == 0) {
            accp += s->opart[q];
            out_seq[(size_t)(orow0 + tr) * NT * NLAT + (size_t)(NT - 1) * NLAT +
                    ocol0 + tc] = sigm(accp);
        }
    }
}

extern "C" void kernel_launch(void* const* d_in, const int* in_sizes, int n_in,
                              void* d_out, int out_size) {
    const float* noise = (const float*)d_in[0];
    const float* h_cpl = (const float*)d_in[1];
    const float* Wx0   = (const float*)d_in[2];
    const float* Wxr   = (const float*)d_in[3];
    const float* Wh    = (const float*)d_in[4];
    const float* Wc    = (const float*)d_in[5];
    const float* bvec  = (const float*)d_in[6];
    const float* Wout  = (const float*)d_in[7];
    const float* bout  = (const float*)d_in[8];
    float* out = (float*)d_out;

    cudaFuncSetAttribute(bilateral_kernel, cudaFuncAttributeMaxDynamicSharedMemorySize,
                         (int)sizeof(Smem));
    bilateral_kernel<<<NCTA, NTHR, sizeof(Smem)>>>(noise, h_cpl, Wx0, Wxr, Wh, Wc,
                                                   bvec, Wout, bout, out);
}

// round 11
// speedup vs baseline: 2.4085x; 1.0057x over previous
#include <cuda_runtime.h>
#include <cuda_bf16.h>
#include <cstdint>

#define NB 128
#define NT 512
#define NDIM 128
#define NH 512
#define NG 2048
#define NLAT 128
#define NL 3
#define NCTA 128
#define NTHR 256
#define NKT 8            // k-tiles
#define NCT 16           // col-tiles
#define KSL 64           // K slice per tile
#define AK 72            // padded bf16 row stride (144B)

struct __align__(1024) Smem {
    __nv_bfloat16 afresh[2][128][AK];   // fresh A (hi/lo)
    __nv_bfloat16 astale[4][128][AK];   // stale GEMM: Ahi,Alo,Whi,Wlo
    __nv_bfloat16 wfresh[2][128][AK];   // fresh GEMM weights (Wxr hi/lo)
    float bias[NL][NB][16];
    float cst[NL][NB][4];
    float gex[4][NB][5];
    float woutc[NH][8];
    float opart[NB];
};

__device__ float g_part[2][NKT][NG][NB];               // ping-pong k-split partials
__device__ float g_xproj[(size_t)NT * NG * NB];        // precomputed x@Wx0
__device__ float g_h2[NB][NH];
__device__ __nv_bfloat16 g_hb[2][2][NL][NB][NH];       // [pingpong][hi/lo]
__device__ __nv_bfloat16 g_nb[2][NB * NT * NDIM];
__device__ __nv_bfloat16 g_cb[2][NL * NB * NH];
__device__ __nv_bfloat16 g_wx0t[2][NG * NDIM];
__device__ __nv_bfloat16 g_wxrt[2][(NL - 1) * NG * NH];
__device__ __nv_bfloat16 g_wht[2][NL * NG * NH];
__device__ __nv_bfloat16 g_wct[2][NL * NG * NH];
__device__ unsigned g_flags[NCTA][32];                 // 128B-padded barrier flags

__device__ __forceinline__ float sigm(float x) { return 1.f / (1.f + __expf(-x)); }

__device__ __forceinline__ void split_bf16(float v, __nv_bfloat16& hi, __nv_bfloat16& lo) {
    unsigned u = __float_as_uint(v);
    hi = __ushort_as_bfloat16((unsigned short)(u >> 16));
    float hf = __uint_as_float(u & 0xFFFF0000u);
    lo = __float2bfloat16(v - hf);
}

__device__ __forceinline__ uint32_t smem_u32(const void* p) {
    uint32_t a;
    asm("{ .reg .u64 t; cvta.to.shared.u64 t, %1; cvt.u32.u64 %0, t; }" : "=r"(a) : "l"(p));
    return a;
}

__device__ __forceinline__ void cpa16(void* dst, const void* src) {
    unsigned d = (unsigned)__cvta_generic_to_shared(dst);
    asm volatile("cp.async.cg.shared.global [%0], [%1], 16;" :: "r"(d), "l"(src));
}
__device__ __forceinline__ void cpa_commit() {
    asm volatile("cp.async.commit_group;" ::: "memory");
}
template <int N>
__device__ __forceinline__ void cpa_wait() {
    asm volatile("cp.async.wait_group %0;" :: "n"(N) : "memory");
}

__device__ __forceinline__ void ldsm4(unsigned& r0, unsigned& r1, unsigned& r2,
                                      unsigned& r3, unsigned addr) {
    asm volatile("ldmatrix.sync.aligned.m8n8.x4.shared.b16 {%0,%1,%2,%3}, [%4];"
                 : "=r"(r0), "=r"(r1), "=r"(r2), "=r"(r3) : "r"(addr));
}
__device__ __forceinline__ void mma16816(float* c, unsigned a0, unsigned a1, unsigned a2,
                                         unsigned a3, unsigned b0, unsigned b1) {
    asm volatile(
        "mma.sync.aligned.m16n8k16.row.col.f32.bf16.bf16.f32 "
        "{%0,%1,%2,%3}, {%4,%5,%6,%7}, {%8,%9}, {%0,%1,%2,%3};"
        : "+f"(c[0]), "+f"(c[1]), "+f"(c[2]), "+f"(c[3])
        : "r"(a0), "r"(a1), "r"(a2), "r"(a3), "r"(b0), "r"(b1));
}

__device__ __forceinline__ void bar_arrive(int cta, unsigned target) {
    __syncthreads();
    if (threadIdx.x == 0) {
        __threadfence();
        atomicExch(&g_flags[cta][0], target);
    }
}
__device__ __forceinline__ void bar_wait(unsigned target) {
    for (;;) {
        unsigned v = (threadIdx.x < NCTA) ? __ldcg(&g_flags[threadIdx.x][0]) : target;
        if (__syncthreads_count((int)(v < target)) == 0) break;
    }
    __threadfence();
}
__device__ __forceinline__ void grid_barrier2(int cta, unsigned target) {
    bar_arrive(cta, target);
    bar_wait(target);
}

// Stage one 128x64 bf16 tile into padded smem rows (144B pitch).
__device__ __forceinline__ void stage_tile(__nv_bfloat16* dst, const __nv_bfloat16* src,
                                           int ld) {
    const int tid = threadIdx.x;
#pragma unroll
    for (int it = 0; it < 4; it++) {
        int idx = it * NTHR + tid;       // 0..1023
        int r = idx >> 3, g = idx & 7;
        cpa16(dst + r * AK + g * 8, src + (size_t)r * ld + g * 8);
    }
}

// HMMA: C += A * W^T (3-term bf16 split). A tiles at At[0..1], W tiles at Wt[0..1].
__device__ __forceinline__ void compute_ab(const __nv_bfloat16 (*At)[128][AK],
                                           const __nv_bfloat16 (*Wt)[128][AK],
                                           float (*C)[4], int warp, int lane) {
    const int ar = warp * 16 + (lane & 15);
    const int ak = (lane >> 4) * 8;
    const unsigned ah_b = smem_u32(&At[0][ar][ak]);
    const unsigned al_b = smem_u32(&At[1][ar][ak]);
    const int bc = (lane & 7) + ((lane >= 16) ? 8 : 0);
    const int bk = ((lane >> 3) & 1) * 8;
    const unsigned bh_b = smem_u32(&Wt[0][bc][bk]);
    const unsigned bl_b = smem_u32(&Wt[1][bc][bk]);
#pragma unroll
    for (int ks = 0; ks < 4; ks++) {
        unsigned ah0, ah1, ah2, ah3, al0, al1, al2, al3;
        ldsm4(ah0, ah1, ah2, ah3, ah_b + ks * 32);
        ldsm4(al0, al1, al2, al3, al_b + ks * 32);
#pragma unroll
        for (int nt = 0; nt < 8; nt++) {
            unsigned bh0, bh1, bh2, bh3, bl0, bl1, bl2, bl3;
            const unsigned off = nt * 16 * (AK * 2) + ks * 32;
            ldsm4(bh0, bh1, bh2, bh3, bh_b + off);
            ldsm4(bl0, bl1, bl2, bl3, bl_b + off);
            mma16816(C[2 * nt],     ah0, ah1, ah2, ah3, bh0, bh1);
            mma16816(C[2 * nt + 1], ah0, ah1, ah2, ah3, bh2, bh3);
            mma16816(C[2 * nt],     ah0, ah1, ah2, ah3, bl0, bl1);
            mma16816(C[2 * nt + 1], ah0, ah1, ah2, ah3, bl2, bl3);
            mma16816(C[2 * nt],     al0, al1, al2, al3, bh0, bh1);
            mma16816(C[2 * nt + 1], al0, al1, al2, al3, bh2, bh3);
        }
    }
}

__device__ __forceinline__ void epilogue_regs(float* base, float (*C)[4],
                                              int warp, int lane) {
    const int r0 = warp * 16 + (lane >> 2);
    const int c0 = 2 * (lane & 3);
#pragma unroll
    for (int n8 = 0; n8 < 16; n8++) {
        int cb = n8 * 8 + c0;
        base[(size_t)cb * NB + r0] = C[n8][0];
        base[(size_t)(cb + 1) * NB + r0] = C[n8][1];
        base[(size_t)cb * NB + r0 + 8] = C[n8][2];
        base[(size_t)(cb + 1) * NB + r0 + 8] = C[n8][3];
    }
}

__global__ void __launch_bounds__(NTHR, 1)
bilateral_kernel(const float* __restrict__ noise,
                 const float* __restrict__ h_cpl,
                 const float* __restrict__ Wx0,
                 const float* __restrict__ Wxr,
                 const float* __restrict__ Wh,
                 const float* __restrict__ Wc,
                 const float* __restrict__ bvec,
                 const float* __restrict__ Wout,
                 const float* __restrict__ bout,
                 float* __restrict__ out) {
    extern __shared__ char smem_raw[];
    Smem* s = reinterpret_cast<Smem*>(smem_raw);
    const int tid = threadIdx.x;
    const int cta = blockIdx.x;
    const int warp = tid >> 5, lane = tid & 31;
    const int kt = cta >> 4;
    const int ct = cta & 15;
    const int gc0 = ct * 128;
    const int kb = kt * KSL;
    const int hc4 = cta * 4;
    const int half = tid >> 7, rr = tid & 127;

    unsigned bar_t = g_flags[cta][0];

    float* out_seq = out;
    float* out_hfin = out + (size_t)NB * NT * NLAT;

    const int orow0 = (cta >> 4) * 16;
    const int ocol0 = (cta & 15) * 8;
    const int q = tid & 127, grp = tid >> 7;
    const int tr = q >> 3, tc = q & 7;
    const float bout_r = bout[ocol0 + tc];

    // reduce column indices (constant per thread)
    int gcolv[8];
#pragma unroll
    for (int gi = 0; gi < 8; gi++) {
        int gl = gi * 2 + half;
        gcolv[gi] = (gl >> 2) * 512 + hc4 + (gl & 3);
    }

    // ---- phase 0: conversions + zero init ----
    for (int i = cta * NTHR + tid; i < NB * NT * NDIM; i += NCTA * NTHR)
        split_bf16(noise[i], g_nb[0][i], g_nb[1][i]);
    for (int i = cta * NTHR + tid; i < NL * NB * NH; i += NCTA * NTHR)
        split_bf16(h_cpl[i], g_cb[0][i], g_cb[1][i]);
    {
        __nv_bfloat16* hz = &g_hb[0][0][0][0][0];
        __nv_bfloat16 z = __float2bfloat16(0.f);
        for (int i = cta * NTHR + tid; i < 2 * NL * NB * NH; i += NCTA * NTHR) hz[i] = z;
    }
    for (int i = tid; i < NL * NB * 4; i += NTHR) (&s->cst[0][0][0])[i] = 0.f;
    for (int i = tid; i < NH * 8; i += NTHR) {
        int k = i >> 3, c = i & 7;
        s->woutc[k][c] = Wout[(size_t)k * NLAT + ocol0 + c];
    }

    // ---- phase 0b: weight transpose + bf16 split ----
    {
        float (*tile)[33] = reinterpret_cast<float (*)[33]>(&s->afresh[0][0][0]);
        const int tx = tid & 31, ty = tid >> 5;
        for (int idx = cta; idx < 8448; idx += NCTA) {
            const float* src;
            __nv_bfloat16 *dh, *dl;
            int R, t;
            if (idx < 256) {
                src = Wx0; dh = g_wx0t[0]; dl = g_wx0t[1]; R = NDIM; t = idx;
            } else {
                int j = (idx - 256) >> 10;
                t = (idx - 256) & 1023;
                R = NH;
                if (j < 2) {
                    src = Wxr + (size_t)j * NH * NG;
                    dh = g_wxrt[0] + (size_t)j * NG * NH;
                    dl = g_wxrt[1] + (size_t)j * NG * NH;
                } else if (j < 5) {
                    src = Wh + (size_t)(j - 2) * NH * NG;
                    dh = g_wht[0] + (size_t)(j - 2) * NG * NH;
                    dl = g_wht[1] + (size_t)(j - 2) * NG * NH;
                } else {
                    src = Wc + (size_t)(j - 5) * NH * NG;
                    dh = g_wct[0] + (size_t)(j - 5) * NG * NH;
                    dl = g_wct[1] + (size_t)(j - 5) * NG * NH;
                }
            }
            const int tr_ = t / (NG / 32), tc_ = t % (NG / 32);
            const int r0 = tr_ * 32, c0 = tc_ * 32;
            __syncthreads();
#pragma unroll
            for (int i = 0; i < 32; i += 8)
                tile[ty + i][tx] = src[(size_t)(r0 + ty + i) * NG + c0 + tx];
            __syncthreads();
#pragma unroll
            for (int i = 0; i < 32; i += 8) {
                float v = tile[tx][ty + i];
                __nv_bfloat16 hi, lo;
                split_bf16(v, hi, lo);
                size_t o = (size_t)(c0 + ty + i) * R + r0 + tx;
                dh[o] = hi;
                dl[o] = lo;
            }
        }
    }
    __syncthreads();
    grid_barrier2(cta, ++bar_t);

    // ---- phase 1: precompute x@Wx0 for all t ----
    for (int idx = cta; idx < NT * NCT; idx += NCTA) {
        const int t = idx >> 4;
        const int gx = (idx & 15) * 128;
        // chunk 0 -> astale (A + W), chunk 1 -> afresh (A) + wfresh (W)
        stage_tile(&s->astale[0][0][0], g_nb[0] + (size_t)t * NDIM, NT * NDIM);
        stage_tile(&s->astale[1][0][0], g_nb[1] + (size_t)t * NDIM, NT * NDIM);
        stage_tile(&s->astale[2][0][0], g_wx0t[0] + (size_t)gx * NDIM, NDIM);
        stage_tile(&s->astale[3][0][0], g_wx0t[1] + (size_t)gx * NDIM, NDIM);
        stage_tile(&s->afresh[0][0][0], g_nb[0] + (size_t)t * NDIM + 64, NT * NDIM);
        stage_tile(&s->afresh[1][0][0], g_nb[1] + (size_t)t * NDIM + 64, NT * NDIM);
        stage_tile(&s->wfresh[0][0][0], g_wx0t[0] + (size_t)gx * NDIM + 64, NDIM);
        stage_tile(&s->wfresh[1][0][0], g_wx0t[1] + (size_t)gx * NDIM + 64, NDIM);
        cpa_commit();
        float C[16][4];
#pragma unroll
        for (int m = 0; m < 16; m++)
#pragma unroll
            for (int v = 0; v < 4; v++) C[m][v] = 0.f;
        cpa_wait<0>();
        __syncthreads();
        compute_ab(&s->astale[0], &s->astale[2], C, warp, lane);
        compute_ab(&s->afresh[0], &s->wfresh[0], C, warp, lane);
        epilogue_regs(&g_xproj[((size_t)t * NG + gx) * NB], C, warp, lane);
        __syncthreads();
    }

    // ---- phase 2: bias = h_coupled @ Wc + b ----
    for (int l = 0; l < NL; l++) {
        stage_tile(&s->astale[0][0][0], g_cb[0] + (size_t)l * NB * NH + kb, NH);
        stage_tile(&s->astale[1][0][0], g_cb[1] + (size_t)l * NB * NH + kb, NH);
        stage_tile(&s->astale[2][0][0], g_wct[0] + ((size_t)l * NG + gc0) * NH + kb, NH);
        stage_tile(&s->astale[3][0][0], g_wct[1] + ((size_t)l * NG + gc0) * NH + kb, NH);
        cpa_commit();
        float C[16][4];
#pragma unroll
        for (int m = 0; m < 16; m++)
#pragma unroll
            for (int v = 0; v < 4; v++) C[m][v] = 0.f;
        cpa_wait<0>();
        __syncthreads();
        compute_ab(&s->astale[0], &s->astale[2], C, warp, lane);
        epilogue_regs(&g_part[0][kt][gc0][0], C, warp, lane);
        grid_barrier2(cta, ++bar_t);
#pragma unroll
        for (int gi = 0; gi < 8; gi++) {
            int gl = gi * 2 + half;
            float sum = 0.f;
#pragma unroll
            for (int k2 = 0; k2 < NKT; k2++) sum += __ldcg(&g_part[0][k2][gcolv[gi]][rr]);
            s->bias[l][rr][gl] = sum + bvec[l * NG + gcolv[gi]];
        }
        grid_barrier2(cta, ++bar_t);
    }

    // ---- pre-loop combined prefetch: L0 stale (h[0][0] + Wht[0]) + L1 wfresh (Wxr[0]) ----
    stage_tile(&s->astale[0][0][0], &g_hb[0][0][0][0][kb], NH);
    stage_tile(&s->astale[1][0][0], &g_hb[0][1][0][0][kb], NH);
    stage_tile(&s->astale[2][0][0], g_wht[0] + (size_t)gc0 * NH + kb, NH);
    stage_tile(&s->astale[3][0][0], g_wht[1] + (size_t)gc0 * NH + kb, NH);
    stage_tile(&s->wfresh[0][0][0], g_wxrt[0] + (size_t)gc0 * NH + kb, NH);
    stage_tile(&s->wfresh[1][0][0], g_wxrt[1] + (size_t)gc0 * NH + kb, NH);
    cpa_commit();

    int pp = 0;

    // ---- phase 3: main recurrence ----
    for (int t = 0; t < NT; t++) {
        const int rd = t & 1, wr = rd ^ 1;

        // ======== Layer 0 ========
        {
            float C[16][4];
#pragma unroll
            for (int m = 0; m < 16; m++)
#pragma unroll
                for (int v = 0; v < 4; v++) C[m][v] = 0.f;
            cpa_wait<0>();
            __syncthreads();
            compute_ab(&s->astale[0], &s->astale[2], C, warp, lane);
            epilogue_regs(&g_part[pp][kt][gc0][0], C, warp, lane);
            __syncthreads();
            // prefetch L1 stale: A=h[rd][1], W=Wht[1]
            stage_tile(&s->astale[0][0][0], &g_hb[rd][0][1][0][kb], NH);
            stage_tile(&s->astale[1][0][0], &g_hb[rd][1][1][0][kb], NH);
            stage_tile(&s->astale[2][0][0], g_wht[0] + ((size_t)1 * NG + gc0) * NH + kb, NH);
            stage_tile(&s->astale[3][0][0], g_wht[1] + ((size_t)1 * NG + gc0) * NH + kb, NH);
            cpa_commit();
            grid_barrier2(cta, ++bar_t);   // barrier A (L0)
            // projection for previous step (MLP-friendly: 4 accumulators, full unroll)
            if (t > 0) {
                const float* hrow = &g_h2[orow0 + tr][0] + (grp << 8);
                const int kb2 = grp << 8;
                float a0 = 0.f, a1 = 0.f, a2 = 0.f, a3 = 0.f;
#pragma unroll
                for (int k = 0; k < 256; k += 16) {
                    float4 v0 = __ldcg(reinterpret_cast<const float4*>(hrow + k));
                    float4 v1 = __ldcg(reinterpret_cast<const float4*>(hrow + k + 4));
                    float4 v2 = __ldcg(reinterpret_cast<const float4*>(hrow + k + 8));
                    float4 v3 = __ldcg(reinterpret_cast<const float4*>(hrow + k + 12));
                    a0 += v0.x * s->woutc[kb2 + k + 0][tc] + v0.y * s->woutc[kb2 + k + 1][tc]
                        + v0.z * s->woutc[kb2 + k + 2][tc] + v0.w * s->woutc[kb2 + k + 3][tc];
                    a1 += v1.x * s->woutc[kb2 + k + 4][tc] + v1.y * s->woutc[kb2 + k + 5][tc]
                        + v1.z * s->woutc[kb2 + k + 6][tc] + v1.w * s->woutc[kb2 + k + 7][tc];
                    a2 += v2.x * s->woutc[kb2 + k + 8][tc] + v2.y * s->woutc[kb2 + k + 9][tc]
                        + v2.z * s->woutc[kb2 + k + 10][tc] + v2.w * s->woutc[kb2 + k + 11][tc];
                    a3 += v3.x * s->woutc[kb2 + k + 12][tc] + v3.y * s->woutc[kb2 + k + 13][tc]
                        + v3.z * s->woutc[kb2 + k + 14][tc] + v3.w * s->woutc[kb2 + k + 15][tc];
                }
                float accp = (grp ? 0.f : bout_r) + ((a0 + a1) + (a2 + a3));
                if (grp == 1) s->opart[q] = accp;
                __syncthreads();
                if (grp == 0) {
                    accp += s->opart[q];
                    out_seq[(size_t)(orow0 + tr) * NT * NLAT + (size_t)(t - 1) * NLAT +
                            ocol0 + tc] = sigm(accp);
                }
            }
            // reduce (fully unrolled: 64 loads in flight) + xproj
            float sum[8];
#pragma unroll
            for (int gi = 0; gi < 8; gi++)
                sum[gi] = __ldcg(&g_xproj[((size_t)t * NG + gcolv[gi]) * NB + rr]);
#pragma unroll
            for (int k2 = 0; k2 < NKT; k2++)
#pragma unroll
                for (int gi = 0; gi < 8; gi++)
                    sum[gi] += __ldcg(&g_part[pp][k2][gcolv[gi]][rr]);
#pragma unroll
            for (int gi = 0; gi < 8; gi++) {
                int gl = gi * 2 + half;
                s->gex[gl >> 2][rr][gl & 3] = sum[gi];
            }
            pp ^= 1;
            __syncthreads();
            if (tid < NB) {
                const int b = tid;
#pragma unroll
                for (int j = 0; j < 4; j++) {
                    float ig = s->gex[0][b][j] + s->bias[0][b][j];
                    float fg = s->gex[1][b][j] + s->bias[0][b][4 + j];
                    float gg = s->gex[2][b][j] + s->bias[0][b][8 + j];
                    float og = s->gex[3][b][j] + s->bias[0][b][12 + j];
                    float c_new = sigm(fg) * s->cst[0][b][j] + sigm(ig) * tanhf(gg);
                    float h_new = sigm(og) * tanhf(c_new);
                    s->cst[0][b][j] = c_new;
                    __nv_bfloat16 hi, lo;
                    split_bf16(h_new, hi, lo);
                    g_hb[wr][0][0][b][hc4 + j] = hi;
                    g_hb[wr][1][0][b][hc4 + j] = lo;
                    if (t == NT - 1)
                        out_hfin[(size_t)b * NH + hc4 + j] = h_new;
                }
            }
            grid_barrier2(cta, ++bar_t);   // barrier B (L0)
        }

        // ======== Layers 1, 2 ========
#pragma unroll
        for (int l = 1; l < NL; l++) {
            // issue fresh A (h[wr][l-1]) immediately; stale compute hides it
            stage_tile(&s->afresh[0][0][0], &g_hb[wr][0][l - 1][0][kb], NH);
            stage_tile(&s->afresh[1][0][0], &g_hb[wr][1][l - 1][0][kb], NH);
            cpa_commit();
            float C[16][4];
#pragma unroll
            for (int m = 0; m < 16; m++)
#pragma unroll
                for (int v = 0; v < 4; v++) C[m][v] = 0.f;
            cpa_wait<1>();                  // stale (+wfresh) group done
            __syncthreads();
            compute_ab(&s->astale[0], &s->astale[2], C, warp, lane);   // Wh GEMM
            cpa_wait<0>();                  // fresh A done
            __syncthreads();
            compute_ab(&s->afresh[0], &s->wfresh[0], C, warp, lane);   // Wxr GEMM
            epilogue_regs(&g_part[pp][kt][gc0][0], C, warp, lane);
            __syncthreads();
            // combined prefetch for next stale + next fresh-W
            if (l == 1) {
                stage_tile(&s->astale[0][0][0], &g_hb[rd][0][2][0][kb], NH);
                stage_tile(&s->astale[1][0][0], &g_hb[rd][1][2][0][kb], NH);
                stage_tile(&s->astale[2][0][0], g_wht[0] + ((size_t)2 * NG + gc0) * NH + kb, NH);
                stage_tile(&s->astale[3][0][0], g_wht[1] + ((size_t)2 * NG + gc0) * NH + kb, NH);
                stage_tile(&s->wfresh[0][0][0],
                           g_wxrt[0] + ((size_t)1 * NG + gc0) * NH + kb, NH);
                stage_tile(&s->wfresh[1][0][0],
                           g_wxrt[1] + ((size_t)1 * NG + gc0) * NH + kb, NH);
            } else {
                stage_tile(&s->astale[0][0][0], &g_hb[wr][0][0][0][kb], NH);
                stage_tile(&s->astale[1][0][0], &g_hb[wr][1][0][0][kb], NH);
                stage_tile(&s->astale[2][0][0], g_wht[0] + (size_t)gc0 * NH + kb, NH);
                stage_tile(&s->astale[3][0][0], g_wht[1] + (size_t)gc0 * NH + kb, NH);
                stage_tile(&s->wfresh[0][0][0], g_wxrt[0] + (size_t)gc0 * NH + kb, NH);
                stage_tile(&s->wfresh[1][0][0], g_wxrt[1] + (size_t)gc0 * NH + kb, NH);
            }
            cpa_commit();
            grid_barrier2(cta, ++bar_t);   // barrier A
            // reduce (fully unrolled)
            float sum[8];
#pragma unroll
            for (int gi = 0; gi < 8; gi++) sum[gi] = 0.f;
#pragma unroll
            for (int k2 = 0; k2 < NKT; k2++)
#pragma unroll
                for (int gi = 0; gi < 8; gi++)
                    sum[gi] += __ldcg(&g_part[pp][k2][gcolv[gi]][rr]);
#pragma unroll
            for (int gi = 0; gi < 8; gi++) {
                int gl = gi * 2 + half;
                s->gex[gl >> 2][rr][gl & 3] = sum[gi];
            }
            pp ^= 1;
            __syncthreads();
            if (tid < NB) {
                const int b = tid;
#pragma unroll
                for (int j = 0; j < 4; j++) {
                    float ig = s->gex[0][b][j] + s->bias[l][b][j];
                    float fg = s->gex[1][b][j] + s->bias[l][b][4 + j];
                    float gg = s->gex[2][b][j] + s->bias[l][b][8 + j];
                    float og = s->gex[3][b][j] + s->bias[l][b][12 + j];
                    float c_new = sigm(fg) * s->cst[l][b][j] + sigm(ig) * tanhf(gg);
                    float h_new = sigm(og) * tanhf(c_new);
                    s->cst[l][b][j] = c_new;
                    __nv_bfloat16 hi, lo;
                    split_bf16(h_new, hi, lo);
                    g_hb[wr][0][l][b][hc4 + j] = hi;
                    g_hb[wr][1][l][b][hc4 + j] = lo;
                    if (l == 2) g_h2[b][hc4 + j] = h_new;
                    if (t == NT - 1)
                        out_hfin[(size_t)l * NB * NH + (size_t)b * NH + hc4 + j] = h_new;
                }
            }
            if (l == 1) grid_barrier2(cta, ++bar_t);   // barrier B (L1 only)
        }
    }

    // ---- final projection (t = NT-1) ----
    grid_barrier2(cta, ++bar_t);
    {
        const float* hrow = &g_h2[orow0 + tr][0] + (grp << 8);
        const int kb2 = grp << 8;
        float a0 = 0.f, a1 = 0.f;
#pragma unroll
        for (int k = 0; k < 256; k += 8) {
            float4 v0 = __ldcg(reinterpret_cast<const float4*>(hrow + k));
            float4 v1 = __ldcg(reinterpret_cast<const float4*>(hrow + k + 4));
            a0 += v0.x * s->woutc[kb2 + k + 0][tc] + v0.y * s->woutc[kb2 + k + 1][tc]
                + v0.z * s->woutc[kb2 + k + 2][tc] + v0.w * s->woutc[kb2 + k + 3][tc];
            a1 += v1.x * s->woutc[kb2 + k + 4][tc] + v1.y * s->woutc[kb2 + k + 5][tc]
                + v1.z * s->woutc[kb2 + k + 6][tc] + v1.w * s->woutc[kb2 + k + 7][tc];
        }
        float accp = (grp ? 0.f : bout_r) + a0 + a1;
        if (grp == 1) s->opart[q] = accp;
        __syncthreads();
        if (grp == 0) {
            accp += s->opart[q];
            out_seq[(size_t)(orow0 + tr) * NT * NLAT + (size_t)(NT - 1) * NLAT +
                    ocol0 + tc] = sigm(accp);
        }
    }
}

extern "C" void kernel_launch(void* const* d_in, const int* in_sizes, int n_in,
                              void* d_out, int out_size) {
    const float* noise = (const float*)d_in[0];
    const float* h_cpl = (const float*)d_in[1];
    const float* Wx0   = (const float*)d_in[2];
    const float* Wxr   = (const float*)d_in[3];
    const float* Wh    = (const float*)d_in[4];
    const float* Wc    = (const float*)d_in[5];
    const float* bvec  = (const float*)d_in[6];
    const float* Wout  = (const float*)d_in[7];
    const float* bout  = (const float*)d_in[8];
    float* out = (float*)d_out;

    cudaFuncSetAttribute(bilateral_kernel, cudaFuncAttributeMaxDynamicSharedMemorySize,
                         (int)sizeof(Smem));
    bilateral_kernel<<<NCTA, NTHR, sizeof(Smem)>>>(noise, h_cpl, Wx0, Wxr, Wh, Wc,
                                                   bvec, Wout, bout, out);
}

// round 12
// speedup vs baseline: 3.0643x; 1.2723x over previous
#include <cuda_runtime.h>
#include <cuda_bf16.h>
#include <cstdint>

#define NB 128
#define NT 512
#define NDIM 128
#define NH 512
#define NG 2048
#define NLAT 128
#define NL 3
#define NCTA 128
#define NTHR 256
#define NKT 8
#define NCT 16
#define KSL 64

struct __align__(1024) Smem {
    char Abuf[3][2][128 * 128];   // [slice][hi/lo] swizzled 128B-pitch tiles (96KB)
    char Wbuf[2][2][128 * 128];   // [buf][hi/lo] (64KB)
    float bias[NL][NB][16];
    float cst[NL][NB][4];
    float gex[4][NB][5];
    float woutc[NH][8];
    float opart[NB];
};

__device__ float g_part3[NL][NKT][NG][NB];             // per-layer k-split partials
__device__ float g_xproj[(size_t)NT * NG * NB];        // precomputed x@Wx0
__device__ float g_h2[NB][NH];
__device__ __nv_bfloat16 g_hb[2][2][NL][NB][NH];       // [pingpong][hi/lo]
__device__ __nv_bfloat16 g_nb[2][NB * NT * NDIM];
__device__ __nv_bfloat16 g_cb[2][NL * NB * NH];
__device__ __nv_bfloat16 g_wx0t[2][NG * NDIM];
__device__ __nv_bfloat16 g_wxrt[2][(NL - 1) * NG * NH];
__device__ __nv_bfloat16 g_wht[2][NL * NG * NH];
__device__ __nv_bfloat16 g_wct[2][NL * NG * NH];
__device__ unsigned g_flags[NCTA][32];                 // 128B-padded flags

__device__ __forceinline__ float sigm(float x) { return 1.f / (1.f + __expf(-x)); }

__device__ __forceinline__ void split_bf16(float v, __nv_bfloat16& hi, __nv_bfloat16& lo) {
    unsigned u = __float_as_uint(v);
    hi = __ushort_as_bfloat16((unsigned short)(u >> 16));
    float hf = __uint_as_float(u & 0xFFFF0000u);
    lo = __float2bfloat16(v - hf);
}

__device__ __forceinline__ uint32_t smem_u32(const void* p) {
    uint32_t a;
    asm("{ .reg .u64 t; cvta.to.shared.u64 t, %1; cvt.u32.u64 %0, t; }" : "=r"(a) : "l"(p));
    return a;
}

__device__ __forceinline__ void cpa16(void* dst, const void* src) {
    unsigned d = (unsigned)__cvta_generic_to_shared(dst);
    asm volatile("cp.async.cg.shared.global [%0], [%1], 16;" :: "r"(d), "l"(src));
}
__device__ __forceinline__ void cpa_commit() {
    asm volatile("cp.async.commit_group;" ::: "memory");
}
template <int N>
__device__ __forceinline__ void cpa_wait() {
    asm volatile("cp.async.wait_group %0;" :: "n"(N) : "memory");
}

__device__ __forceinline__ void ldsm4(unsigned& r0, unsigned& r1, unsigned& r2,
                                      unsigned& r3, unsigned addr) {
    asm volatile("ldmatrix.sync.aligned.m8n8.x4.shared.b16 {%0,%1,%2,%3}, [%4];"
                 : "=r"(r0), "=r"(r1), "=r"(r2), "=r"(r3) : "r"(addr));
}
__device__ __forceinline__ void mma16816(float* c, unsigned a0, unsigned a1, unsigned a2,
                                         unsigned a3, unsigned b0, unsigned b1) {
    asm volatile(
        "mma.sync.aligned.m16n8k16.row.col.f32.bf16.bf16.f32 "
        "{%0,%1,%2,%3}, {%4,%5,%6,%7}, {%8,%9}, {%0,%1,%2,%3};"
        : "+f"(c[0]), "+f"(c[1]), "+f"(c[2]), "+f"(c[3])
        : "r"(a0), "r"(a1), "r"(a2), "r"(a3), "r"(b0), "r"(b1));
}

__device__ __forceinline__ void grid_barrier2(int cta, unsigned target) {
    __syncthreads();
    if (threadIdx.x == 0) {
        __threadfence();
        atomicExch(&g_flags[cta][0], target);
    }
    for (;;) {
        unsigned v = (threadIdx.x < NCTA) ? __ldcg(&g_flags[threadIdx.x][0]) : target;
        if (__syncthreads_count((int)(v < target)) == 0) break;
    }
    __threadfence();
}

// Stage one 128x64 bf16 tile into 128B-pitch swizzled smem (chunk ^= row&7).
__device__ __forceinline__ void stage_sw(char* dst, const __nv_bfloat16* src, int ld) {
    const int tid = threadIdx.x;
#pragma unroll
    for (int it = 0; it < 4; it++) {
        int idx = it * NTHR + tid;       // 0..1023
        int r = idx >> 3, g = idx & 7;
        cpa16(dst + r * 128 + ((g ^ (r & 7)) << 4), src + (size_t)r * ld + g * 8);
    }
}

// HMMA: C += A * W^T (3-term bf16 split) on swizzled tiles.
__device__ __forceinline__ void compute_sw(const char* Ah, const char* Al,
                                           const char* Wh_, const char* Wl_,
                                           float (*C)[4], int warp, int lane) {
    const int ar = warp * 16 + (lane & 15);
    const int ac = lane >> 4;                     // A k-chunk half
    const unsigned ah_b = smem_u32(Ah) + ar * 128;
    const unsigned al_b = smem_u32(Al) + ar * 128;
    const int bc = (lane & 7) + ((lane >= 16) ? 8 : 0);
    const int bsel = (lane >> 3) & 1;             // B k-chunk half
    const unsigned bh_b = smem_u32(Wh_) + bc * 128;
    const unsigned bl_b = smem_u32(Wl_) + bc * 128;
    const int asw = ar & 7, bsw = bc & 7;
#pragma unroll
    for (int ks = 0; ks < 4; ks++) {
        const unsigned aoff = (unsigned)(((ks * 2 + ac) ^ asw) << 4);
        const unsigned boff = (unsigned)(((ks * 2 + bsel) ^ bsw) << 4);
        unsigned ah0, ah1, ah2, ah3, al0, al1, al2, al3;
        ldsm4(ah0, ah1, ah2, ah3, ah_b + aoff);
        ldsm4(al0, al1, al2, al3, al_b + aoff);
#pragma unroll
        for (int nt = 0; nt < 8; nt++) {
            unsigned bh0, bh1, bh2, bh3, bl0, bl1, bl2, bl3;
            const unsigned roff = nt * 16 * 128 + boff;
            ldsm4(bh0, bh1, bh2, bh3, bh_b + roff);
            ldsm4(bl0, bl1, bl2, bl3, bl_b + roff);
            mma16816(C[2 * nt],     ah0, ah1, ah2, ah3, bh0, bh1);
            mma16816(C[2 * nt + 1], ah0, ah1, ah2, ah3, bh2, bh3);
            mma16816(C[2 * nt],     ah0, ah1, ah2, ah3, bl0, bl1);
            mma16816(C[2 * nt + 1], ah0, ah1, ah2, ah3, bl2, bl3);
            mma16816(C[2 * nt],     al0, al1, al2, al3, bh0, bh1);
            mma16816(C[2 * nt + 1], al0, al1, al2, al3, bh2, bh3);
        }
    }
}

__device__ __forceinline__ void epilogue_regs(float* base, float (*C)[4],
                                              int warp, int lane) {
    const int r0 = warp * 16 + (lane >> 2);
    const int c0 = 2 * (lane & 3);
#pragma unroll
    for (int n8 = 0; n8 < 16; n8++) {
        int cb = n8 * 8 + c0;
        base[(size_t)cb * NB + r0] = C[n8][0];
        base[(size_t)(cb + 1) * NB + r0] = C[n8][1];
        base[(size_t)cb * NB + r0 + 8] = C[n8][2];
        base[(size_t)(cb + 1) * NB + r0 + 8] = C[n8][3];
    }
}

#define ZERO_C(C)                      \
    _Pragma("unroll")                  \
    for (int m = 0; m < 16; m++)       \
        _Pragma("unroll")              \
        for (int v = 0; v < 4; v++) (C)[m][v] = 0.f;

__global__ void __launch_bounds__(NTHR, 1)
bilateral_kernel(const float* __restrict__ noise,
                 const float* __restrict__ h_cpl,
                 const float* __restrict__ Wx0,
                 const float* __restrict__ Wxr,
                 const float* __restrict__ Wh,
                 const float* __restrict__ Wc,
                 const float* __restrict__ bvec,
                 const float* __restrict__ Wout,
                 const float* __restrict__ bout,
                 float* __restrict__ out) {
    extern __shared__ char smem_raw[];
    Smem* s = reinterpret_cast<Smem*>(smem_raw);
    const int tid = threadIdx.x;
    const int cta = blockIdx.x;
    const int warp = tid >> 5, lane = tid & 31;
    const int kt = cta >> 4;
    const int ct = cta & 15;
    const int gc0 = ct * 128;
    const int kb = kt * KSL;
    const int hc4 = cta * 4;
    const int half = tid >> 7, rr = tid & 127;

    unsigned bar_t = g_flags[cta][0];

    float* out_seq = out;
    float* out_hfin = out + (size_t)NB * NT * NLAT;

    const int orow0 = (cta >> 4) * 16;
    const int ocol0 = (cta & 15) * 8;
    const int q = tid & 127, grp = tid >> 7;
    const int tr = q >> 3, tc = q & 7;
    const float bout_r = bout[ocol0 + tc];

    int gcolv[8];
#pragma unroll
    for (int gi = 0; gi < 8; gi++) {
        int gl = gi * 2 + half;
        gcolv[gi] = (gl >> 2) * 512 + hc4 + (gl & 3);
    }

    // ---- phase 0: conversions + zero init ----
    for (int i = cta * NTHR + tid; i < NB * NT * NDIM; i += NCTA * NTHR)
        split_bf16(noise[i], g_nb[0][i], g_nb[1][i]);
    for (int i = cta * NTHR + tid; i < NL * NB * NH; i += NCTA * NTHR)
        split_bf16(h_cpl[i], g_cb[0][i], g_cb[1][i]);
    {
        __nv_bfloat16* hz = &g_hb[0][0][0][0][0];
        __nv_bfloat16 z = __float2bfloat16(0.f);
        for (int i = cta * NTHR + tid; i < 2 * 2 * NL * NB * NH; i += NCTA * NTHR) hz[i] = z;
    }
    for (int i = tid; i < NL * NB * 4; i += NTHR) (&s->cst[0][0][0])[i] = 0.f;
    for (int i = tid; i < NH * 8; i += NTHR) {
        int k = i >> 3, c = i & 7;
        s->woutc[k][c] = Wout[(size_t)k * NLAT + ocol0 + c];
    }

    // ---- phase 0b: weight transpose + bf16 split ----
    {
        float (*tile)[33] = reinterpret_cast<float (*)[33]>(&s->Abuf[0][0][0]);
        const int tx = tid & 31, ty = tid >> 5;
        for (int idx = cta; idx < 8448; idx += NCTA) {
            const float* src;
            __nv_bfloat16 *dh, *dl;
            int R, t;
            if (idx < 256) {
                src = Wx0; dh = g_wx0t[0]; dl = g_wx0t[1]; R = NDIM; t = idx;
            } else {
                int j = (idx - 256) >> 10;
                t = (idx - 256) & 1023;
                R = NH;
                if (j < 2) {
                    src = Wxr + (size_t)j * NH * NG;
                    dh = g_wxrt[0] + (size_t)j * NG * NH;
                    dl = g_wxrt[1] + (size_t)j * NG * NH;
                } else if (j < 5) {
                    src = Wh + (size_t)(j - 2) * NH * NG;
                    dh = g_wht[0] + (size_t)(j - 2) * NG * NH;
                    dl = g_wht[1] + (size_t)(j - 2) * NG * NH;
                } else {
                    src = Wc + (size_t)(j - 5) * NH * NG;
                    dh = g_wct[0] + (size_t)(j - 5) * NG * NH;
                    dl = g_wct[1] + (size_t)(j - 5) * NG * NH;
                }
            }
            const int tr_ = t / (NG / 32), tc_ = t % (NG / 32);
            const int r0 = tr_ * 32, c0 = tc_ * 32;
            __syncthreads();
#pragma unroll
            for (int i = 0; i < 32; i += 8)
                tile[ty + i][tx] = src[(size_t)(r0 + ty + i) * NG + c0 + tx];
            __syncthreads();
#pragma unroll
            for (int i = 0; i < 32; i += 8) {
                float v = tile[tx][ty + i];
                __nv_bfloat16 hi, lo;
                split_bf16(v, hi, lo);
                size_t o = (size_t)(c0 + ty + i) * R + r0 + tx;
                dh[o] = hi;
                dl[o] = lo;
            }
        }
    }
    __syncthreads();
    grid_barrier2(cta, ++bar_t);

    // ---- phase 1: precompute x@Wx0 for all t ----
    for (int idx = cta; idx < NT * NCT; idx += NCTA) {
        const int t = idx >> 4;
        const int gx = (idx & 15) * 128;
        stage_sw(s->Abuf[0][0], g_nb[0] + (size_t)t * NDIM, NT * NDIM);
        stage_sw(s->Abuf[0][1], g_nb[1] + (size_t)t * NDIM, NT * NDIM);
        stage_sw(s->Abuf[1][0], g_nb[0] + (size_t)t * NDIM + 64, NT * NDIM);
        stage_sw(s->Abuf[1][1], g_nb[1] + (size_t)t * NDIM + 64, NT * NDIM);
        stage_sw(s->Wbuf[0][0], g_wx0t[0] + (size_t)gx * NDIM, NDIM);
        stage_sw(s->Wbuf[0][1], g_wx0t[1] + (size_t)gx * NDIM, NDIM);
        stage_sw(s->Wbuf[1][0], g_wx0t[0] + (size_t)gx * NDIM + 64, NDIM);
        stage_sw(s->Wbuf[1][1], g_wx0t[1] + (size_t)gx * NDIM + 64, NDIM);
        cpa_commit();
        float C[16][4];
        ZERO_C(C)
        cpa_wait<0>();
        __syncthreads();
        compute_sw(s->Abuf[0][0], s->Abuf[0][1], s->Wbuf[0][0], s->Wbuf[0][1], C, warp, lane);
        compute_sw(s->Abuf[1][0], s->Abuf[1][1], s->Wbuf[1][0], s->Wbuf[1][1], C, warp, lane);
        epilogue_regs(&g_xproj[((size_t)t * NG + gx) * NB], C, warp, lane);
        __syncthreads();
    }

    // ---- phase 2: bias = h_coupled @ Wc + b ----
    for (int l = 0; l < NL; l++) {
        stage_sw(s->Abuf[0][0], g_cb[0] + (size_t)l * NB * NH + kb, NH);
        stage_sw(s->Abuf[0][1], g_cb[1] + (size_t)l * NB * NH + kb, NH);
        stage_sw(s->Wbuf[0][0], g_wct[0] + ((size_t)l * NG + gc0) * NH + kb, NH);
        stage_sw(s->Wbuf[0][1], g_wct[1] + ((size_t)l * NG + gc0) * NH + kb, NH);
        cpa_commit();
        float C[16][4];
        ZERO_C(C)
        cpa_wait<0>();
        __syncthreads();
        compute_sw(s->Abuf[0][0], s->Abuf[0][1], s->Wbuf[0][0], s->Wbuf[0][1], C, warp, lane);
        epilogue_regs(&g_part3[0][kt][gc0][0], C, warp, lane);
        grid_barrier2(cta, ++bar_t);
#pragma unroll
        for (int gi = 0; gi < 8; gi++) {
            int gl = gi * 2 + half;
            float sum = 0.f;
#pragma unroll
            for (int k2 = 0; k2 < NKT; k2++) sum += __ldcg(&g_part3[0][k2][gcolv[gi]][rr]);
            s->bias[l][rr][gl] = sum + bvec[l * NG + gcolv[gi]];
        }
        grid_barrier2(cta, ++bar_t);
    }

    // ---- phase 3: wavefront recurrence (interval s computes L0(s), L1(s-1), L2(s-2)) ----
    for (int sIv = 0; sIv < NT + 2; sIv++) {
        const int wr = sIv & 1, rd = wr ^ 1;
        const bool act0 = (sIv < NT);
        const bool act1 = (sIv >= 1 && sIv <= NT);
        const bool act2 = (sIv >= 2 && sIv <= NT + 1);

        // --- top staging: A slices (h written last interval) + first W tiles ---
        stage_sw(s->Abuf[0][0], &g_hb[rd][0][0][0][kb], NH);   // A0 = h[0][s-1]
        stage_sw(s->Abuf[0][1], &g_hb[rd][1][0][0][kb], NH);
        cpa_commit();                                          // [A0]
        stage_sw(s->Wbuf[0][0], g_wht[0] + (size_t)gc0 * NH + kb, NH);   // Wh0
        stage_sw(s->Wbuf[0][1], g_wht[1] + (size_t)gc0 * NH + kb, NH);
        cpa_commit();                                          // [Wh0]
        stage_sw(s->Wbuf[1][0], g_wxrt[0] + (size_t)gc0 * NH + kb, NH);  // Wxr0
        stage_sw(s->Wbuf[1][1], g_wxrt[1] + (size_t)gc0 * NH + kb, NH);
        cpa_commit();                                          // [Wxr0]
        stage_sw(s->Abuf[1][0], &g_hb[rd][0][1][0][kb], NH);   // A1 = h[1][s-2]
        stage_sw(s->Abuf[1][1], &g_hb[rd][1][1][0][kb], NH);
        stage_sw(s->Abuf[2][0], &g_hb[rd][0][2][0][kb], NH);   // A2 = h[2][s-3]
        stage_sw(s->Abuf[2][1], &g_hb[rd][1][2][0][kb], NH);
        cpa_commit();                                          // [A1A2]

        // --- projection for t = sIv-3 (overlaps staging) ---
        if (sIv >= 3) {
            const float* hrow = &g_h2[orow0 + tr][0] + (grp << 8);
            const int kb2 = grp << 8;
            float a0 = 0.f, a1 = 0.f, a2 = 0.f, a3 = 0.f;
#pragma unroll
            for (int k = 0; k < 256; k += 16) {
                float4 v0 = __ldcg(reinterpret_cast<const float4*>(hrow + k));
                float4 v1 = __ldcg(reinterpret_cast<const float4*>(hrow + k + 4));
                float4 v2 = __ldcg(reinterpret_cast<const float4*>(hrow + k + 8));
                float4 v3 = __ldcg(reinterpret_cast<const float4*>(hrow + k + 12));
                a0 += v0.x * s->woutc[kb2 + k + 0][tc] + v0.y * s->woutc[kb2 + k + 1][tc]
                    + v0.z * s->woutc[kb2 + k + 2][tc] + v0.w * s->woutc[kb2 + k + 3][tc];
                a1 += v1.x * s->woutc[kb2 + k + 4][tc] + v1.y * s->woutc[kb2 + k + 5][tc]
                    + v1.z * s->woutc[kb2 + k + 6][tc] + v1.w * s->woutc[kb2 + k + 7][tc];
                a2 += v2.x * s->woutc[kb2 + k + 8][tc] + v2.y * s->woutc[kb2 + k + 9][tc]
                    + v2.z * s->woutc[kb2 + k + 10][tc] + v2.w * s->woutc[kb2 + k + 11][tc];
                a3 += v3.x * s->woutc[kb2 + k + 12][tc] + v3.y * s->woutc[kb2 + k + 13][tc]
                    + v3.z * s->woutc[kb2 + k + 14][tc] + v3.w * s->woutc[kb2 + k + 15][tc];
            }
            float accp = (grp ? 0.f : bout_r) + ((a0 + a1) + (a2 + a3));
            if (grp == 1) s->opart[q] = accp;
            __syncthreads();
            if (grp == 0) {
                accp += s->opart[q];
                out_seq[(size_t)(orow0 + tr) * NT * NLAT + (size_t)(sIv - 3) * NLAT +
                        ocol0 + tc] = sigm(accp);
            }
        }

        float C[16][4];
        // job1: L0 = A0 x Wh0
        cpa_wait<2>();
        __syncthreads();
        ZERO_C(C)
        compute_sw(s->Abuf[0][0], s->Abuf[0][1], s->Wbuf[0][0], s->Wbuf[0][1], C, warp, lane);
        __syncthreads();
        stage_sw(s->Wbuf[0][0], g_wht[0] + ((size_t)1 * NG + gc0) * NH + kb, NH);  // Wh1
        stage_sw(s->Wbuf[0][1], g_wht[1] + ((size_t)1 * NG + gc0) * NH + kb, NH);
        cpa_commit();
        epilogue_regs(&g_part3[0][kt][gc0][0], C, warp, lane);
        // job2: L1 += A0 x Wxr0
        cpa_wait<2>();
        __syncthreads();
        ZERO_C(C)
        compute_sw(s->Abuf[0][0], s->Abuf[0][1], s->Wbuf[1][0], s->Wbuf[1][1], C, warp, lane);
        __syncthreads();
        stage_sw(s->Wbuf[1][0], g_wxrt[0] + ((size_t)1 * NG + gc0) * NH + kb, NH); // Wxr1
        stage_sw(s->Wbuf[1][1], g_wxrt[1] + ((size_t)1 * NG + gc0) * NH + kb, NH);
        cpa_commit();
        // job3: L1 += A1 x Wh1
        cpa_wait<1>();
        __syncthreads();
        compute_sw(s->Abuf[1][0], s->Abuf[1][1], s->Wbuf[0][0], s->Wbuf[0][1], C, warp, lane);
        __syncthreads();
        stage_sw(s->Wbuf[0][0], g_wht[0] + ((size_t)2 * NG + gc0) * NH + kb, NH);  // Wh2
        stage_sw(s->Wbuf[0][1], g_wht[1] + ((size_t)2 * NG + gc0) * NH + kb, NH);
        cpa_commit();
        epilogue_regs(&g_part3[1][kt][gc0][0], C, warp, lane);
        // job4: L2 += A1 x Wxr1
        cpa_wait<1>();
        __syncthreads();
        ZERO_C(C)
        compute_sw(s->Abuf[1][0], s->Abuf[1][1], s->Wbuf[1][0], s->Wbuf[1][1], C, warp, lane);
        // job5: L2 += A2 x Wh2
        cpa_wait<0>();
        __syncthreads();
        compute_sw(s->Abuf[2][0], s->Abuf[2][1], s->Wbuf[0][0], s->Wbuf[0][1], C, warp, lane);
        epilogue_regs(&g_part3[2][kt][gc0][0], C, warp, lane);

        grid_barrier2(cta, ++bar_t);   // A: all partials visible

        // --- reduce + cell per active layer ---
#pragma unroll
        for (int l = 0; l < NL; l++) {
            const bool act = (l == 0) ? act0 : (l == 1) ? act1 : act2;
            if (!act) continue;
            const int tL = sIv - l;
            float sum[8];
            if (l == 0) {
#pragma unroll
                for (int gi = 0; gi < 8; gi++)
                    sum[gi] = __ldcg(&g_xproj[((size_t)tL * NG + gcolv[gi]) * NB + rr]);
            } else {
#pragma unroll
                for (int gi = 0; gi < 8; gi++) sum[gi] = 0.f;
            }
#pragma unroll
            for (int k2 = 0; k2 < NKT; k2++)
#pragma unroll
                for (int gi = 0; gi < 8; gi++)
                    sum[gi] += __ldcg(&g_part3[l][k2][gcolv[gi]][rr]);
#pragma unroll
            for (int gi = 0; gi < 8; gi++) {
                int gl = gi * 2 + half;
                s->gex[gl >> 2][rr][gl & 3] = sum[gi];
            }
            __syncthreads();
            if (tid < NB) {
                const int b = tid;
#pragma unroll
                for (int j = 0; j < 4; j++) {
                    float ig = s->gex[0][b][j] + s->bias[l][b][j];
                    float fg = s->gex[1][b][j] + s->bias[l][b][4 + j];
                    float gg = s->gex[2][b][j] + s->bias[l][b][8 + j];
                    float og = s->gex[3][b][j] + s->bias[l][b][12 + j];
                    float c_new = sigm(fg) * s->cst[l][b][j] + sigm(ig) * tanhf(gg);
                    float h_new = sigm(og) * tanhf(c_new);
                    s->cst[l][b][j] = c_new;
                    __nv_bfloat16 hi, lo;
                    split_bf16(h_new, hi, lo);
                    g_hb[wr][0][l][b][hc4 + j] = hi;
                    g_hb[wr][1][l][b][hc4 + j] = lo;
                    if (l == 2) g_h2[b][hc4 + j] = h_new;
                    if (tL == NT - 1)
                        out_hfin[(size_t)l * NB * NH + (size_t)b * NH + hc4 + j] = h_new;
                }
            }
            __syncthreads();
        }

        grid_barrier2(cta, ++bar_t);   // B: all h writes visible
    }

    // ---- final projection (t = NT-1) ----
    {
        const float* hrow = &g_h2[orow0 + tr][0] + (grp << 8);
        const int kb2 = grp << 8;
        float a0 = 0.f, a1 = 0.f;
#pragma unroll
        for (int k = 0; k < 256; k += 8) {
            float4 v0 = __ldcg(reinterpret_cast<const float4*>(hrow + k));
            float4 v1 = __ldcg(reinterpret_cast<const float4*>(hrow + k + 4));
            a0 += v0.x * s->woutc[kb2 + k + 0][tc] + v0.y * s->woutc[kb2 + k + 1][tc]
                + v0.z * s->woutc[kb2 + k + 2][tc] + v0.w * s->woutc[kb2 + k + 3][tc];
            a1 += v1.x * s->woutc[kb2 + k + 4][tc] + v1.y * s->woutc[kb2 + k + 5][tc]
                + v1.z * s->woutc[kb2 + k + 6][tc] + v1.w * s->woutc[kb2 + k + 7][tc];
        }
        float accp = (grp ? 0.f : bout_r) + a0 + a1;
        if (grp == 1) s->opart[q] = accp;
        __syncthreads();
        if (grp == 0) {
            accp += s->opart[q];
            out_seq[(size_t)(orow0 + tr) * NT * NLAT + (size_t)(NT - 1) * NLAT +
                    ocol0 + tc] = sigm(accp);
        }
    }
}

extern "C" void kernel_launch(void* const* d_in, const int* in_sizes, int n_in,
                              void* d_out, int out_size) {
    const float* noise = (const float*)d_in[0];
    const float* h_cpl = (const float*)d_in[1];
    const float* Wx0   = (const float*)d_in[2];
    const float* Wxr   = (const float*)d_in[3];
    const float* Wh    = (const float*)d_in[4];
    const float* Wc    = (const float*)d_in[5];
    const float* bvec  = (const float*)d_in[6];
    const float* Wout  = (const float*)d_in[7];
    const float* bout  = (const float*)d_in[8];
    float* out = (float*)d_out;

    cudaFuncSetAttribute(bilateral_kernel, cudaFuncAttributeMaxDynamicSharedMemorySize,
                         (int)sizeof(Smem));
    bilateral_kernel<<<NCTA, NTHR, sizeof(Smem)>>>(noise, h_cpl, Wx0, Wxr, Wh, Wc,
                                                   bvec, Wout, bout, out);
}

// round 13
// speedup vs baseline: 3.0660x; 1.0005x over previous
#include <cuda_runtime.h>
#include <cuda_bf16.h>
#include <cstdint>

#define NB 128
#define NT 512
#define NDIM 128
#define NH 512
#define NG 2048
#define NLAT 128
#define NL 3
#define NCTA 128
#define NTHR 256
#define NKT 8
#define NCT 16
#define KSL 64

struct __align__(1024) Smem {
    char Abuf[3][2][128 * 128];   // [slice][hi/lo] swizzled 128B-pitch tiles (96KB)
    char Wbuf[2][2][128 * 128];   // [buf][hi/lo] (64KB)
    float bias[NL][NB][16];
    float cst[NL][NB][4];
    float gex[4][NB][5];
    float woutc[NH][8];
    float opart[NB];
};

__device__ float g_part3[NL][NKT][NG][NB];             // per-layer k-split partials
__device__ float g_xproj[(size_t)NT * NG * NB];        // precomputed x@Wx0
__device__ float g_h2[NB][NH];
__device__ __nv_bfloat16 g_hb[2][2][NL][NB][NH];       // [pingpong][hi/lo]
__device__ __nv_bfloat16 g_nb[2][NB * NT * NDIM];
__device__ __nv_bfloat16 g_cb[2][NL * NB * NH];
__device__ __nv_bfloat16 g_wx0t[2][NG * NDIM];
__device__ __nv_bfloat16 g_wxrt[2][(NL - 1) * NG * NH];
__device__ __nv_bfloat16 g_wht[2][NL * NG * NH];
__device__ __nv_bfloat16 g_wct[2][NL * NG * NH];
__device__ unsigned g_flags[NCTA][32];                 // 128B-padded flags

__device__ __forceinline__ float sigm(float x) { return 1.f / (1.f + __expf(-x)); }

__device__ __forceinline__ void split_bf16(float v, __nv_bfloat16& hi, __nv_bfloat16& lo) {
    unsigned u = __float_as_uint(v);
    hi = __ushort_as_bfloat16((unsigned short)(u >> 16));
    float hf = __uint_as_float(u & 0xFFFF0000u);
    lo = __float2bfloat16(v - hf);
}

__device__ __forceinline__ uint32_t smem_u32(const void* p) {
    uint32_t a;
    asm("{ .reg .u64 t; cvta.to.shared.u64 t, %1; cvt.u32.u64 %0, t; }" : "=r"(a) : "l"(p));
    return a;
}

__device__ __forceinline__ void cpa16(void* dst, const void* src) {
    unsigned d = (unsigned)__cvta_generic_to_shared(dst);
    asm volatile("cp.async.cg.shared.global [%0], [%1], 16;" :: "r"(d), "l"(src));
}
__device__ __forceinline__ void cpa_commit() {
    asm volatile("cp.async.commit_group;" ::: "memory");
}
template <int N>
__device__ __forceinline__ void cpa_wait() {
    asm volatile("cp.async.wait_group %0;" :: "n"(N) : "memory");
}

__device__ __forceinline__ void ldsm4(unsigned& r0, unsigned& r1, unsigned& r2,
                                      unsigned& r3, unsigned addr) {
    asm volatile("ldmatrix.sync.aligned.m8n8.x4.shared.b16 {%0,%1,%2,%3}, [%4];"
                 : "=r"(r0), "=r"(r1), "=r"(r2), "=r"(r3) : "r"(addr));
}
__device__ __forceinline__ void mma16816(float* c, unsigned a0, unsigned a1, unsigned a2,
                                         unsigned a3, unsigned b0, unsigned b1) {
    asm volatile(
        "mma.sync.aligned.m16n8k16.row.col.f32.bf16.bf16.f32 "
        "{%0,%1,%2,%3}, {%4,%5,%6,%7}, {%8,%9}, {%0,%1,%2,%3};"
        : "+f"(c[0]), "+f"(c[1]), "+f"(c[2]), "+f"(c[3])
        : "r"(a0), "r"(a1), "r"(a2), "r"(a3), "r"(b0), "r"(b1));
}

__device__ __forceinline__ void grid_barrier2(int cta, unsigned target) {
    __syncthreads();
    if (threadIdx.x == 0) {
        __threadfence();
        atomicExch(&g_flags[cta][0], target);
    }
    for (;;) {
        unsigned v = (threadIdx.x < NCTA) ? __ldcg(&g_flags[threadIdx.x][0]) : target;
        if (__syncthreads_count((int)(v < target)) == 0) break;
    }
    __threadfence();
}

// Stage one 128x64 bf16 tile into 128B-pitch swizzled smem (chunk ^= row&7).
__device__ __forceinline__ void stage_sw(char* dst, const __nv_bfloat16* src, int ld) {
    const int tid = threadIdx.x;
#pragma unroll
    for (int it = 0; it < 4; it++) {
        int idx = it * NTHR + tid;       // 0..1023
        int r = idx >> 3, g = idx & 7;
        cpa16(dst + r * 128 + ((g ^ (r & 7)) << 4), src + (size_t)r * ld + g * 8);
    }
}

// HMMA: C += A * W^T (3-term bf16 split) on swizzled tiles.
__device__ __forceinline__ void compute_sw(const char* Ah, const char* Al,
                                           const char* Wh_, const char* Wl_,
                                           float (*C)[4], int warp, int lane) {
    const int ar = warp * 16 + (lane & 15);
    const int ac = lane >> 4;                     // A k-chunk half
    const unsigned ah_b = smem_u32(Ah) + ar * 128;
    const unsigned al_b = smem_u32(Al) + ar * 128;
    const int bc = (lane & 7) + ((lane >= 16) ? 8 : 0);
    const int bsel = (lane >> 3) & 1;             // B k-chunk half
    const unsigned bh_b = smem_u32(Wh_) + bc * 128;
    const unsigned bl_b = smem_u32(Wl_) + bc * 128;
    const int asw = ar & 7, bsw = bc & 7;
#pragma unroll
    for (int ks = 0; ks < 4; ks++) {
        const unsigned aoff = (unsigned)(((ks * 2 + ac) ^ asw) << 4);
        const unsigned boff = (unsigned)(((ks * 2 + bsel) ^ bsw) << 4);
        unsigned ah0, ah1, ah2, ah3, al0, al1, al2, al3;
        ldsm4(ah0, ah1, ah2, ah3, ah_b + aoff);
        ldsm4(al0, al1, al2, al3, al_b + aoff);
#pragma unroll
        for (int nt = 0; nt < 8; nt++) {
            unsigned bh0, bh1, bh2, bh3, bl0, bl1, bl2, bl3;
            const unsigned roff = nt * 16 * 128 + boff;
            ldsm4(bh0, bh1, bh2, bh3, bh_b + roff);
            ldsm4(bl0, bl1, bl2, bl3, bl_b + roff);
            mma16816(C[2 * nt],     ah0, ah1, ah2, ah3, bh0, bh1);
            mma16816(C[2 * nt + 1], ah0, ah1, ah2, ah3, bh2, bh3);
            mma16816(C[2 * nt],     ah0, ah1, ah2, ah3, bl0, bl1);
            mma16816(C[2 * nt + 1], ah0, ah1, ah2, ah3, bl2, bl3);
            mma16816(C[2 * nt],     al0, al1, al2, al3, bh0, bh1);
            mma16816(C[2 * nt + 1], al0, al1, al2, al3, bh2, bh3);
        }
    }
}

__device__ __forceinline__ void epilogue_regs(float* base, float (*C)[4],
                                              int warp, int lane) {
    const int r0 = warp * 16 + (lane >> 2);
    const int c0 = 2 * (lane & 3);
#pragma unroll
    for (int n8 = 0; n8 < 16; n8++) {
        int cb = n8 * 8 + c0;
        base[(size_t)cb * NB + r0] = C[n8][0];
        base[(size_t)(cb + 1) * NB + r0] = C[n8][1];
        base[(size_t)cb * NB + r0 + 8] = C[n8][2];
        base[(size_t)(cb + 1) * NB + r0 + 8] = C[n8][3];
    }
}

#define ZERO_C(C)                      \
    _Pragma("unroll")                  \
    for (int m = 0; m < 16; m++)       \
        _Pragma("unroll")              \
        for (int v = 0; v < 4; v++) (C)[m][v] = 0.f;

__global__ void __launch_bounds__(NTHR, 1)
bilateral_kernel(const float* __restrict__ noise,
                 const float* __restrict__ h_cpl,
                 const float* __restrict__ Wx0,
                 const float* __restrict__ Wxr,
                 const float* __restrict__ Wh,
                 const float* __restrict__ Wc,
                 const float* __restrict__ bvec,
                 const float* __restrict__ Wout,
                 const float* __restrict__ bout,
                 float* __restrict__ out) {
    extern __shared__ char smem_raw[];
    Smem* s = reinterpret_cast<Smem*>(smem_raw);
    const int tid = threadIdx.x;
    const int cta = blockIdx.x;
    const int warp = tid >> 5, lane = tid & 31;
    const int kt = cta >> 4;
    const int ct = cta & 15;
    const int gc0 = ct * 128;
    const int kb = kt * KSL;
    const int hc4 = cta * 4;
    const int half = tid >> 7, rr = tid & 127;

    unsigned bar_t = g_flags[cta][0];

    float* out_seq = out;
    float* out_hfin = out + (size_t)NB * NT * NLAT;

    const int orow0 = (cta >> 4) * 16;
    const int ocol0 = (cta & 15) * 8;
    const int q = tid & 127, grp = tid >> 7;
    const int tr = q >> 3, tc = q & 7;
    const float bout_r = bout[ocol0 + tc];

    int gcolv[8];
#pragma unroll
    for (int gi = 0; gi < 8; gi++) {
        int gl = gi * 2 + half;
        gcolv[gi] = (gl >> 2) * 512 + hc4 + (gl & 3);
    }

    // ---- phase 0: conversions + zero init ----
    for (int i = cta * NTHR + tid; i < NB * NT * NDIM; i += NCTA * NTHR)
        split_bf16(noise[i], g_nb[0][i], g_nb[1][i]);
    for (int i = cta * NTHR + tid; i < NL * NB * NH; i += NCTA * NTHR)
        split_bf16(h_cpl[i], g_cb[0][i], g_cb[1][i]);
    {
        __nv_bfloat16* hz = &g_hb[0][0][0][0][0];
        __nv_bfloat16 z = __float2bfloat16(0.f);
        for (int i = cta * NTHR + tid; i < 2 * 2 * NL * NB * NH; i += NCTA * NTHR) hz[i] = z;
    }
    for (int i = tid; i < NL * NB * 4; i += NTHR) (&s->cst[0][0][0])[i] = 0.f;
    for (int i = tid; i < NH * 8; i += NTHR) {
        int k = i >> 3, c = i & 7;
        s->woutc[k][c] = Wout[(size_t)k * NLAT + ocol0 + c];
    }

    // ---- phase 0b: weight transpose + bf16 split ----
    {
        float (*tile)[33] = reinterpret_cast<float (*)[33]>(&s->Abuf[0][0][0]);
        const int tx = tid & 31, ty = tid >> 5;
        for (int idx = cta; idx < 8448; idx += NCTA) {
            const float* src;
            __nv_bfloat16 *dh, *dl;
            int R, t;
            if (idx < 256) {
                src = Wx0; dh = g_wx0t[0]; dl = g_wx0t[1]; R = NDIM; t = idx;
            } else {
                int j = (idx - 256) >> 10;
                t = (idx - 256) & 1023;
                R = NH;
                if (j < 2) {
                    src = Wxr + (size_t)j * NH * NG;
                    dh = g_wxrt[0] + (size_t)j * NG * NH;
                    dl = g_wxrt[1] + (size_t)j * NG * NH;
                } else if (j < 5) {
                    src = Wh + (size_t)(j - 2) * NH * NG;
                    dh = g_wht[0] + (size_t)(j - 2) * NG * NH;
                    dl = g_wht[1] + (size_t)(j - 2) * NG * NH;
                } else {
                    src = Wc + (size_t)(j - 5) * NH * NG;
                    dh = g_wct[0] + (size_t)(j - 5) * NG * NH;
                    dl = g_wct[1] + (size_t)(j - 5) * NG * NH;
                }
            }
            const int tr_ = t / (NG / 32), tc_ = t % (NG / 32);
            const int r0 = tr_ * 32, c0 = tc_ * 32;
            __syncthreads();
#pragma unroll
            for (int i = 0; i < 32; i += 8)
                tile[ty + i][tx] = src[(size_t)(r0 + ty + i) * NG + c0 + tx];
            __syncthreads();
#pragma unroll
            for (int i = 0; i < 32; i += 8) {
                float v = tile[tx][ty + i];
                __nv_bfloat16 hi, lo;
                split_bf16(v, hi, lo);
                size_t o = (size_t)(c0 + ty + i) * R + r0 + tx;
                dh[o] = hi;
                dl[o] = lo;
            }
        }
    }
    __syncthreads();
    grid_barrier2(cta, ++bar_t);

    // ---- phase 1: precompute x@Wx0 for all t ----
    for (int idx = cta; idx < NT * NCT; idx += NCTA) {
        const int t = idx >> 4;
        const int gx = (idx & 15) * 128;
        stage_sw(s->Abuf[0][0], g_nb[0] + (size_t)t * NDIM, NT * NDIM);
        stage_sw(s->Abuf[0][1], g_nb[1] + (size_t)t * NDIM, NT * NDIM);
        stage_sw(s->Abuf[1][0], g_nb[0] + (size_t)t * NDIM + 64, NT * NDIM);
        stage_sw(s->Abuf[1][1], g_nb[1] + (size_t)t * NDIM + 64, NT * NDIM);
        stage_sw(s->Wbuf[0][0], g_wx0t[0] + (size_t)gx * NDIM, NDIM);
        stage_sw(s->Wbuf[0][1], g_wx0t[1] + (size_t)gx * NDIM, NDIM);
        stage_sw(s->Wbuf[1][0], g_wx0t[0] + (size_t)gx * NDIM + 64, NDIM);
        stage_sw(s->Wbuf[1][1], g_wx0t[1] + (size_t)gx * NDIM + 64, NDIM);
        cpa_commit();
        float C[16][4];
        ZERO_C(C)
        cpa_wait<0>();
        __syncthreads();
        compute_sw(s->Abuf[0][0], s->Abuf[0][1], s->Wbuf[0][0], s->Wbuf[0][1], C, warp, lane);
        compute_sw(s->Abuf[1][0], s->Abuf[1][1], s->Wbuf[1][0], s->Wbuf[1][1], C, warp, lane);
        epilogue_regs(&g_xproj[((size_t)t * NG + gx) * NB], C, warp, lane);
        __syncthreads();
    }

    // ---- phase 2: bias = h_coupled @ Wc + b ----
    for (int l = 0; l < NL; l++) {
        stage_sw(s->Abuf[0][0], g_cb[0] + (size_t)l * NB * NH + kb, NH);
        stage_sw(s->Abuf[0][1], g_cb[1] + (size_t)l * NB * NH + kb, NH);
        stage_sw(s->Wbuf[0][0], g_wct[0] + ((size_t)l * NG + gc0) * NH + kb, NH);
        stage_sw(s->Wbuf[0][1], g_wct[1] + ((size_t)l * NG + gc0) * NH + kb, NH);
        cpa_commit();
        float C[16][4];
        ZERO_C(C)
        cpa_wait<0>();
        __syncthreads();
        compute_sw(s->Abuf[0][0], s->Abuf[0][1], s->Wbuf[0][0], s->Wbuf[0][1], C, warp, lane);
        epilogue_regs(&g_part3[0][kt][gc0][0], C, warp, lane);
        grid_barrier2(cta, ++bar_t);
#pragma unroll
        for (int gi = 0; gi < 8; gi++) {
            int gl = gi * 2 + half;
            float sum = 0.f;
#pragma unroll
            for (int k2 = 0; k2 < NKT; k2++) sum += __ldcg(&g_part3[0][k2][gcolv[gi]][rr]);
            s->bias[l][rr][gl] = sum + bvec[l * NG + gcolv[gi]];
        }
        grid_barrier2(cta, ++bar_t);
    }

    // ---- phase 3: wavefront recurrence (interval s computes L0(s), L1(s-1), L2(s-2)) ----
    for (int sIv = 0; sIv < NT + 2; sIv++) {
        const int wr = sIv & 1, rd = wr ^ 1;
        const bool act0 = (sIv < NT);
        const bool act1 = (sIv >= 1 && sIv <= NT);
        const bool act2 = (sIv >= 2 && sIv <= NT + 1);

        // --- top staging: A slices (h written last interval) + first W tiles ---
        stage_sw(s->Abuf[0][0], &g_hb[rd][0][0][0][kb], NH);   // A0 = h[0][s-1]
        stage_sw(s->Abuf[0][1], &g_hb[rd][1][0][0][kb], NH);
        cpa_commit();                                          // [A0]
        stage_sw(s->Wbuf[0][0], g_wht[0] + (size_t)gc0 * NH + kb, NH);   // Wh0
        stage_sw(s->Wbuf[0][1], g_wht[1] + (size_t)gc0 * NH + kb, NH);
        cpa_commit();                                          // [Wh0]
        stage_sw(s->Wbuf[1][0], g_wxrt[0] + (size_t)gc0 * NH + kb, NH);  // Wxr0
        stage_sw(s->Wbuf[1][1], g_wxrt[1] + (size_t)gc0 * NH + kb, NH);
        cpa_commit();                                          // [Wxr0]
        stage_sw(s->Abuf[1][0], &g_hb[rd][0][1][0][kb], NH);   // A1 = h[1][s-2]
        stage_sw(s->Abuf[1][1], &g_hb[rd][1][1][0][kb], NH);
        stage_sw(s->Abuf[2][0], &g_hb[rd][0][2][0][kb], NH);   // A2 = h[2][s-3]
        stage_sw(s->Abuf[2][1], &g_hb[rd][1][2][0][kb], NH);
        cpa_commit();                                          // [A1A2]

        // --- projection for t = sIv-3 (overlaps staging) ---
        if (sIv >= 3) {
            const float* hrow = &g_h2[orow0 + tr][0] + (grp << 8);
            const int kb2 = grp << 8;
            float a0 = 0.f, a1 = 0.f, a2 = 0.f, a3 = 0.f;
#pragma unroll
            for (int k = 0; k < 256; k += 16) {
                float4 v0 = __ldcg(reinterpret_cast<const float4*>(hrow + k));
                float4 v1 = __ldcg(reinterpret_cast<const float4*>(hrow + k + 4));
                float4 v2 = __ldcg(reinterpret_cast<const float4*>(hrow + k + 8));
                float4 v3 = __ldcg(reinterpret_cast<const float4*>(hrow + k + 12));
                a0 += v0.x * s->woutc[kb2 + k + 0][tc] + v0.y * s->woutc[kb2 + k + 1][tc]
                    + v0.z * s->woutc[kb2 + k + 2][tc] + v0.w * s->woutc[kb2 + k + 3][tc];
                a1 += v1.x * s->woutc[kb2 + k + 4][tc] + v1.y * s->woutc[kb2 + k + 5][tc]
                    + v1.z * s->woutc[kb2 + k + 6][tc] + v1.w * s->woutc[kb2 + k + 7][tc];
                a2 += v2.x * s->woutc[kb2 + k + 8][tc] + v2.y * s->woutc[kb2 + k + 9][tc]
                    + v2.z * s->woutc[kb2 + k + 10][tc] + v2.w * s->woutc[kb2 + k + 11][tc];
                a3 += v3.x * s->woutc[kb2 + k + 12][tc] + v3.y * s->woutc[kb2 + k + 13][tc]
                    + v3.z * s->woutc[kb2 + k + 14][tc] + v3.w * s->woutc[kb2 + k + 15][tc];
            }
            float accp = (grp ? 0.f : bout_r) + ((a0 + a1) + (a2 + a3));
            if (grp == 1) s->opart[q] = accp;
            __syncthreads();
            if (grp == 0) {
                accp += s->opart[q];
                out_seq[(size_t)(orow0 + tr) * NT * NLAT + (size_t)(sIv - 3) * NLAT +
                        ocol0 + tc] = sigm(accp);
            }
        }

        float C[16][4];
        // job1: L0 = A0 x Wh0
        cpa_wait<2>();
        __syncthreads();
        ZERO_C(C)
        compute_sw(s->Abuf[0][0], s->Abuf[0][1], s->Wbuf[0][0], s->Wbuf[0][1], C, warp, lane);
        __syncthreads();
        stage_sw(s->Wbuf[0][0], g_wht[0] + ((size_t)1 * NG + gc0) * NH + kb, NH);  // Wh1
        stage_sw(s->Wbuf[0][1], g_wht[1] + ((size_t)1 * NG + gc0) * NH + kb, NH);
        cpa_commit();
        epilogue_regs(&g_part3[0][kt][gc0][0], C, warp, lane);
        // job2: L1 += A0 x Wxr0
        cpa_wait<2>();
        __syncthreads();
        ZERO_C(C)
        compute_sw(s->Abuf[0][0], s->Abuf[0][1], s->Wbuf[1][0], s->Wbuf[1][1], C, warp, lane);
        __syncthreads();
        stage_sw(s->Wbuf[1][0], g_wxrt[0] + ((size_t)1 * NG + gc0) * NH + kb, NH); // Wxr1
        stage_sw(s->Wbuf[1][1], g_wxrt[1] + ((size_t)1 * NG + gc0) * NH + kb, NH);
        cpa_commit();
        // job3: L1 += A1 x Wh1
        cpa_wait<1>();
        __syncthreads();
        compute_sw(s->Abuf[1][0], s->Abuf[1][1], s->Wbuf[0][0], s->Wbuf[0][1], C, warp, lane);
        __syncthreads();
        stage_sw(s->Wbuf[0][0], g_wht[0] + ((size_t)2 * NG + gc0) * NH + kb, NH);  // Wh2
        stage_sw(s->Wbuf[0][1], g_wht[1] + ((size_t)2 * NG + gc0) * NH + kb, NH);
        cpa_commit();
        epilogue_regs(&g_part3[1][kt][gc0][0], C, warp, lane);
        // job4: L2 += A1 x Wxr1
        cpa_wait<1>();
        __syncthreads();
        ZERO_C(C)
        compute_sw(s->Abuf[1][0], s->Abuf[1][1], s->Wbuf[1][0], s->Wbuf[1][1], C, warp, lane);
        // job5: L2 += A2 x Wh2
        cpa_wait<0>();
        __syncthreads();
        compute_sw(s->Abuf[2][0], s->Abuf[2][1], s->Wbuf[0][0], s->Wbuf[0][1], C, warp, lane);
        epilogue_regs(&g_part3[2][kt][gc0][0], C, warp, lane);

        grid_barrier2(cta, ++bar_t);   // A: all partials visible

        // --- reduce + cell per active layer ---
#pragma unroll
        for (int l = 0; l < NL; l++) {
            const bool act = (l == 0) ? act0 : (l == 1) ? act1 : act2;
            if (!act) continue;
            const int tL = sIv - l;
            float sum[8];
            if (l == 0) {
#pragma unroll
                for (int gi = 0; gi < 8; gi++)
                    sum[gi] = __ldcg(&g_xproj[((size_t)tL * NG + gcolv[gi]) * NB + rr]);
            } else {
#pragma unroll
                for (int gi = 0; gi < 8; gi++) sum[gi] = 0.f;
            }
#pragma unroll
            for (int k2 = 0; k2 < NKT; k2++)
#pragma unroll
                for (int gi = 0; gi < 8; gi++)
                    sum[gi] += __ldcg(&g_part3[l][k2][gcolv[gi]][rr]);
#pragma unroll
            for (int gi = 0; gi < 8; gi++) {
                int gl = gi * 2 + half;
                s->gex[gl >> 2][rr][gl & 3] = sum[gi];
            }
            __syncthreads();
            if (tid < NB) {
                const int b = tid;
#pragma unroll
                for (int j = 0; j < 4; j++) {
                    float ig = s->gex[0][b][j] + s->bias[l][b][j];
                    float fg = s->gex[1][b][j] + s->bias[l][b][4 + j];
                    float gg = s->gex[2][b][j] + s->bias[l][b][8 + j];
                    float og = s->gex[3][b][j] + s->bias[l][b][12 + j];
                    float c_new = sigm(fg) * s->cst[l][b][j] + sigm(ig) * tanhf(gg);
                    float h_new = sigm(og) * tanhf(c_new);
                    s->cst[l][b][j] = c_new;
                    __nv_bfloat16 hi, lo;
                    split_bf16(h_new, hi, lo);
                    g_hb[wr][0][l][b][hc4 + j] = hi;
                    g_hb[wr][1][l][b][hc4 + j] = lo;
                    if (l == 2) g_h2[b][hc4 + j] = h_new;
                    if (tL == NT - 1)
                        out_hfin[(size_t)l * NB * NH + (size_t)b * NH + hc4 + j] = h_new;
                }
            }
            __syncthreads();
        }

        grid_barrier2(cta, ++bar_t);   // B: all h writes visible
    }

    // ---- final projection (t = NT-1) ----
    {
        const float* hrow = &g_h2[orow0 + tr][0] + (grp << 8);
        const int kb2 = grp << 8;
        float a0 = 0.f, a1 = 0.f;
#pragma unroll
        for (int k = 0; k < 256; k += 8) {
            float4 v0 = __ldcg(reinterpret_cast<const float4*>(hrow + k));
            float4 v1 = __ldcg(reinterpret_cast<const float4*>(hrow + k + 4));
            a0 += v0.x * s->woutc[kb2 + k + 0][tc] + v0.y * s->woutc[kb2 + k + 1][tc]
                + v0.z * s->woutc[kb2 + k + 2][tc] + v0.w * s->woutc[kb2 + k + 3][tc];
            a1 += v1.x * s->woutc[kb2 + k + 4][tc] + v1.y * s->woutc[kb2 + k + 5][tc]
                + v1.z * s->woutc[kb2 + k + 6][tc] + v1.w * s->woutc[kb2 + k + 7][tc];
        }
        float accp = (grp ? 0.f : bout_r) + a0 + a1;
        if (grp == 1) s->opart[q] = accp;
        __syncthreads();
        if (grp == 0) {
            accp += s->opart[q];
            out_seq[(size_t)(orow0 + tr) * NT * NLAT + (size_t)(NT - 1) * NLAT +
                    ocol0 + tc] = sigm(accp);
        }
    }
}

extern "C" void kernel_launch(void* const* d_in, const int* in_sizes, int n_in,
                              void* d_out, int out_size) {
    const float* noise = (const float*)d_in[0];
    const float* h_cpl = (const float*)d_in[1];
    const float* Wx0   = (const float*)d_in[2];
    const float* Wxr   = (const float*)d_in[3];
    const float* Wh    = (const float*)d_in[4];
    const float* Wc    = (const float*)d_in[5];
    const float* bvec  = (const float*)d_in[6];
    const float* Wout  = (const float*)d_in[7];
    const float* bout  = (const float*)d_in[8];
    float* out = (float*)d_out;

    cudaFuncSetAttribute(bilateral_kernel, cudaFuncAttributeMaxDynamicSharedMemorySize,
                         (int)sizeof(Smem));
    bilateral_kernel<<<NCTA, NTHR, sizeof(Smem)>>>(noise, h_cpl, Wx0, Wxr, Wh, Wc,
                                                   bvec, Wout, bout, out);
}

// round 14
// speedup vs baseline: 3.0994x; 1.0109x over previous
#include <cuda_runtime.h>
#include <cuda_bf16.h>
#include <cstdint>

#define NB 128
#define NT 512
#define NDIM 128
#define NH 512
#define NG 2048
#define NLAT 128
#define NL 3
#define NCTA 128
#define NTHR 512
#define NKT 8
#define NCT 16
#define KSL 64

struct __align__(1024) Smem {
    char Abuf[3][2][128 * 128];   // [slice][hi/lo] swizzled 128B-pitch tiles (96KB)
    char Wbuf[2][2][128 * 128];   // [buf][hi/lo] (64KB)
    float bias[NL][NB][16];
    float cst[NL][NB][4];
    float gex[4][NB][5];
    float woutc[NH][8];
    float opart[4][NB];
};

__device__ float g_part3[NL][NKT][NG][NB];             // per-layer k-split partials
__device__ float g_xproj[(size_t)NT * NG * NB];        // precomputed x@Wx0
__device__ float g_h2[NB][NH];
__device__ __nv_bfloat16 g_hb[2][2][NL][NB][NH];       // [pingpong][hi/lo]
__device__ __nv_bfloat16 g_nb[2][NB * NT * NDIM];
__device__ __nv_bfloat16 g_cb[2][NL * NB * NH];
__device__ __nv_bfloat16 g_wx0t[2][NG * NDIM];
__device__ __nv_bfloat16 g_wxrt[2][(NL - 1) * NG * NH];
__device__ __nv_bfloat16 g_wht[2][NL * NG * NH];
__device__ __nv_bfloat16 g_wct[2][NL * NG * NH];
__device__ unsigned g_flags[NCTA][32];                 // 128B-padded flags

__device__ __forceinline__ float sigm(float x) { return 1.f / (1.f + __expf(-x)); }

__device__ __forceinline__ void split_bf16(float v, __nv_bfloat16& hi, __nv_bfloat16& lo) {
    unsigned u = __float_as_uint(v);
    hi = __ushort_as_bfloat16((unsigned short)(u >> 16));
    float hf = __uint_as_float(u & 0xFFFF0000u);
    lo = __float2bfloat16(v - hf);
}

__device__ __forceinline__ uint32_t smem_u32(const void* p) {
    uint32_t a;
    asm("{ .reg .u64 t; cvta.to.shared.u64 t, %1; cvt.u32.u64 %0, t; }" : "=r"(a) : "l"(p));
    return a;
}

__device__ __forceinline__ void cpa16(void* dst, const void* src) {
    unsigned d = (unsigned)__cvta_generic_to_shared(dst);
    asm volatile("cp.async.cg.shared.global [%0], [%1], 16;" :: "r"(d), "l"(src));
}
__device__ __forceinline__ void cpa_commit() {
    asm volatile("cp.async.commit_group;" ::: "memory");
}
template <int N>
__device__ __forceinline__ void cpa_wait() {
    asm volatile("cp.async.wait_group %0;" :: "n"(N) : "memory");
}

__device__ __forceinline__ void ldsm4(unsigned& r0, unsigned& r1, unsigned& r2,
                                      unsigned& r3, unsigned addr) {
    asm volatile("ldmatrix.sync.aligned.m8n8.x4.shared.b16 {%0,%1,%2,%3}, [%4];"
                 : "=r"(r0), "=r"(r1), "=r"(r2), "=r"(r3) : "r"(addr));
}
__device__ __forceinline__ void mma16816(float* c, unsigned a0, unsigned a1, unsigned a2,
                                         unsigned a3, unsigned b0, unsigned b1) {
    asm volatile(
        "mma.sync.aligned.m16n8k16.row.col.f32.bf16.bf16.f32 "
        "{%0,%1,%2,%3}, {%4,%5,%6,%7}, {%8,%9}, {%0,%1,%2,%3};"
        : "+f"(c[0]), "+f"(c[1]), "+f"(c[2]), "+f"(c[3])
        : "r"(a0), "r"(a1), "r"(a2), "r"(a3), "r"(b0), "r"(b1));
}

__device__ __forceinline__ void grid_barrier2(int cta, unsigned target) {
    __syncthreads();
    if (threadIdx.x == 0) {
        __threadfence();
        atomicExch(&g_flags[cta][0], target);
    }
    for (;;) {
        unsigned v = (threadIdx.x < NCTA) ? __ldcg(&g_flags[threadIdx.x][0]) : target;
        if (__syncthreads_count((int)(v < target)) == 0) break;
    }
    __threadfence();
}

// Stage one 128x64 bf16 tile into 128B-pitch swizzled smem (chunk ^= row&7).
__device__ __forceinline__ void stage_sw(char* dst, const __nv_bfloat16* src, int ld) {
    const int tid = threadIdx.x;
#pragma unroll
    for (int it = 0; it < 1024 / NTHR; it++) {
        int idx = it * NTHR + tid;       // 0..1023
        int r = idx >> 3, g = idx & 7;
        cpa16(dst + r * 128 + ((g ^ (r & 7)) << 4), src + (size_t)r * ld + g * 8);
    }
}

// HMMA: C += A * W^T (3-term bf16 split) on swizzled tiles.
// 16 warps: wr2 = warp>>1 (row group of 16), wc2 = warp&1 (64-col half). C[8][4].
__device__ __forceinline__ void compute_sw(const char* Ah, const char* Al,
                                           const char* Wh_, const char* Wl_,
                                           float (*C)[4], int warp, int lane) {
    const int wr2 = warp >> 1, wc2 = warp & 1;
    const int ar = wr2 * 16 + (lane & 15);
    const int ac = lane >> 4;
    const unsigned ah_b = smem_u32(Ah) + ar * 128;
    const unsigned al_b = smem_u32(Al) + ar * 128;
    const int bc = wc2 * 64 + (lane & 7) + ((lane >= 16) ? 8 : 0);
    const int bsel = (lane >> 3) & 1;
    const unsigned bh_b = smem_u32(Wh_) + bc * 128;
    const unsigned bl_b = smem_u32(Wl_) + bc * 128;
    const int asw = ar & 7, bsw = bc & 7;
#pragma unroll
    for (int ks = 0; ks < 4; ks++) {
        const unsigned aoff = (unsigned)(((ks * 2 + ac) ^ asw) << 4);
        const unsigned boff = (unsigned)(((ks * 2 + bsel) ^ bsw) << 4);
        unsigned ah0, ah1, ah2, ah3, al0, al1, al2, al3;
        ldsm4(ah0, ah1, ah2, ah3, ah_b + aoff);
        ldsm4(al0, al1, al2, al3, al_b + aoff);
#pragma unroll
        for (int nt = 0; nt < 4; nt++) {
            unsigned bh0, bh1, bh2, bh3, bl0, bl1, bl2, bl3;
            const unsigned roff = nt * 16 * 128 + boff;
            ldsm4(bh0, bh1, bh2, bh3, bh_b + roff);
            ldsm4(bl0, bl1, bl2, bl3, bl_b + roff);
            mma16816(C[2 * nt],     ah0, ah1, ah2, ah3, bh0, bh1);
            mma16816(C[2 * nt + 1], ah0, ah1, ah2, ah3, bh2, bh3);
            mma16816(C[2 * nt],     ah0, ah1, ah2, ah3, bl0, bl1);
            mma16816(C[2 * nt + 1], ah0, ah1, ah2, ah3, bl2, bl3);
            mma16816(C[2 * nt],     al0, al1, al2, al3, bh0, bh1);
            mma16816(C[2 * nt + 1], al0, al1, al2, al3, bh2, bh3);
        }
    }
}

// Write warp's 16x64 C tile to base[col][NB].
__device__ __forceinline__ void epilogue_regs(float* base, float (*C)[4],
                                              int warp, int lane) {
    const int wr2 = warp >> 1, wc2 = warp & 1;
    const int r0 = wr2 * 16 + (lane >> 2);
    const int c0 = 2 * (lane & 3);
#pragma unroll
    for (int n8 = 0; n8 < 8; n8++) {
        int cb = wc2 * 64 + n8 * 8 + c0;
        base[(size_t)cb * NB + r0] = C[n8][0];
        base[(size_t)(cb + 1) * NB + r0] = C[n8][1];
        base[(size_t)cb * NB + r0 + 8] = C[n8][2];
        base[(size_t)(cb + 1) * NB + r0 + 8] = C[n8][3];
    }
}

#define ZERO_C(C)                      \
    _Pragma("unroll")                  \
    for (int m = 0; m < 8; m++)        \
        _Pragma("unroll")              \
        for (int v = 0; v < 4; v++) (C)[m][v] = 0.f;

__global__ void __launch_bounds__(NTHR, 1)
bilateral_kernel(const float* __restrict__ noise,
                 const float* __restrict__ h_cpl,
                 const float* __restrict__ Wx0,
                 const float* __restrict__ Wxr,
                 const float* __restrict__ Wh,
                 const float* __restrict__ Wc,
                 const float* __restrict__ bvec,
                 const float* __restrict__ Wout,
                 const float* __restrict__ bout,
                 float* __restrict__ out) {
    extern __shared__ char smem_raw[];
    Smem* s = reinterpret_cast<Smem*>(smem_raw);
    const int tid = threadIdx.x;
    const int cta = blockIdx.x;
    const int warp = tid >> 5, lane = tid & 31;
    const int kt = cta >> 4;
    const int ct = cta & 15;
    const int gc0 = ct * 128;
    const int kb = kt * KSL;
    const int hc4 = cta * 4;
    const int half4 = tid >> 7;      // 0..3
    const int rr = tid & 127;

    unsigned bar_t = g_flags[cta][0];

    float* out_seq = out;
    float* out_hfin = out + (size_t)NB * NT * NLAT;

    const int orow0 = (cta >> 4) * 16;
    const int ocol0 = (cta & 15) * 8;
    const int q = tid & 127;
    const int tr = q >> 3, tc = q & 7;
    const float bout_r = bout[ocol0 + tc];

    int gcolv[4];
#pragma unroll
    for (int gi = 0; gi < 4; gi++) {
        int gl = gi * 4 + half4;     // gate=gi, col=half4
        gcolv[gi] = (gl >> 2) * 512 + hc4 + (gl & 3);
    }

    // ---- phase 0: conversions + zero init ----
    for (int i = cta * NTHR + tid; i < NB * NT * NDIM; i += NCTA * NTHR)
        split_bf16(noise[i], g_nb[0][i], g_nb[1][i]);
    for (int i = cta * NTHR + tid; i < NL * NB * NH; i += NCTA * NTHR)
        split_bf16(h_cpl[i], g_cb[0][i], g_cb[1][i]);
    {
        __nv_bfloat16* hz = &g_hb[0][0][0][0][0];
        __nv_bfloat16 z = __float2bfloat16(0.f);
        for (int i = cta * NTHR + tid; i < 2 * 2 * NL * NB * NH; i += NCTA * NTHR) hz[i] = z;
    }
    for (int i = tid; i < NL * NB * 4; i += NTHR) (&s->cst[0][0][0])[i] = 0.f;
    for (int i = tid; i < NH * 8; i += NTHR) {
        int k = i >> 3, c = i & 7;
        s->woutc[k][c] = Wout[(size_t)k * NLAT + ocol0 + c];
    }

    // ---- phase 0b: weight transpose + bf16 split (first 256 threads work) ----
    {
        float (*tile)[33] = reinterpret_cast<float (*)[33]>(&s->Abuf[0][0][0]);
        const int tx = tid & 31, ty = (tid >> 5) & 7;
        const bool tw = (tid < 256);
        for (int idx = cta; idx < 8448; idx += NCTA) {
            const float* src;
            __nv_bfloat16 *dh, *dl;
            int R, t;
            if (idx < 256) {
                src = Wx0; dh = g_wx0t[0]; dl = g_wx0t[1]; R = NDIM; t = idx;
            } else {
                int j = (idx - 256) >> 10;
                t = (idx - 256) & 1023;
                R = NH;
                if (j < 2) {
                    src = Wxr + (size_t)j * NH * NG;
                    dh = g_wxrt[0] + (size_t)j * NG * NH;
                    dl = g_wxrt[1] + (size_t)j * NG * NH;
                } else if (j < 5) {
                    src = Wh + (size_t)(j - 2) * NH * NG;
                    dh = g_wht[0] + (size_t)(j - 2) * NG * NH;
                    dl = g_wht[1] + (size_t)(j - 2) * NG * NH;
                } else {
                    src = Wc + (size_t)(j - 5) * NH * NG;
                    dh = g_wct[0] + (size_t)(j - 5) * NG * NH;
                    dl = g_wct[1] + (size_t)(j - 5) * NG * NH;
                }
            }
            const int tr_ = t / (NG / 32), tc_ = t % (NG / 32);
            const int r0 = tr_ * 32, c0 = tc_ * 32;
            __syncthreads();
            if (tw) {
#pragma unroll
                for (int i = 0; i < 32; i += 8)
                    tile[ty + i][tx] = src[(size_t)(r0 + ty + i) * NG + c0 + tx];
            }
            __syncthreads();
            if (tw) {
#pragma unroll
                for (int i = 0; i < 32; i += 8) {
                    float v = tile[tx][ty + i];
                    __nv_bfloat16 hi, lo;
                    split_bf16(v, hi, lo);
                    size_t o = (size_t)(c0 + ty + i) * R + r0 + tx;
                    dh[o] = hi;
                    dl[o] = lo;
                }
            }
        }
    }
    __syncthreads();
    grid_barrier2(cta, ++bar_t);

    // ---- phase 1: precompute x@Wx0 for all t ----
    for (int idx = cta; idx < NT * NCT; idx += NCTA) {
        const int t = idx >> 4;
        const int gx = (idx & 15) * 128;
        stage_sw(s->Abuf[0][0], g_nb[0] + (size_t)t * NDIM, NT * NDIM);
        stage_sw(s->Abuf[0][1], g_nb[1] + (size_t)t * NDIM, NT * NDIM);
        stage_sw(s->Abuf[1][0], g_nb[0] + (size_t)t * NDIM + 64, NT * NDIM);
        stage_sw(s->Abuf[1][1], g_nb[1] + (size_t)t * NDIM + 64, NT * NDIM);
        stage_sw(s->Wbuf[0][0], g_wx0t[0] + (size_t)gx * NDIM, NDIM);
        stage_sw(s->Wbuf[0][1], g_wx0t[1] + (size_t)gx * NDIM, NDIM);
        stage_sw(s->Wbuf[1][0], g_wx0t[0] + (size_t)gx * NDIM + 64, NDIM);
        stage_sw(s->Wbuf[1][1], g_wx0t[1] + (size_t)gx * NDIM + 64, NDIM);
        cpa_commit();
        float C[8][4];
        ZERO_C(C)
        cpa_wait<0>();
        __syncthreads();
        compute_sw(s->Abuf[0][0], s->Abuf[0][1], s->Wbuf[0][0], s->Wbuf[0][1], C, warp, lane);
        compute_sw(s->Abuf[1][0], s->Abuf[1][1], s->Wbuf[1][0], s->Wbuf[1][1], C, warp, lane);
        epilogue_regs(&g_xproj[((size_t)t * NG + gx) * NB], C, warp, lane);
        __syncthreads();
    }

    // ---- phase 2: bias = h_coupled @ Wc + b ----
    for (int l = 0; l < NL; l++) {
        stage_sw(s->Abuf[0][0], g_cb[0] + (size_t)l * NB * NH + kb, NH);
        stage_sw(s->Abuf[0][1], g_cb[1] + (size_t)l * NB * NH + kb, NH);
        stage_sw(s->Wbuf[0][0], g_wct[0] + ((size_t)l * NG + gc0) * NH + kb, NH);
        stage_sw(s->Wbuf[0][1], g_wct[1] + ((size_t)l * NG + gc0) * NH + kb, NH);
        cpa_commit();
        float C[8][4];
        ZERO_C(C)
        cpa_wait<0>();
        __syncthreads();
        compute_sw(s->Abuf[0][0], s->Abuf[0][1], s->Wbuf[0][0], s->Wbuf[0][1], C, warp, lane);
        epilogue_regs(&g_part3[0][kt][gc0][0], C, warp, lane);
        grid_barrier2(cta, ++bar_t);
#pragma unroll
        for (int gi = 0; gi < 4; gi++) {
            int gl = gi * 4 + half4;
            float sum = 0.f;
#pragma unroll
            for (int k2 = 0; k2 < NKT; k2++) sum += __ldcg(&g_part3[0][k2][gcolv[gi]][rr]);
            s->bias[l][rr][gl] = sum + bvec[l * NG + gcolv[gi]];
        }
        grid_barrier2(cta, ++bar_t);
    }

    // ---- phase 3: wavefront recurrence (interval s computes L0(s), L1(s-1), L2(s-2)) ----
    for (int sIv = 0; sIv < NT + 2; sIv++) {
        const int wr = sIv & 1, rd = wr ^ 1;
        const bool act0 = (sIv < NT);
        const bool act1 = (sIv >= 1 && sIv <= NT);
        const bool act2 = (sIv >= 2 && sIv <= NT + 1);

        // --- top staging: A slices (h written last interval) + first W tiles ---
        stage_sw(s->Abuf[0][0], &g_hb[rd][0][0][0][kb], NH);   // A0 = h[0][s-1]
        stage_sw(s->Abuf[0][1], &g_hb[rd][1][0][0][kb], NH);
        cpa_commit();                                          // [A0]
        stage_sw(s->Wbuf[0][0], g_wht[0] + (size_t)gc0 * NH + kb, NH);   // Wh0
        stage_sw(s->Wbuf[0][1], g_wht[1] + (size_t)gc0 * NH + kb, NH);
        cpa_commit();                                          // [Wh0]
        stage_sw(s->Wbuf[1][0], g_wxrt[0] + (size_t)gc0 * NH + kb, NH);  // Wxr0
        stage_sw(s->Wbuf[1][1], g_wxrt[1] + (size_t)gc0 * NH + kb, NH);
        cpa_commit();                                          // [Wxr0]
        stage_sw(s->Abuf[1][0], &g_hb[rd][0][1][0][kb], NH);   // A1 = h[1][s-2]
        stage_sw(s->Abuf[1][1], &g_hb[rd][1][1][0][kb], NH);
        stage_sw(s->Abuf[2][0], &g_hb[rd][0][2][0][kb], NH);   // A2 = h[2][s-3]
        stage_sw(s->Abuf[2][1], &g_hb[rd][1][2][0][kb], NH);
        cpa_commit();                                          // [A1A2]

        // --- projection for t = sIv-3 (overlaps staging), 4-way K split ---
        if (sIv >= 3) {
            const float* hrow = &g_h2[orow0 + tr][0] + (half4 << 7);
            const int kb2 = half4 << 7;
            float a0 = 0.f, a1 = 0.f;
#pragma unroll
            for (int k = 0; k < 128; k += 8) {
                float4 v0 = __ldcg(reinterpret_cast<const float4*>(hrow + k));
                float4 v1 = __ldcg(reinterpret_cast<const float4*>(hrow + k + 4));
                a0 += v0.x * s->woutc[kb2 + k + 0][tc] + v0.y * s->woutc[kb2 + k + 1][tc]
                    + v0.z * s->woutc[kb2 + k + 2][tc] + v0.w * s->woutc[kb2 + k + 3][tc];
                a1 += v1.x * s->woutc[kb2 + k + 4][tc] + v1.y * s->woutc[kb2 + k + 5][tc]
                    + v1.z * s->woutc[kb2 + k + 6][tc] + v1.w * s->woutc[kb2 + k + 7][tc];
            }
            float accp = (half4 == 0 ? bout_r : 0.f) + a0 + a1;
            if (half4 > 0) s->opart[half4][q] = accp;
            __syncthreads();
            if (half4 == 0) {
                accp += s->opart[1][q] + s->opart[2][q] + s->opart[3][q];
                out_seq[(size_t)(orow0 + tr) * NT * NLAT + (size_t)(sIv - 3) * NLAT +
                        ocol0 + tc] = sigm(accp);
            }
        }

        float C[8][4];
        // job1: L0 = A0 x Wh0
        cpa_wait<2>();
        __syncthreads();
        ZERO_C(C)
        compute_sw(s->Abuf[0][0], s->Abuf[0][1], s->Wbuf[0][0], s->Wbuf[0][1], C, warp, lane);
        __syncthreads();
        stage_sw(s->Wbuf[0][0], g_wht[0] + ((size_t)1 * NG + gc0) * NH + kb, NH);  // Wh1
        stage_sw(s->Wbuf[0][1], g_wht[1] + ((size_t)1 * NG + gc0) * NH + kb, NH);
        cpa_commit();
        epilogue_regs(&g_part3[0][kt][gc0][0], C, warp, lane);
        // job2: L1 += A0 x Wxr0
        cpa_wait<2>();
        __syncthreads();
        ZERO_C(C)
        compute_sw(s->Abuf[0][0], s->Abuf[0][1], s->Wbuf[1][0], s->Wbuf[1][1], C, warp, lane);
        __syncthreads();
        stage_sw(s->Wbuf[1][0], g_wxrt[0] + ((size_t)1 * NG + gc0) * NH + kb, NH); // Wxr1
        stage_sw(s->Wbuf[1][1], g_wxrt[1] + ((size_t)1 * NG + gc0) * NH + kb, NH);
        cpa_commit();
        // job3: L1 += A1 x Wh1
        cpa_wait<1>();
        __syncthreads();
        compute_sw(s->Abuf[1][0], s->Abuf[1][1], s->Wbuf[0][0], s->Wbuf[0][1], C, warp, lane);
        __syncthreads();
        stage_sw(s->Wbuf[0][0], g_wht[0] + ((size_t)2 * NG + gc0) * NH + kb, NH);  // Wh2
        stage_sw(s->Wbuf[0][1], g_wht[1] + ((size_t)2 * NG + gc0) * NH + kb, NH);
        cpa_commit();
        epilogue_regs(&g_part3[1][kt][gc0][0], C, warp, lane);
        // job4: L2 += A1 x Wxr1
        cpa_wait<1>();
        __syncthreads();
        ZERO_C(C)
        compute_sw(s->Abuf[1][0], s->Abuf[1][1], s->Wbuf[1][0], s->Wbuf[1][1], C, warp, lane);
        // job5: L2 += A2 x Wh2
        cpa_wait<0>();
        __syncthreads();
        compute_sw(s->Abuf[2][0], s->Abuf[2][1], s->Wbuf[0][0], s->Wbuf[0][1], C, warp, lane);
        epilogue_regs(&g_part3[2][kt][gc0][0], C, warp, lane);

        grid_barrier2(cta, ++bar_t);   // A: all partials visible

        // --- reduce + cell per active layer ---
#pragma unroll
        for (int l = 0; l < NL; l++) {
            const bool act = (l == 0) ? act0 : (l == 1) ? act1 : act2;
            if (!act) continue;
            const int tL = sIv - l;
            float sum[4];
            if (l == 0) {
#pragma unroll
                for (int gi = 0; gi < 4; gi++)
                    sum[gi] = __ldcg(&g_xproj[((size_t)tL * NG + gcolv[gi]) * NB + rr]);
            } else {
#pragma unroll
                for (int gi = 0; gi < 4; gi++) sum[gi] = 0.f;
            }
#pragma unroll
            for (int k2 = 0; k2 < NKT; k2++)
#pragma unroll
                for (int gi = 0; gi < 4; gi++)
                    sum[gi] += __ldcg(&g_part3[l][k2][gcolv[gi]][rr]);
#pragma unroll
            for (int gi = 0; gi < 4; gi++) {
                int gl = gi * 4 + half4;
                s->gex[gl >> 2][rr][gl & 3] = sum[gi];
            }
            __syncthreads();
            if (tid < NB) {
                const int b = tid;
#pragma unroll
                for (int j = 0; j < 4; j++) {
                    float ig = s->gex[0][b][j] + s->bias[l][b][j];
                    float fg = s->gex[1][b][j] + s->bias[l][b][4 + j];
                    float gg = s->gex[2][b][j] + s->bias[l][b][8 + j];
                    float og = s->gex[3][b][j] + s->bias[l][b][12 + j];
                    float c_new = sigm(fg) * s->cst[l][b][j] + sigm(ig) * tanhf(gg);
                    float h_new = sigm(og) * tanhf(c_new);
                    s->cst[l][b][j] = c_new;
                    __nv_bfloat16 hi, lo;
                    split_bf16(h_new, hi, lo);
                    g_hb[wr][0][l][b][hc4 + j] = hi;
                    g_hb[wr][1][l][b][hc4 + j] = lo;
                    if (l == 2) g_h2[b][hc4 + j] = h_new;
                    if (tL == NT - 1)
                        out_hfin[(size_t)l * NB * NH + (size_t)b * NH + hc4 + j] = h_new;
                }
            }
            __syncthreads();
        }

        grid_barrier2(cta, ++bar_t);   // B: all h writes visible
    }

    // ---- final projection (t = NT-1) ----
    {
        const float* hrow = &g_h2[orow0 + tr][0] + (half4 << 7);
        const int kb2 = half4 << 7;
        float a0 = 0.f, a1 = 0.f;
#pragma unroll
        for (int k = 0; k < 128; k += 8) {
            float4 v0 = __ldcg(reinterpret_cast<const float4*>(hrow + k));
            float4 v1 = __ldcg(reinterpret_cast<const float4*>(hrow + k + 4));
            a0 += v0.x * s->woutc[kb2 + k + 0][tc] + v0.y * s->woutc[kb2 + k + 1][tc]
                + v0.z * s->woutc[kb2 + k + 2][tc] + v0.w * s->woutc[kb2 + k + 3][tc];
            a1 += v1.x * s->woutc[kb2 + k + 4][tc] + v1.y * s->woutc[kb2 + k + 5][tc]
                + v1.z * s->woutc[kb2 + k + 6][tc] + v1.w * s->woutc[kb2 + k + 7][tc];
        }
        float accp = (half4 == 0 ? bout_r : 0.f) + a0 + a1;
        if (half4 > 0) s->opart[half4][q] = accp;
        __syncthreads();
        if (half4 == 0) {
            accp += s->opart[1][q] + s->opart[2][q] + s->opart[3][q];
            out_seq[(size_t)(orow0 + tr) * NT * NLAT + (size_t)(NT - 1) * NLAT +
                    ocol0 + tc] = sigm(accp);
        }
    }
}

extern "C" void kernel_launch(void* const* d_in, const int* in_sizes, int n_in,
                              void* d_out, int out_size) {
    const float* noise = (const float*)d_in[0];
    const float* h_cpl = (const float*)d_in[1];
    const float* Wx0   = (const float*)d_in[2];
    const float* Wxr   = (const float*)d_in[3];
    const float* Wh    = (const float*)d_in[4];
    const float* Wc    = (const float*)d_in[5];
    const float* bvec  = (const float*)d_in[6];
    const float* Wout  = (const float*)d_in[7];
    const float* bout  = (const float*)d_in[8];
    float* out = (float*)d_out;

    cudaFuncSetAttribute(bilateral_kernel, cudaFuncAttributeMaxDynamicSharedMemorySize,
                         (int)sizeof(Smem));
    bilateral_kernel<<<NCTA, NTHR, sizeof(Smem)>>>(noise, h_cpl, Wx0, Wxr, Wh, Wc,
                                                   bvec, Wout, bout, out);
}

// round 16
// speedup vs baseline: 3.1179x; 1.0060x over previous
#include <cuda_runtime.h>
#include <cuda_bf16.h>
#include <cstdint>

#define NB 128
#define NT 512
#define NDIM 128
#define NH 512
#define NG 2048
#define NLAT 128
#define NL 3
#define NCTA 128
#define NTHR 512
#define NKT 8
#define NCT 16
#define KSL 64

// Resident W slots: 0=Wh0 1=Wh1 2=Wh2 3=Wxr0 4=Wxr1
struct __align__(1024) Smem {
    char W[5][2][16384];          // resident weight tiles (160KB)
    char A[2][16384];             // A slice hi/lo (32KB)
    float cst[NL][NB][4];         // 6KB
    float gex[4][NB][5];          // 10KB
    float woutc[NH][8];           // 16KB
    float opart[4][NB];           // 2KB
};                                 // total 231,424 B

__device__ float g_part3[NL][NKT][NG][NB];
__device__ float g_bias[NL][NG][NB];                   // bias, [layer][GLOBAL gatecol][row]
__device__ float g_xproj[(size_t)NT * NG * NB];
__device__ float g_h2[NB][NH];
__device__ __nv_bfloat16 g_hb[2][2][NL][NB][NH];
__device__ __nv_bfloat16 g_nb[2][NB * NT * NDIM];
__device__ __nv_bfloat16 g_cb[2][NL * NB * NH];
__device__ __nv_bfloat16 g_wx0t[2][NG * NDIM];
__device__ __nv_bfloat16 g_wxrt[2][(NL - 1) * NG * NH];
__device__ __nv_bfloat16 g_wht[2][NL * NG * NH];
__device__ __nv_bfloat16 g_wct[2][NL * NG * NH];
__device__ unsigned g_flags[NCTA][32];

__device__ __forceinline__ float sigm(float x) { return 1.f / (1.f + __expf(-x)); }

__device__ __forceinline__ void split_bf16(float v, __nv_bfloat16& hi, __nv_bfloat16& lo) {
    unsigned u = __float_as_uint(v);
    hi = __ushort_as_bfloat16((unsigned short)(u >> 16));
    float hf = __uint_as_float(u & 0xFFFF0000u);
    lo = __float2bfloat16(v - hf);
}

__device__ __forceinline__ uint32_t smem_u32(const void* p) {
    uint32_t a;
    asm("{ .reg .u64 t; cvta.to.shared.u64 t, %1; cvt.u32.u64 %0, t; }" : "=r"(a) : "l"(p));
    return a;
}

__device__ __forceinline__ void cpa16(void* dst, const void* src) {
    unsigned d = (unsigned)__cvta_generic_to_shared(dst);
    asm volatile("cp.async.cg.shared.global [%0], [%1], 16;" :: "r"(d), "l"(src));
}
__device__ __forceinline__ void cpa_commit() {
    asm volatile("cp.async.commit_group;" ::: "memory");
}
template <int N>
__device__ __forceinline__ void cpa_wait() {
    asm volatile("cp.async.wait_group %0;" :: "n"(N) : "memory");
}

__device__ __forceinline__ void ldsm4(unsigned& r0, unsigned& r1, unsigned& r2,
                                      unsigned& r3, unsigned addr) {
    asm volatile("ldmatrix.sync.aligned.m8n8.x4.shared.b16 {%0,%1,%2,%3}, [%4];"
                 : "=r"(r0), "=r"(r1), "=r"(r2), "=r"(r3) : "r"(addr));
}
__device__ __forceinline__ void mma16816(float* c, unsigned a0, unsigned a1, unsigned a2,
                                         unsigned a3, unsigned b0, unsigned b1) {
    asm volatile(
        "mma.sync.aligned.m16n8k16.row.col.f32.bf16.bf16.f32 "
        "{%0,%1,%2,%3}, {%4,%5,%6,%7}, {%8,%9}, {%0,%1,%2,%3};"
        : "+f"(c[0]), "+f"(c[1]), "+f"(c[2]), "+f"(c[3])
        : "r"(a0), "r"(a1), "r"(a2), "r"(a3), "r"(b0), "r"(b1));
}

__device__ __forceinline__ void grid_barrier2(int cta, unsigned target) {
    __syncthreads();
    if (threadIdx.x == 0) {
        __threadfence();
        atomicExch(&g_flags[cta][0], target);
    }
    for (;;) {
        unsigned v = (threadIdx.x < NCTA) ? __ldcg(&g_flags[threadIdx.x][0]) : target;
        if (__syncthreads_count((int)(v < target)) == 0) break;
    }
    __threadfence();
}

// Stage one 128x64 bf16 tile into 128B-pitch swizzled smem (chunk ^= row&7).
__device__ __forceinline__ void stage_sw(char* dst, const __nv_bfloat16* src, int ld) {
    const int tid = threadIdx.x;
#pragma unroll
    for (int it = 0; it < 1024 / NTHR; it++) {
        int idx = it * NTHR + tid;
        int r = idx >> 3, g = idx & 7;
        cpa16(dst + r * 128 + ((g ^ (r & 7)) << 4), src + (size_t)r * ld + g * 8);
    }
}

// HMMA: C += A * W^T (3-term bf16 split). 16 warps: row-group x col-half. C[8][4].
__device__ __forceinline__ void compute_sw(const char* Ah, const char* Al,
                                           const char* Wh_, const char* Wl_,
                                           float (*C)[4], int warp, int lane) {
    const int wr2 = warp >> 1, wc2 = warp & 1;
    const int ar = wr2 * 16 + (lane & 15);
    const int ac = lane >> 4;
    const unsigned ah_b = smem_u32(Ah) + ar * 128;
    const unsigned al_b = smem_u32(Al) + ar * 128;
    const int bc = wc2 * 64 + (lane & 7) + ((lane >= 16) ? 8 : 0);
    const int bsel = (lane >> 3) & 1;
    const unsigned bh_b = smem_u32(Wh_) + bc * 128;
    const unsigned bl_b = smem_u32(Wl_) + bc * 128;
    const int asw = ar & 7, bsw = bc & 7;
#pragma unroll
    for (int ks = 0; ks < 4; ks++) {
        const unsigned aoff = (unsigned)(((ks * 2 + ac) ^ asw) << 4);
        const unsigned boff = (unsigned)(((ks * 2 + bsel) ^ bsw) << 4);
        unsigned ah0, ah1, ah2, ah3, al0, al1, al2, al3;
        ldsm4(ah0, ah1, ah2, ah3, ah_b + aoff);
        ldsm4(al0, al1, al2, al3, al_b + aoff);
#pragma unroll
        for (int nt = 0; nt < 4; nt++) {
            unsigned bh0, bh1, bh2, bh3, bl0, bl1, bl2, bl3;
            const unsigned roff = nt * 16 * 128 + boff;
            ldsm4(bh0, bh1, bh2, bh3, bh_b + roff);
            ldsm4(bl0, bl1, bl2, bl3, bl_b + roff);
            mma16816(C[2 * nt],     ah0, ah1, ah2, ah3, bh0, bh1);
            mma16816(C[2 * nt + 1], ah0, ah1, ah2, ah3, bh2, bh3);
            mma16816(C[2 * nt],     ah0, ah1, ah2, ah3, bl0, bl1);
            mma16816(C[2 * nt + 1], ah0, ah1, ah2, ah3, bl2, bl3);
            mma16816(C[2 * nt],     al0, al1, al2, al3, bh0, bh1);
            mma16816(C[2 * nt + 1], al0, al1, al2, al3, bh2, bh3);
        }
    }
}

__device__ __forceinline__ void epilogue_regs(float* base, float (*C)[4],
                                              int warp, int lane) {
    const int wr2 = warp >> 1, wc2 = warp & 1;
    const int r0 = wr2 * 16 + (lane >> 2);
    const int c0 = 2 * (lane & 3);
#pragma unroll
    for (int n8 = 0; n8 < 8; n8++) {
        int cb = wc2 * 64 + n8 * 8 + c0;
        base[(size_t)cb * NB + r0] = C[n8][0];
        base[(size_t)(cb + 1) * NB + r0] = C[n8][1];
        base[(size_t)cb * NB + r0 + 8] = C[n8][2];
        base[(size_t)(cb + 1) * NB + r0 + 8] = C[n8][3];
    }
}

#define ZERO_C(C)                      \
    _Pragma("unroll")                  \
    for (int m = 0; m < 8; m++)        \
        _Pragma("unroll")              \
        for (int v = 0; v < 4; v++) (C)[m][v] = 0.f;

__global__ void __launch_bounds__(NTHR, 1)
bilateral_kernel(const float* __restrict__ noise,
                 const float* __restrict__ h_cpl,
                 const float* __restrict__ Wx0,
                 const float* __restrict__ Wxr,
                 const float* __restrict__ Wh,
                 const float* __restrict__ Wc,
                 const float* __restrict__ bvec,
                 const float* __restrict__ Wout,
                 const float* __restrict__ bout,
                 float* __restrict__ out) {
    extern __shared__ char smem_raw[];
    Smem* s = reinterpret_cast<Smem*>(smem_raw);
    const int tid = threadIdx.x;
    const int cta = blockIdx.x;
    const int warp = tid >> 5, lane = tid & 31;
    const int kt = cta >> 4;
    const int ct = cta & 15;
    const int gc0 = ct * 128;
    const int kb = kt * KSL;
    const int hc4 = cta * 4;
    const int half4 = tid >> 7;      // 0..3
    const int rr = tid & 127;

    unsigned bar_t = g_flags[cta][0];

    float* out_seq = out;
    float* out_hfin = out + (size_t)NB * NT * NLAT;

    const int orow0 = (cta >> 4) * 16;
    const int ocol0 = (cta & 15) * 8;
    const int q = tid & 127;
    const int tr = q >> 3, tc = q & 7;
    const float bout_r = bout[ocol0 + tc];

    int gcolv[4], glv[4];
#pragma unroll
    for (int gi = 0; gi < 4; gi++) {
        int gl = gi * 4 + half4;
        glv[gi] = gl;
        gcolv[gi] = (gl >> 2) * 512 + hc4 + (gl & 3);
    }

    // ---- phase 0: conversions + zero init ----
    for (int i = cta * NTHR + tid; i < NB * NT * NDIM; i += NCTA * NTHR)
        split_bf16(noise[i], g_nb[0][i], g_nb[1][i]);
    for (int i = cta * NTHR + tid; i < NL * NB * NH; i += NCTA * NTHR)
        split_bf16(h_cpl[i], g_cb[0][i], g_cb[1][i]);
    {
        __nv_bfloat16* hz = &g_hb[0][0][0][0][0];
        __nv_bfloat16 z = __float2bfloat16(0.f);
        for (int i = cta * NTHR + tid; i < 2 * 2 * NL * NB * NH; i += NCTA * NTHR) hz[i] = z;
    }
    for (int i = tid; i < NL * NB * 4; i += NTHR) (&s->cst[0][0][0])[i] = 0.f;
    for (int i = tid; i < NH * 8; i += NTHR) {
        int k = i >> 3, c = i & 7;
        s->woutc[k][c] = Wout[(size_t)k * NLAT + ocol0 + c];
    }

    // ---- phase 0b: weight transpose + bf16 split (first 256 threads) ----
    {
        float (*tile)[33] = reinterpret_cast<float (*)[33]>(&s->W[0][0][0]);
        const int tx = tid & 31, ty = (tid >> 5) & 7;
        const bool tw = (tid < 256);
        for (int idx = cta; idx < 8448; idx += NCTA) {
            const float* src;
            __nv_bfloat16 *dh, *dl;
            int R, t;
            if (idx < 256) {
                src = Wx0; dh = g_wx0t[0]; dl = g_wx0t[1]; R = NDIM; t = idx;
            } else {
                int j = (idx - 256) >> 10;
                t = (idx - 256) & 1023;
                R = NH;
                if (j < 2) {
                    src = Wxr + (size_t)j * NH * NG;
                    dh = g_wxrt[0] + (size_t)j * NG * NH;
                    dl = g_wxrt[1] + (size_t)j * NG * NH;
                } else if (j < 5) {
                    src = Wh + (size_t)(j - 2) * NH * NG;
                    dh = g_wht[0] + (size_t)(j - 2) * NG * NH;
                    dl = g_wht[1] + (size_t)(j - 2) * NG * NH;
                } else {
                    src = Wc + (size_t)(j - 5) * NH * NG;
                    dh = g_wct[0] + (size_t)(j - 5) * NG * NH;
                    dl = g_wct[1] + (size_t)(j - 5) * NG * NH;
                }
            }
            const int tr_ = t / (NG / 32), tc_ = t % (NG / 32);
            const int r0 = tr_ * 32, c0 = tc_ * 32;
            __syncthreads();
            if (tw) {
#pragma unroll
                for (int i = 0; i < 32; i += 8)
                    tile[ty + i][tx] = src[(size_t)(r0 + ty + i) * NG + c0 + tx];
            }
            __syncthreads();
            if (tw) {
#pragma unroll
                for (int i = 0; i < 32; i += 8) {
                    float v = tile[tx][ty + i];
                    __nv_bfloat16 hi, lo;
                    split_bf16(v, hi, lo);
                    size_t o = (size_t)(c0 + ty + i) * R + r0 + tx;
                    dh[o] = hi;
                    dl[o] = lo;
                }
            }
        }
    }
    __syncthreads();
    grid_barrier2(cta, ++bar_t);

    // ---- phase 1: precompute x@Wx0 for all t (W slots used as scratch) ----
    for (int idx = cta; idx < NT * NCT; idx += NCTA) {
        const int t = idx >> 4;
        const int gx = (idx & 15) * 128;
        stage_sw(s->A[0],    g_nb[0] + (size_t)t * NDIM, NT * NDIM);
        stage_sw(s->A[1],    g_nb[1] + (size_t)t * NDIM, NT * NDIM);
        stage_sw(s->W[1][0], g_nb[0] + (size_t)t * NDIM + 64, NT * NDIM);
        stage_sw(s->W[1][1], g_nb[1] + (size_t)t * NDIM + 64, NT * NDIM);
        stage_sw(s->W[0][0], g_wx0t[0] + (size_t)gx * NDIM, NDIM);
        stage_sw(s->W[0][1], g_wx0t[1] + (size_t)gx * NDIM, NDIM);
        stage_sw(s->W[2][0], g_wx0t[0] + (size_t)gx * NDIM + 64, NDIM);
        stage_sw(s->W[2][1], g_wx0t[1] + (size_t)gx * NDIM + 64, NDIM);
        cpa_commit();
        float C[8][4];
        ZERO_C(C)
        cpa_wait<0>();
        __syncthreads();
        compute_sw(s->A[0], s->A[1], s->W[0][0], s->W[0][1], C, warp, lane);
        compute_sw(s->W[1][0], s->W[1][1], s->W[2][0], s->W[2][1], C, warp, lane);
        epilogue_regs(&g_xproj[((size_t)t * NG + gx) * NB], C, warp, lane);
        __syncthreads();
    }

    // ---- phase 2: bias = h_coupled @ Wc + b -> g_bias (GLOBAL gate-col index) ----
    for (int l = 0; l < NL; l++) {
        stage_sw(s->A[0],    g_cb[0] + (size_t)l * NB * NH + kb, NH);
        stage_sw(s->A[1],    g_cb[1] + (size_t)l * NB * NH + kb, NH);
        stage_sw(s->W[0][0], g_wct[0] + ((size_t)l * NG + gc0) * NH + kb, NH);
        stage_sw(s->W[0][1], g_wct[1] + ((size_t)l * NG + gc0) * NH + kb, NH);
        cpa_commit();
        float C[8][4];
        ZERO_C(C)
        cpa_wait<0>();
        __syncthreads();
        compute_sw(s->A[0], s->A[1], s->W[0][0], s->W[0][1], C, warp, lane);
        epilogue_regs(&g_part3[0][kt][gc0][0], C, warp, lane);
        grid_barrier2(cta, ++bar_t);
#pragma unroll
        for (int gi = 0; gi < 4; gi++) {
            float sum = 0.f;
#pragma unroll
            for (int k2 = 0; k2 < NKT; k2++) sum += __ldcg(&g_part3[0][k2][gcolv[gi]][rr]);
            g_bias[l][gcolv[gi]][rr] = sum + bvec[l * NG + gcolv[gi]];
        }
        grid_barrier2(cta, ++bar_t);
    }

    // ---- load resident W tiles (once) ----
    stage_sw(s->W[0][0], g_wht[0] + (size_t)gc0 * NH + kb, NH);
    stage_sw(s->W[0][1], g_wht[1] + (size_t)gc0 * NH + kb, NH);
    stage_sw(s->W[1][0], g_wht[0] + ((size_t)1 * NG + gc0) * NH + kb, NH);
    stage_sw(s->W[1][1], g_wht[1] + ((size_t)1 * NG + gc0) * NH + kb, NH);
    stage_sw(s->W[2][0], g_wht[0] + ((size_t)2 * NG + gc0) * NH + kb, NH);
    stage_sw(s->W[2][1], g_wht[1] + ((size_t)2 * NG + gc0) * NH + kb, NH);
    stage_sw(s->W[3][0], g_wxrt[0] + (size_t)gc0 * NH + kb, NH);
    stage_sw(s->W[3][1], g_wxrt[1] + (size_t)gc0 * NH + kb, NH);
    stage_sw(s->W[4][0], g_wxrt[0] + ((size_t)1 * NG + gc0) * NH + kb, NH);
    stage_sw(s->W[4][1], g_wxrt[1] + ((size_t)1 * NG + gc0) * NH + kb, NH);
    cpa_commit();
    cpa_wait<0>();
    __syncthreads();

    // ---- phase 3: wavefront recurrence ----
    for (int sIv = 0; sIv < NT + 2; sIv++) {
        const int wr = sIv & 1, rd = wr ^ 1;
        const bool act0 = (sIv < NT);
        const bool act1 = (sIv >= 1 && sIv <= NT);
        const bool act2 = (sIv >= 2 && sIv <= NT + 1);

        // stage A0 = h[0][s-1]
        stage_sw(s->A[0], &g_hb[rd][0][0][0][kb], NH);
        stage_sw(s->A[1], &g_hb[rd][1][0][0][kb], NH);
        cpa_commit();

        // projection for t = sIv-3 (overlaps A0 staging)
        if (sIv >= 3) {
            const float* hrow = &g_h2[orow0 + tr][0] + (half4 << 7);
            const int kb2 = half4 << 7;
            float a0 = 0.f, a1 = 0.f;
#pragma unroll
            for (int k = 0; k < 128; k += 8) {
                float4 v0 = __ldcg(reinterpret_cast<const float4*>(hrow + k));
                float4 v1 = __ldcg(reinterpret_cast<const float4*>(hrow + k + 4));
                a0 += v0.x * s->woutc[kb2 + k + 0][tc] + v0.y * s->woutc[kb2 + k + 1][tc]
                    + v0.z * s->woutc[kb2 + k + 2][tc] + v0.w * s->woutc[kb2 + k + 3][tc];
                a1 += v1.x * s->woutc[kb2 + k + 4][tc] + v1.y * s->woutc[kb2 + k + 5][tc]
                    + v1.z * s->woutc[kb2 + k + 6][tc] + v1.w * s->woutc[kb2 + k + 7][tc];
            }
            float accp = (half4 == 0 ? bout_r : 0.f) + a0 + a1;
            if (half4 > 0) s->opart[half4][q] = accp;
            __syncthreads();
            if (half4 == 0) {
                accp += s->opart[1][q] + s->opart[2][q] + s->opart[3][q];
                out_seq[(size_t)(orow0 + tr) * NT * NLAT + (size_t)(sIv - 3) * NLAT +
                        ocol0 + tc] = sigm(accp);
            }
        }

        float C[8][4];
        // job1: L0 = A0 x Wh0(res)
        cpa_wait<0>();
        __syncthreads();
        ZERO_C(C)
        compute_sw(s->A[0], s->A[1], s->W[0][0], s->W[0][1], C, warp, lane);
        epilogue_regs(&g_part3[0][kt][gc0][0], C, warp, lane);
        // job2: L1 = A0 x Wxr0(res)   (C kept for job3)
        ZERO_C(C)
        compute_sw(s->A[0], s->A[1], s->W[3][0], s->W[3][1], C, warp, lane);
        __syncthreads();                       // all warps done with A0
        // stage A1 = h[1][s-2]
        stage_sw(s->A[0], &g_hb[rd][0][1][0][kb], NH);
        stage_sw(s->A[1], &g_hb[rd][1][1][0][kb], NH);
        cpa_commit();
        cpa_wait<0>();
        __syncthreads();
        // job3: L1 += A1 x Wh1(res)
        compute_sw(s->A[0], s->A[1], s->W[1][0], s->W[1][1], C, warp, lane);
        epilogue_regs(&g_part3[1][kt][gc0][0], C, warp, lane);
        // job4: L2 = A1 x Wxr1(res)   (C kept for job5)
        ZERO_C(C)
        compute_sw(s->A[0], s->A[1], s->W[4][0], s->W[4][1], C, warp, lane);
        __syncthreads();                       // all warps done with A1
        // stage A2 = h[2][s-3]
        stage_sw(s->A[0], &g_hb[rd][0][2][0][kb], NH);
        stage_sw(s->A[1], &g_hb[rd][1][2][0][kb], NH);
        cpa_commit();
        cpa_wait<0>();
        __syncthreads();
        // job5: L2 += A2 x Wh2(res)
        compute_sw(s->A[0], s->A[1], s->W[2][0], s->W[2][1], C, warp, lane);
        epilogue_regs(&g_part3[2][kt][gc0][0], C, warp, lane);

        grid_barrier2(cta, ++bar_t);   // A: all partials visible

        // --- reduce (+bias +xproj) + cell per active layer ---
#pragma unroll
        for (int l = 0; l < NL; l++) {
            const bool act = (l == 0) ? act0 : (l == 1) ? act1 : act2;
            if (!act) continue;
            const int tL = sIv - l;
            float sum[4];
#pragma unroll
            for (int gi = 0; gi < 4; gi++)
                sum[gi] = __ldcg(&g_bias[l][gcolv[gi]][rr]);
            if (l == 0) {
#pragma unroll
                for (int gi = 0; gi < 4; gi++)
                    sum[gi] += __ldcg(&g_xproj[((size_t)tL * NG + gcolv[gi]) * NB + rr]);
            }
#pragma unroll
            for (int k2 = 0; k2 < NKT; k2++)
#pragma unroll
                for (int gi = 0; gi < 4; gi++)
                    sum[gi] += __ldcg(&g_part3[l][k2][gcolv[gi]][rr]);
#pragma unroll
            for (int gi = 0; gi < 4; gi++) {
                int gl = glv[gi];
                s->gex[gl >> 2][rr][gl & 3] = sum[gi];
            }
            __syncthreads();
            if (tid < NB) {
                const int b = tid;
#pragma unroll
                for (int j = 0; j < 4; j++) {
                    float ig = s->gex[0][b][j];
                    float fg = s->gex[1][b][j];
                    float gg = s->gex[2][b][j];
                    float og = s->gex[3][b][j];
                    float c_new = sigm(fg) * s->cst[l][b][j] + sigm(ig) * tanhf(gg);
                    float h_new = sigm(og) * tanhf(c_new);
                    s->cst[l][b][j] = c_new;
                    __nv_bfloat16 hi, lo;
                    split_bf16(h_new, hi, lo);
                    g_hb[wr][0][l][b][hc4 + j] = hi;
                    g_hb[wr][1][l][b][hc4 + j] = lo;
                    if (l == 2) g_h2[b][hc4 + j] = h_new;
                    if (tL == NT - 1)
                        out_hfin[(size_t)l * NB * NH + (size_t)b * NH + hc4 + j] = h_new;
                }
            }
            __syncthreads();
        }

        grid_barrier2(cta, ++bar_t);   // B: all h writes visible
    }

    // ---- final projection (t = NT-1) ----
    {
        const float* hrow = &g_h2[orow0 + tr][0] + (half4 << 7);
        const int kb2 = half4 << 7;
        float a0 = 0.f, a1 = 0.f;
#pragma unroll
        for (int k = 0; k < 128; k += 8) {
            float4 v0 = __ldcg(reinterpret_cast<const float4*>(hrow + k));
            float4 v1 = __ldcg(reinterpret_cast<const float4*>(hrow + k + 4));
            a0 += v0.x * s->woutc[kb2 + k + 0][tc] + v0.y * s->woutc[kb2 + k + 1][tc]
                + v0.z * s->woutc[kb2 + k + 2][tc] + v0.w * s->woutc[kb2 + k + 3][tc];
            a1 += v1.x * s->woutc[kb2 + k + 4][tc] + v1.y * s->woutc[kb2 + k + 5][tc]
                + v1.z * s->woutc[kb2 + k + 6][tc] + v1.w * s->woutc[kb2 + k + 7][tc];
        }
        float accp = (half4 == 0 ? bout_r : 0.f) + a0 + a1;
        if (half4 > 0) s->opart[half4][q] = accp;
        __syncthreads();
        if (half4 == 0) {
            accp += s->opart[1][q] + s->opart[2][q] + s->opart[3][q];
            out_seq[(size_t)(orow0 + tr) * NT * NLAT + (size_t)(NT - 1) * NLAT +
                    ocol0 + tc] = sigm(accp);
        }
    }
}

extern "C" void kernel_launch(void* const* d_in, const int* in_sizes, int n_in,
                              void* d_out, int out_size) {
    const float* noise = (const float*)d_in[0];
    const float* h_cpl = (const float*)d_in[1];
    const float* Wx0   = (const float*)d_in[2];
    const float* Wxr   = (const float*)d_in[3];
    const float* Wh    = (const float*)d_in[4];
    const float* Wc    = (const float*)d_in[5];
    const float* bvec  = (const float*)d_in[6];
    const float* Wout  = (const float*)d_in[7];
    const float* bout  = (const float*)d_in[8];
    float* out = (float*)d_out;

    cudaFuncSetAttribute(bilateral_kernel, cudaFuncAttributeMaxDynamicSharedMemorySize,
                         (int)sizeof(Smem));
    bilateral_kernel<<<NCTA, NTHR, sizeof(Smem)>>>(noise, h_cpl, Wx0, Wxr, Wh, Wc,
                                                   bvec, Wout, bout, out);
}

// round 17
// speedup vs baseline: 3.2742x; 1.0501x over previous
#include <cuda_runtime.h>
#include <cuda_bf16.h>
#include <cstdint>

#define NB 128
#define NT 512
#define NDIM 128
#define NH 512
#define NG 2048
#define NLAT 128
#define NL 3
#define NCTA 128
#define NTHR 512
#define NKT 8
#define NCT 16
#define KSL 64

// Resident W slots: 0=Wh0 1=Wh1 2=Wh2 3=Wxr0 4=Wxr1
struct __align__(1024) Smem {
    char W[5][2][16384];          // resident weight tiles (160KB)
    char A[2][16384];             // A slice hi/lo (32KB)
    float woutc[NH][8];           // 16KB
    float opart[4][NB];           // 2KB
};                                 // total ~215KB

__device__ float g_part3[NL][NKT][NG][NB];
__device__ float g_bias[NL][NG][NB];                   // [layer][GLOBAL gatecol][row]
__device__ float g_xproj[(size_t)NT * NG * NB];
__device__ float g_h2[NB][NH];
__device__ __nv_bfloat16 g_hb[2][2][NL][NB][NH];
__device__ __nv_bfloat16 g_nb[2][NB * NT * NDIM];
__device__ __nv_bfloat16 g_cb[2][NL * NB * NH];
__device__ __nv_bfloat16 g_wx0t[2][NG * NDIM];
__device__ __nv_bfloat16 g_wxrt[2][(NL - 1) * NG * NH];
__device__ __nv_bfloat16 g_wht[2][NL * NG * NH];
__device__ __nv_bfloat16 g_wct[2][NL * NG * NH];
__device__ unsigned g_flags[NCTA][32];

__device__ __forceinline__ float sigm(float x) { return 1.f / (1.f + __expf(-x)); }

__device__ __forceinline__ void split_bf16(float v, __nv_bfloat16& hi, __nv_bfloat16& lo) {
    unsigned u = __float_as_uint(v);
    hi = __ushort_as_bfloat16((unsigned short)(u >> 16));
    float hf = __uint_as_float(u & 0xFFFF0000u);
    lo = __float2bfloat16(v - hf);
}

__device__ __forceinline__ uint32_t smem_u32(const void* p) {
    uint32_t a;
    asm("{ .reg .u64 t; cvta.to.shared.u64 t, %1; cvt.u32.u64 %0, t; }" : "=r"(a) : "l"(p));
    return a;
}

__device__ __forceinline__ void cpa16(void* dst, const void* src) {
    unsigned d = (unsigned)__cvta_generic_to_shared(dst);
    asm volatile("cp.async.cg.shared.global [%0], [%1], 16;" :: "r"(d), "l"(src));
}
__device__ __forceinline__ void cpa_commit() {
    asm volatile("cp.async.commit_group;" ::: "memory");
}
template <int N>
__device__ __forceinline__ void cpa_wait() {
    asm volatile("cp.async.wait_group %0;" :: "n"(N) : "memory");
}

__device__ __forceinline__ void ldsm4(unsigned& r0, unsigned& r1, unsigned& r2,
                                      unsigned& r3, unsigned addr) {
    asm volatile("ldmatrix.sync.aligned.m8n8.x4.shared.b16 {%0,%1,%2,%3}, [%4];"
                 : "=r"(r0), "=r"(r1), "=r"(r2), "=r"(r3) : "r"(addr));
}
__device__ __forceinline__ void mma16816(float* c, unsigned a0, unsigned a1, unsigned a2,
                                         unsigned a3, unsigned b0, unsigned b1) {
    asm volatile(
        "mma.sync.aligned.m16n8k16.row.col.f32.bf16.bf16.f32 "
        "{%0,%1,%2,%3}, {%4,%5,%6,%7}, {%8,%9}, {%0,%1,%2,%3};"
        : "+f"(c[0]), "+f"(c[1]), "+f"(c[2]), "+f"(c[3])
        : "r"(a0), "r"(a1), "r"(a2), "r"(a3), "r"(b0), "r"(b1));
}

__device__ __forceinline__ void grid_barrier2(int cta, unsigned target) {
    __syncthreads();
    if (threadIdx.x == 0) {
        __threadfence();
        atomicExch(&g_flags[cta][0], target);
    }
    for (;;) {
        unsigned v = (threadIdx.x < NCTA) ? __ldcg(&g_flags[threadIdx.x][0]) : target;
        if (__syncthreads_count((int)(v < target)) == 0) break;
    }
    __threadfence();
}

// Stage one 128x64 bf16 tile into 128B-pitch swizzled smem (chunk ^= row&7).
__device__ __forceinline__ void stage_sw(char* dst, const __nv_bfloat16* src, int ld) {
    const int tid = threadIdx.x;
#pragma unroll
    for (int it = 0; it < 1024 / NTHR; it++) {
        int idx = it * NTHR + tid;
        int r = idx >> 3, g = idx & 7;
        cpa16(dst + r * 128 + ((g ^ (r & 7)) << 4), src + (size_t)r * ld + g * 8);
    }
}

// HMMA: C += A * W^T (3-term bf16 split). 16 warps: row-group x col-half. C[8][4].
__device__ __forceinline__ void compute_sw(const char* Ah, const char* Al,
                                           const char* Wh_, const char* Wl_,
                                           float (*C)[4], int warp, int lane) {
    const int wr2 = warp >> 1, wc2 = warp & 1;
    const int ar = wr2 * 16 + (lane & 15);
    const int ac = lane >> 4;
    const unsigned ah_b = smem_u32(Ah) + ar * 128;
    const unsigned al_b = smem_u32(Al) + ar * 128;
    const int bc = wc2 * 64 + (lane & 7) + ((lane >= 16) ? 8 : 0);
    const int bsel = (lane >> 3) & 1;
    const unsigned bh_b = smem_u32(Wh_) + bc * 128;
    const unsigned bl_b = smem_u32(Wl_) + bc * 128;
    const int asw = ar & 7, bsw = bc & 7;
#pragma unroll
    for (int ks = 0; ks < 4; ks++) {
        const unsigned aoff = (unsigned)(((ks * 2 + ac) ^ asw) << 4);
        const unsigned boff = (unsigned)(((ks * 2 + bsel) ^ bsw) << 4);
        unsigned ah0, ah1, ah2, ah3, al0, al1, al2, al3;
        ldsm4(ah0, ah1, ah2, ah3, ah_b + aoff);
        ldsm4(al0, al1, al2, al3, al_b + aoff);
#pragma unroll
        for (int nt = 0; nt < 4; nt++) {
            unsigned bh0, bh1, bh2, bh3, bl0, bl1, bl2, bl3;
            const unsigned roff = nt * 16 * 128 + boff;
            ldsm4(bh0, bh1, bh2, bh3, bh_b + roff);
            ldsm4(bl0, bl1, bl2, bl3, bl_b + roff);
            mma16816(C[2 * nt],     ah0, ah1, ah2, ah3, bh0, bh1);
            mma16816(C[2 * nt + 1], ah0, ah1, ah2, ah3, bh2, bh3);
            mma16816(C[2 * nt],     ah0, ah1, ah2, ah3, bl0, bl1);
            mma16816(C[2 * nt + 1], ah0, ah1, ah2, ah3, bl2, bl3);
            mma16816(C[2 * nt],     al0, al1, al2, al3, bh0, bh1);
            mma16816(C[2 * nt + 1], al0, al1, al2, al3, bh2, bh3);
        }
    }
}

__device__ __forceinline__ void epilogue_regs(float* base, float (*C)[4],
                                              int warp, int lane) {
    const int wr2 = warp >> 1, wc2 = warp & 1;
    const int r0 = wr2 * 16 + (lane >> 2);
    const int c0 = 2 * (lane & 3);
#pragma unroll
    for (int n8 = 0; n8 < 8; n8++) {
        int cb = wc2 * 64 + n8 * 8 + c0;
        base[(size_t)cb * NB + r0] = C[n8][0];
        base[(size_t)(cb + 1) * NB + r0] = C[n8][1];
        base[(size_t)cb * NB + r0 + 8] = C[n8][2];
        base[(size_t)(cb + 1) * NB + r0 + 8] = C[n8][3];
    }
}

#define ZERO_C(C)                      \
    _Pragma("unroll")                  \
    for (int m = 0; m < 8; m++)        \
        _Pragma("unroll")              \
        for (int v = 0; v < 4; v++) (C)[m][v] = 0.f;

__global__ void __launch_bounds__(NTHR, 1)
bilateral_kernel(const float* __restrict__ noise,
                 const float* __restrict__ h_cpl,
                 const float* __restrict__ Wx0,
                 const float* __restrict__ Wxr,
                 const float* __restrict__ Wh,
                 const float* __restrict__ Wc,
                 const float* __restrict__ bvec,
                 const float* __restrict__ Wout,
                 const float* __restrict__ bout,
                 float* __restrict__ out) {
    extern __shared__ char smem_raw[];
    Smem* s = reinterpret_cast<Smem*>(smem_raw);
    const int tid = threadIdx.x;
    const int cta = blockIdx.x;
    const int warp = tid >> 5, lane = tid & 31;
    const int kt = cta >> 4;
    const int ct = cta & 15;
    const int gc0 = ct * 128;
    const int kb = kt * KSL;
    const int hc4 = cta * 4;
    const int half4 = tid >> 7;      // 0..3 = this thread's hidden col j
    const int rr = tid & 127;        // this thread's batch row b

    unsigned bar_t = g_flags[cta][0];

    float* out_seq = out;
    float* out_hfin = out + (size_t)NB * NT * NLAT;

    const int orow0 = (cta >> 4) * 16;
    const int ocol0 = (cta & 15) * 8;
    const int q = tid & 127;
    const int tr = q >> 3, tc = q & 7;
    const float bout_r = bout[ocol0 + tc];

    int gcolv[4];
#pragma unroll
    for (int gi = 0; gi < 4; gi++)
        gcolv[gi] = gi * 512 + hc4 + half4;   // gate gi, hidden col hc4+half4

    // register-resident c-state for this thread's (row, col) cell, per layer
    float cst_reg[NL];
#pragma unroll
    for (int l = 0; l < NL; l++) cst_reg[l] = 0.f;

    // ---- phase 0: conversions + zero init ----
    for (int i = cta * NTHR + tid; i < NB * NT * NDIM; i += NCTA * NTHR)
        split_bf16(noise[i], g_nb[0][i], g_nb[1][i]);
    for (int i = cta * NTHR + tid; i < NL * NB * NH; i += NCTA * NTHR)
        split_bf16(h_cpl[i], g_cb[0][i], g_cb[1][i]);
    {
        __nv_bfloat16* hz = &g_hb[0][0][0][0][0];
        __nv_bfloat16 z = __float2bfloat16(0.f);
        for (int i = cta * NTHR + tid; i < 2 * 2 * NL * NB * NH; i += NCTA * NTHR) hz[i] = z;
    }
    for (int i = tid; i < NH * 8; i += NTHR) {
        int k = i >> 3, c = i & 7;
        s->woutc[k][c] = Wout[(size_t)k * NLAT + ocol0 + c];
    }

    // ---- phase 0b: weight transpose + bf16 split (first 256 threads) ----
    {
        float (*tile)[33] = reinterpret_cast<float (*)[33]>(&s->W[0][0][0]);
        const int tx = tid & 31, ty = (tid >> 5) & 7;
        const bool tw = (tid < 256);
        for (int idx = cta; idx < 8448; idx += NCTA) {
            const float* src;
            __nv_bfloat16 *dh, *dl;
            int R, t;
            if (idx < 256) {
                src = Wx0; dh = g_wx0t[0]; dl = g_wx0t[1]; R = NDIM; t = idx;
            } else {
                int j = (idx - 256) >> 10;
                t = (idx - 256) & 1023;
                R = NH;
                if (j < 2) {
                    src = Wxr + (size_t)j * NH * NG;
                    dh = g_wxrt[0] + (size_t)j * NG * NH;
                    dl = g_wxrt[1] + (size_t)j * NG * NH;
                } else if (j < 5) {
                    src = Wh + (size_t)(j - 2) * NH * NG;
                    dh = g_wht[0] + (size_t)(j - 2) * NG * NH;
                    dl = g_wht[1] + (size_t)(j - 2) * NG * NH;
                } else {
                    src = Wc + (size_t)(j - 5) * NH * NG;
                    dh = g_wct[0] + (size_t)(j - 5) * NG * NH;
                    dl = g_wct[1] + (size_t)(j - 5) * NG * NH;
                }
            }
            const int tr_ = t / (NG / 32), tc_ = t % (NG / 32);
            const int r0 = tr_ * 32, c0 = tc_ * 32;
            __syncthreads();
            if (tw) {
#pragma unroll
                for (int i = 0; i < 32; i += 8)
                    tile[ty + i][tx] = src[(size_t)(r0 + ty + i) * NG + c0 + tx];
            }
            __syncthreads();
            if (tw) {
#pragma unroll
                for (int i = 0; i < 32; i += 8) {
                    float v = tile[tx][ty + i];
                    __nv_bfloat16 hi, lo;
                    split_bf16(v, hi, lo);
                    size_t o = (size_t)(c0 + ty + i) * R + r0 + tx;
                    dh[o] = hi;
                    dl[o] = lo;
                }
            }
        }
    }
    __syncthreads();
    grid_barrier2(cta, ++bar_t);

    // ---- phase 1: precompute x@Wx0 for all t (W slots as scratch) ----
    for (int idx = cta; idx < NT * NCT; idx += NCTA) {
        const int t = idx >> 4;
        const int gx = (idx & 15) * 128;
        stage_sw(s->A[0],    g_nb[0] + (size_t)t * NDIM, NT * NDIM);
        stage_sw(s->A[1],    g_nb[1] + (size_t)t * NDIM, NT * NDIM);
        stage_sw(s->W[1][0], g_nb[0] + (size_t)t * NDIM + 64, NT * NDIM);
        stage_sw(s->W[1][1], g_nb[1] + (size_t)t * NDIM + 64, NT * NDIM);
        stage_sw(s->W[0][0], g_wx0t[0] + (size_t)gx * NDIM, NDIM);
        stage_sw(s->W[0][1], g_wx0t[1] + (size_t)gx * NDIM, NDIM);
        stage_sw(s->W[2][0], g_wx0t[0] + (size_t)gx * NDIM + 64, NDIM);
        stage_sw(s->W[2][1], g_wx0t[1] + (size_t)gx * NDIM + 64, NDIM);
        cpa_commit();
        float C[8][4];
        ZERO_C(C)
        cpa_wait<0>();
        __syncthreads();
        compute_sw(s->A[0], s->A[1], s->W[0][0], s->W[0][1], C, warp, lane);
        compute_sw(s->W[1][0], s->W[1][1], s->W[2][0], s->W[2][1], C, warp, lane);
        epilogue_regs(&g_xproj[((size_t)t * NG + gx) * NB], C, warp, lane);
        __syncthreads();
    }

    // ---- phase 2: bias = h_coupled @ Wc + b -> g_bias (global gate-col index) ----
    for (int l = 0; l < NL; l++) {
        stage_sw(s->A[0],    g_cb[0] + (size_t)l * NB * NH + kb, NH);
        stage_sw(s->A[1],    g_cb[1] + (size_t)l * NB * NH + kb, NH);
        stage_sw(s->W[0][0], g_wct[0] + ((size_t)l * NG + gc0) * NH + kb, NH);
        stage_sw(s->W[0][1], g_wct[1] + ((size_t)l * NG + gc0) * NH + kb, NH);
        cpa_commit();
        float C[8][4];
        ZERO_C(C)
        cpa_wait<0>();
        __syncthreads();
        compute_sw(s->A[0], s->A[1], s->W[0][0], s->W[0][1], C, warp, lane);
        epilogue_regs(&g_part3[0][kt][gc0][0], C, warp, lane);
        grid_barrier2(cta, ++bar_t);
#pragma unroll
        for (int gi = 0; gi < 4; gi++) {
            float sum = 0.f;
#pragma unroll
            for (int k2 = 0; k2 < NKT; k2++) sum += __ldcg(&g_part3[0][k2][gcolv[gi]][rr]);
            g_bias[l][gcolv[gi]][rr] = sum + bvec[l * NG + gcolv[gi]];
        }
        grid_barrier2(cta, ++bar_t);
    }

    // ---- load resident W tiles (once) ----
    stage_sw(s->W[0][0], g_wht[0] + (size_t)gc0 * NH + kb, NH);
    stage_sw(s->W[0][1], g_wht[1] + (size_t)gc0 * NH + kb, NH);
    stage_sw(s->W[1][0], g_wht[0] + ((size_t)1 * NG + gc0) * NH + kb, NH);
    stage_sw(s->W[1][1], g_wht[1] + ((size_t)1 * NG + gc0) * NH + kb, NH);
    stage_sw(s->W[2][0], g_wht[0] + ((size_t)2 * NG + gc0) * NH + kb, NH);
    stage_sw(s->W[2][1], g_wht[1] + ((size_t)2 * NG + gc0) * NH + kb, NH);
    stage_sw(s->W[3][0], g_wxrt[0] + (size_t)gc0 * NH + kb, NH);
    stage_sw(s->W[3][1], g_wxrt[1] + (size_t)gc0 * NH + kb, NH);
    stage_sw(s->W[4][0], g_wxrt[0] + ((size_t)1 * NG + gc0) * NH + kb, NH);
    stage_sw(s->W[4][1], g_wxrt[1] + ((size_t)1 * NG + gc0) * NH + kb, NH);
    cpa_commit();
    cpa_wait<0>();
    __syncthreads();

    // ---- phase 3: wavefront recurrence ----
    for (int sIv = 0; sIv < NT + 2; sIv++) {
        const int wr = sIv & 1, rd = wr ^ 1;
        const bool act0 = (sIv < NT);
        const bool act1 = (sIv >= 1 && sIv <= NT);
        const bool act2 = (sIv >= 2 && sIv <= NT + 1);

        // stage A0 = h[0][s-1]
        stage_sw(s->A[0], &g_hb[rd][0][0][0][kb], NH);
        stage_sw(s->A[1], &g_hb[rd][1][0][0][kb], NH);
        cpa_commit();

        // projection for t = sIv-3 (overlaps A0 staging)
        if (sIv >= 3) {
            const float* hrow = &g_h2[orow0 + tr][0] + (half4 << 7);
            const int kb2 = half4 << 7;
            float a0 = 0.f, a1 = 0.f;
#pragma unroll
            for (int k = 0; k < 128; k += 8) {
                float4 v0 = __ldcg(reinterpret_cast<const float4*>(hrow + k));
                float4 v1 = __ldcg(reinterpret_cast<const float4*>(hrow + k + 4));
                a0 += v0.x * s->woutc[kb2 + k + 0][tc] + v0.y * s->woutc[kb2 + k + 1][tc]
                    + v0.z * s->woutc[kb2 + k + 2][tc] + v0.w * s->woutc[kb2 + k + 3][tc];
                a1 += v1.x * s->woutc[kb2 + k + 4][tc] + v1.y * s->woutc[kb2 + k + 5][tc]
                    + v1.z * s->woutc[kb2 + k + 6][tc] + v1.w * s->woutc[kb2 + k + 7][tc];
            }
            float accp = (half4 == 0 ? bout_r : 0.f) + a0 + a1;
            if (half4 > 0) s->opart[half4][q] = accp;
            __syncthreads();
            if (half4 == 0) {
                accp += s->opart[1][q] + s->opart[2][q] + s->opart[3][q];
                out_seq[(size_t)(orow0 + tr) * NT * NLAT + (size_t)(sIv - 3) * NLAT +
                        ocol0 + tc] = sigm(accp);
            }
        }

        float C[8][4];
        // job1: L0 = A0 x Wh0(res)
        cpa_wait<0>();
        __syncthreads();
        ZERO_C(C)
        compute_sw(s->A[0], s->A[1], s->W[0][0], s->W[0][1], C, warp, lane);
        epilogue_regs(&g_part3[0][kt][gc0][0], C, warp, lane);
        // job2: L1 = A0 x Wxr0(res)   (C kept for job3)
        ZERO_C(C)
        compute_sw(s->A[0], s->A[1], s->W[3][0], s->W[3][1], C, warp, lane);
        __syncthreads();                       // all warps done with A0
        // stage A1 = h[1][s-2]
        stage_sw(s->A[0], &g_hb[rd][0][1][0][kb], NH);
        stage_sw(s->A[1], &g_hb[rd][1][1][0][kb], NH);
        cpa_commit();
        cpa_wait<0>();
        __syncthreads();
        // job3: L1 += A1 x Wh1(res)
        compute_sw(s->A[0], s->A[1], s->W[1][0], s->W[1][1], C, warp, lane);
        epilogue_regs(&g_part3[1][kt][gc0][0], C, warp, lane);
        // job4: L2 = A1 x Wxr1(res)   (C kept for job5)
        ZERO_C(C)
        compute_sw(s->A[0], s->A[1], s->W[4][0], s->W[4][1], C, warp, lane);
        __syncthreads();                       // all warps done with A1
        // stage A2 = h[2][s-3]
        stage_sw(s->A[0], &g_hb[rd][0][2][0][kb], NH);
        stage_sw(s->A[1], &g_hb[rd][1][2][0][kb], NH);
        cpa_commit();
        cpa_wait<0>();
        __syncthreads();
        // job5: L2 += A2 x Wh2(res)
        compute_sw(s->A[0], s->A[1], s->W[2][0], s->W[2][1], C, warp, lane);
        epilogue_regs(&g_part3[2][kt][gc0][0], C, warp, lane);

        grid_barrier2(cta, ++bar_t);   // A: all partials visible

        // --- batched reduce (all layers, one MLP round) + register cells ---
        {
            float sum[NL][4];
#pragma unroll
            for (int l = 0; l < NL; l++)
#pragma unroll
                for (int gi = 0; gi < 4; gi++)
                    sum[l][gi] = __ldcg(&g_bias[l][gcolv[gi]][rr]);
            if (act0) {
                const int tL0 = sIv;
#pragma unroll
                for (int gi = 0; gi < 4; gi++)
                    sum[0][gi] += __ldcg(&g_xproj[((size_t)tL0 * NG + gcolv[gi]) * NB + rr]);
            }
#pragma unroll
            for (int k2 = 0; k2 < NKT; k2++)
#pragma unroll
                for (int l = 0; l < NL; l++)
#pragma unroll
                    for (int gi = 0; gi < 4; gi++)
                        sum[l][gi] += __ldcg(&g_part3[l][k2][gcolv[gi]][rr]);

#pragma unroll
            for (int l = 0; l < NL; l++) {
                const bool act = (l == 0) ? act0 : (l == 1) ? act1 : act2;
                if (!act) continue;
                const int tL = sIv - l;
                float c_new = sigm(sum[l][1]) * cst_reg[l] +
                              sigm(sum[l][0]) * tanhf(sum[l][2]);
                float h_new = sigm(sum[l][3]) * tanhf(c_new);
                cst_reg[l] = c_new;
                __nv_bfloat16 hi, lo;
                split_bf16(h_new, hi, lo);
                g_hb[wr][0][l][rr][hc4 + half4] = hi;
                g_hb[wr][1][l][rr][hc4 + half4] = lo;
                if (l == 2) g_h2[rr][hc4 + half4] = h_new;
                if (tL == NT - 1)
                    out_hfin[(size_t)l * NB * NH + (size_t)rr * NH + hc4 + half4] = h_new;
            }
        }

        grid_barrier2(cta, ++bar_t);   // B: all h writes visible
    }

    // ---- final projection (t = NT-1) ----
    {
        const float* hrow = &g_h2[orow0 + tr][0] + (half4 << 7);
        const int kb2 = half4 << 7;
        float a0 = 0.f, a1 = 0.f;
#pragma unroll
        for (int k = 0; k < 128; k += 8) {
            float4 v0 = __ldcg(reinterpret_cast<const float4*>(hrow + k));
            float4 v1 = __ldcg(reinterpret_cast<const float4*>(hrow + k + 4));
            a0 += v0.x * s->woutc[kb2 + k + 0][tc] + v0.y * s->woutc[kb2 + k + 1][tc]
                + v0.z * s->woutc[kb2 + k + 2][tc] + v0.w * s->woutc[kb2 + k + 3][tc];
            a1 += v1.x * s->woutc[kb2 + k + 4][tc] + v1.y * s->woutc[kb2 + k + 5][tc]
                + v1.z * s->woutc[kb2 + k + 6][tc] + v1.w * s->woutc[kb2 + k + 7][tc];
        }
        float accp = (half4 == 0 ? bout_r : 0.f) + a0 + a1;
        if (half4 > 0) s->opart[half4][q] = accp;
        __syncthreads();
        if (half4 == 0) {
            accp += s->opart[1][q] + s->opart[2][q] + s->opart[3][q];
            out_seq[(size_t)(orow0 + tr) * NT * NLAT + (size_t)(NT - 1) * NLAT +
                    ocol0 + tc] = sigm(accp);
        }
    }
}

extern "C" void kernel_launch(void* const* d_in, const int* in_sizes, int n_in,
                              void* d_out, int out_size) {
    const float* noise = (const float*)d_in[0];
    const float* h_cpl = (const float*)d_in[1];
    const float* Wx0   = (const float*)d_in[2];
    const float* Wxr   = (const float*)d_in[3];
    const float* Wh    = (const float*)d_in[4];
    const float* Wc    = (const float*)d_in[5];
    const float* bvec  = (const float*)d_in[6];
    const float* Wout  = (const float*)d_in[7];
    const float* bout  = (const float*)d_in[8];
    float* out = (float*)d_out;

    cudaFuncSetAttribute(bilateral_kernel, cudaFuncAttributeMaxDynamicSharedMemorySize,
                         (int)sizeof(Smem));
    bilateral_kernel<<<NCTA, NTHR, sizeof(Smem)>>>(noise, h_cpl, Wx0, Wxr, Wh, Wc,
                                                   bvec, Wout, bout, out);
}